// round 1
// baseline (speedup 1.0000x reference)
#include <cuda_runtime.h>
#include <cstddef>

#define D_MODEL 768
#define NHEAD   12
#define HEAD_DIM 64
#define BATCH   8
#define SEQ     1024
#define BH      (BATCH * NHEAD)     // 96
#define DA      128                 // augmented head dim: [q | k/48] vs [k+pq | pk]
#define M_ROWS  (BATCH * SEQ)       // 8192
#define INV_SCALE (1.0f / 48.0f)    // 1/sqrt(3*768) = 1/48 exactly

// ---------------- scratch (static device allocation; no cudaMalloc) ----------------
__device__ float g_QKV [M_ROWS * 3 * D_MODEL];   // 75.5 MB
__device__ float g_PQ  [M_ROWS * D_MODEL];       // 25.2 MB
__device__ float g_PK  [M_ROWS * D_MODEL];       // 25.2 MB
__device__ float g_Qaug[(size_t)BH * SEQ * DA];  // 50.3 MB
__device__ float g_Kaug[(size_t)BH * SEQ * DA];  // 50.3 MB
__device__ float g_Vh  [(size_t)BH * SEQ * HEAD_DIM]; // 25.2 MB

// ====================================================================
// SGEMM (NT): C[M,N] = A[M,K] @ W[N,K]^T + bias[N]
// 128x128 tile, BK=8, 256 threads, 8x8 microtile.
// ====================================================================
__global__ __launch_bounds__(256) void sgemm_nt_bias(
    const float* __restrict__ A, const float* __restrict__ W,
    const float* __restrict__ bias, float* __restrict__ C,
    int M, int N, int K)
{
    __shared__ float As[8][128];
    __shared__ float Ws[8][128];

    const int tid = threadIdx.x;
    const int tr  = tid >> 4;       // 0..15
    const int tc  = tid & 15;       // 0..15
    const int rowBase = blockIdx.y << 7;
    const int colBase = blockIdx.x << 7;

    const int lr = tid >> 1;        // 0..127
    const int lk = (tid & 1) << 2;  // 0 or 4
    const float* Ap = A + (size_t)(rowBase + lr) * K + lk;
    const float* Wp = W + (size_t)(colBase + lr) * K + lk;

    float acc[8][8];
    #pragma unroll
    for (int i = 0; i < 8; i++)
        #pragma unroll
        for (int j = 0; j < 8; j++) acc[i][j] = 0.0f;

    for (int k0 = 0; k0 < K; k0 += 8) {
        float4 av = *(const float4*)(Ap + k0);
        float4 wv = *(const float4*)(Wp + k0);
        __syncthreads();
        As[lk + 0][lr] = av.x; As[lk + 1][lr] = av.y;
        As[lk + 2][lr] = av.z; As[lk + 3][lr] = av.w;
        Ws[lk + 0][lr] = wv.x; Ws[lk + 1][lr] = wv.y;
        Ws[lk + 2][lr] = wv.z; Ws[lk + 3][lr] = wv.w;
        __syncthreads();
        #pragma unroll
        for (int kk = 0; kk < 8; kk++) {
            float a[8], b[8];
            *(float4*)(a)     = *(const float4*)(&As[kk][tr * 8]);
            *(float4*)(a + 4) = *(const float4*)(&As[kk][tr * 8 + 4]);
            *(float4*)(b)     = *(const float4*)(&Ws[kk][tc * 8]);
            *(float4*)(b + 4) = *(const float4*)(&Ws[kk][tc * 8 + 4]);
            #pragma unroll
            for (int i = 0; i < 8; i++)
                #pragma unroll
                for (int j = 0; j < 8; j++)
                    acc[i][j] += a[i] * b[j];
        }
    }

    #pragma unroll
    for (int i = 0; i < 8; i++) {
        const int row = rowBase + tr * 8 + i;
        #pragma unroll
        for (int j = 0; j < 8; j++) {
            const int col = colBase + tc * 8 + j;
            C[(size_t)row * N + col] = acc[i][j] + bias[col];
        }
    }
}

// ====================================================================
// Build augmented Q/K and head-major V:
//   Qaug[bh][n][0:64]   = q[n]            Qaug[bh][n][64:128] = k[n]/48
//   Kaug[bh][l][0:64]   = k[l] + pq[l]    Kaug[bh][l][64:128] = pk[l]
//   Vh  [bh][l][0:64]   = v[l]
// Then softmax(Qaug·Kaugᵀ) == softmax(CC + CP + PC/48) exactly.
// ====================================================================
__global__ __launch_bounds__(256) void build_aug_kernel()
{
    const int idx = blockIdx.x * 256 + threadIdx.x;     // [0, BH*SEQ*DA)
    const int d  = idx & (DA - 1);
    const int l  = (idx >> 7) & (SEQ - 1);
    const int bh = idx >> 17;
    const int b  = bh / NHEAD;
    const int h  = bh - b * NHEAD;
    const size_t row = (size_t)b * SEQ + l;
    const float* qkvr = g_QKV + row * (3 * D_MODEL);
    const size_t aidx = (size_t)bh * SEQ * DA + (size_t)l * DA + d;

    if (d < HEAD_DIM) {
        const int c = h * HEAD_DIM + d;
        float q  = qkvr[c];
        float k  = qkvr[D_MODEL + c];
        float pq = g_PQ[row * D_MODEL + c];
        float v  = qkvr[2 * D_MODEL + c];
        g_Qaug[aidx] = q;
        g_Kaug[aidx] = k + pq;
        g_Vh[(size_t)bh * SEQ * HEAD_DIM + (size_t)l * HEAD_DIM + d] = v;
    } else {
        const int c = h * HEAD_DIM + (d - HEAD_DIM);
        float k  = qkvr[D_MODEL + c];
        float pk = g_PK[row * D_MODEL + c];
        g_Qaug[aidx] = k * INV_SCALE;
        g_Kaug[aidx] = pk;
    }
}

// ====================================================================
// Fused flash attention. Grid (SEQ/64, BH), 256 threads.
// Per CTA: 64 query rows. Tiles of 64 keys. smem transposed layouts
// (pitch 68) so the microkernel uses pure float4 LDS.
// ====================================================================
#define BM 64
#define BN 64
#define PITCH 68
#define SMEM_ATTN ((DA*PITCH + DA*PITCH + BN*HEAD_DIM + BN*PITCH) * 4)

__global__ __launch_bounds__(256) void attn_kernel(float* __restrict__ out)
{
    extern __shared__ float sm[];
    float* Qt = sm;                         // [DA][PITCH]  Qt[d][n]
    float* Kt = Qt + DA * PITCH;            // [DA][PITCH]  Kt[d][l]
    float* Vs = Kt + DA * PITCH;            // [BN][HEAD_DIM] Vs[l][d]
    float* Pt = Vs + BN * HEAD_DIM;         // [BN][PITCH]  Pt[l][n]

    const int tid = threadIdx.x;
    const int tr = tid >> 4;   // 0..15 -> owns rows tr*4..tr*4+3
    const int tc = tid & 15;   // 0..15 -> owns cols tc*4..tc*4+3
    const int qb = blockIdx.x;
    const int bh = blockIdx.y;

    const float* Qg = g_Qaug + (size_t)bh * SEQ * DA + (size_t)qb * BM * DA;
    const float* Kg = g_Kaug + (size_t)bh * SEQ * DA;
    const float* Vg = g_Vh   + (size_t)bh * SEQ * HEAD_DIM;

    // ---- load Q tile transposed (coalesced global, 2-way STS conflict) ----
    {
        const int n = tid >> 2;            // 0..63
        const int c = (tid & 3) << 2;      // 0,4,8,12
        #pragma unroll
        for (int it = 0; it < 8; it++) {
            const int d4 = it * 16 + c;
            float4 v = *(const float4*)(Qg + (size_t)n * DA + d4);
            Qt[(d4 + 0) * PITCH + n] = v.x;
            Qt[(d4 + 1) * PITCH + n] = v.y;
            Qt[(d4 + 2) * PITCH + n] = v.z;
            Qt[(d4 + 3) * PITCH + n] = v.w;
        }
    }

    float o[4][4];
    float mrow[4], lrow[4];
    #pragma unroll
    for (int i = 0; i < 4; i++) {
        mrow[i] = -1e30f; lrow[i] = 0.0f;
        #pragma unroll
        for (int j = 0; j < 4; j++) o[i][j] = 0.0f;
    }

    for (int kb = 0; kb < SEQ / BN; kb++) {
        __syncthreads();   // protect Kt/Vs/Pt (and first-iter Qt) before overwrite
        // ---- load K tile transposed + V tile ----
        {
            const int n = tid >> 2;
            const int c = (tid & 3) << 2;
            const float* Kgb = Kg + (size_t)(kb * BN) * DA;
            #pragma unroll
            for (int it = 0; it < 8; it++) {
                const int d4 = it * 16 + c;
                float4 v = *(const float4*)(Kgb + (size_t)n * DA + d4);
                Kt[(d4 + 0) * PITCH + n] = v.x;
                Kt[(d4 + 1) * PITCH + n] = v.y;
                Kt[(d4 + 2) * PITCH + n] = v.z;
                Kt[(d4 + 3) * PITCH + n] = v.w;
            }
            const float* Vgb = Vg + (size_t)(kb * BN) * HEAD_DIM;
            #pragma unroll
            for (int it = 0; it < 4; it++) {
                const int idx = it * 256 + tid;     // 0..1023 float4s
                *(float4*)(Vs + idx * 4) = *(const float4*)(Vgb + idx * 4);
            }
        }
        __syncthreads();

        // ---- S = Qaug @ Kaug^T (64x64, k=128) ----
        float s[4][4];
        #pragma unroll
        for (int i = 0; i < 4; i++)
            #pragma unroll
            for (int j = 0; j < 4; j++) s[i][j] = 0.0f;

        #pragma unroll 4
        for (int d = 0; d < DA; d++) {
            float a[4], b[4];
            *(float4*)a = *(const float4*)(Qt + d * PITCH + tr * 4);
            *(float4*)b = *(const float4*)(Kt + d * PITCH + tc * 4);
            #pragma unroll
            for (int i = 0; i < 4; i++)
                #pragma unroll
                for (int j = 0; j < 4; j++)
                    s[i][j] += a[i] * b[j];
        }

        // ---- online softmax (row groups of 16 lanes, shfl_xor reductions) ----
        #pragma unroll
        for (int i = 0; i < 4; i++) {
            float mx = fmaxf(fmaxf(s[i][0], s[i][1]), fmaxf(s[i][2], s[i][3]));
            #pragma unroll
            for (int msk = 8; msk >= 1; msk >>= 1)
                mx = fmaxf(mx, __shfl_xor_sync(0xffffffffu, mx, msk));
            const float mnew = fmaxf(mrow[i], mx);
            const float corr = __expf(mrow[i] - mnew);
            float rs = 0.0f;
            #pragma unroll
            for (int j = 0; j < 4; j++) {
                float p = __expf(s[i][j] - mnew);
                s[i][j] = p;
                rs += p;
            }
            #pragma unroll
            for (int msk = 8; msk >= 1; msk >>= 1)
                rs += __shfl_xor_sync(0xffffffffu, rs, msk);
            lrow[i] = lrow[i] * corr + rs;
            mrow[i] = mnew;
            #pragma unroll
            for (int j = 0; j < 4; j++) o[i][j] *= corr;
        }

        // ---- stage P transposed, then O += P @ V ----
        #pragma unroll
        for (int i = 0; i < 4; i++)
            #pragma unroll
            for (int j = 0; j < 4; j++)
                Pt[(tc * 4 + j) * PITCH + tr * 4 + i] = s[i][j];
        __syncthreads();

        #pragma unroll 4
        for (int l = 0; l < BN; l++) {
            float a[4], b[4];
            *(float4*)a = *(const float4*)(Pt + l * PITCH + tr * 4);
            *(float4*)b = *(const float4*)(Vs + l * HEAD_DIM + tc * 4);
            #pragma unroll
            for (int i = 0; i < 4; i++)
                #pragma unroll
                for (int j = 0; j < 4; j++)
                    o[i][j] += a[i] * b[j];
        }
    }

    // ---- epilogue: out[b, n, h, d] = o / l ----
    const int b_ = bh / NHEAD;
    const int h  = bh - b_ * NHEAD;
    #pragma unroll
    for (int i = 0; i < 4; i++) {
        const int n = qb * BM + tr * 4 + i;
        const float inv = 1.0f / lrow[i];
        float* orow = out + (((size_t)(b_ * SEQ + n)) * NHEAD + h) * HEAD_DIM + tc * 4;
        float4 ov = make_float4(o[i][0] * inv, o[i][1] * inv,
                                o[i][2] * inv, o[i][3] * inv);
        *(float4*)orow = ov;
    }
}

// ====================================================================
extern "C" void kernel_launch(void* const* d_in, const int* in_sizes, int n_in,
                              void* d_out, int out_size)
{
    const float* x     = (const float*)d_in[0];
    const float* pos   = (const float*)d_in[1];
    const float* qkv_w = (const float*)d_in[2];
    const float* qkv_b = (const float*)d_in[3];
    const float* pq_w  = (const float*)d_in[4];
    const float* pq_b  = (const float*)d_in[5];
    const float* pk_w  = (const float*)d_in[6];
    const float* pk_b  = (const float*)d_in[7];
    float* out = (float*)d_out;

    float *qkv, *pq, *pk;
    cudaGetSymbolAddress((void**)&qkv, g_QKV);
    cudaGetSymbolAddress((void**)&pq,  g_PQ);
    cudaGetSymbolAddress((void**)&pk,  g_PK);

    // Projections (NT SGEMM + bias)
    sgemm_nt_bias<<<dim3(3 * D_MODEL / 128, M_ROWS / 128), 256>>>(
        x, qkv_w, qkv_b, qkv, M_ROWS, 3 * D_MODEL, D_MODEL);
    sgemm_nt_bias<<<dim3(D_MODEL / 128, M_ROWS / 128), 256>>>(
        pos, pq_w, pq_b, pq, M_ROWS, D_MODEL, D_MODEL);
    sgemm_nt_bias<<<dim3(D_MODEL / 128, M_ROWS / 128), 256>>>(
        pos, pk_w, pk_b, pk, M_ROWS, D_MODEL, D_MODEL);

    // Build augmented Q/K (folds CC+CP+PC/scale into one GEMM) and head-major V
    build_aug_kernel<<<(BH * SEQ * DA) / 256, 256>>>();

    // Fused flash attention
    cudaFuncSetAttribute(attn_kernel,
                         cudaFuncAttributeMaxDynamicSharedMemorySize, SMEM_ATTN);
    attn_kernel<<<dim3(SEQ / BM, BH), 256, SMEM_ATTN>>>(out);
}

// round 3
// speedup vs baseline: 1.4765x; 1.4765x over previous
#include <cuda_runtime.h>
#include <cuda_bf16.h>
#include <cstdint>
#include <cstddef>

#define D_MODEL 768
#define NHEAD   12
#define HEAD_DIM 64
#define BATCH   8
#define SEQ     1024
#define BH      (BATCH * NHEAD)     // 96
#define DA      128                 // augmented head dim
#define M_ROWS  (BATCH * SEQ)       // 8192
#define K3      2304                // 3 * D_MODEL (split-concat K)
#define INV_SCALE (1.0f / 48.0f)    // 1/sqrt(3*768)

// ---------------- scratch (static device allocation; no cudaMalloc) ----------------
__device__ float g_QKV [M_ROWS * 3 * D_MODEL];
__device__ float g_PQ  [M_ROWS * D_MODEL];
__device__ float g_PK  [M_ROWS * D_MODEL];
__device__ float g_Qaug[(size_t)BH * SEQ * DA];
__device__ float g_Kaug[(size_t)BH * SEQ * DA];
__device__ float g_Vh  [(size_t)BH * SEQ * HEAD_DIM];

// split-bf16 concatenated planes: activations [Ah|Ah|Al], weights [Wh|Wl|Wh]
__device__ __nv_bfloat16 g_xs  [(size_t)M_ROWS * K3];
__device__ __nv_bfloat16 g_ps  [(size_t)M_ROWS * K3];
__device__ __nv_bfloat16 g_wq  [(size_t)(3 * D_MODEL) * K3];
__device__ __nv_bfloat16 g_wpq [(size_t)D_MODEL * K3];
__device__ __nv_bfloat16 g_wpk [(size_t)D_MODEL * K3];

// ==================== helpers ====================
__device__ __forceinline__ uint32_t smem_u32(const void* p) {
    uint32_t a;
    asm("{ .reg .u64 t; cvta.to.shared.u64 t, %1; cvt.u32.u64 %0, t; }" : "=r"(a) : "l"(p));
    return a;
}
__device__ __forceinline__ void cp16(uint32_t dst, const void* src) {
    asm volatile("cp.async.cg.shared.global [%0], [%1], 16;" :: "r"(dst), "l"(src));
}
__device__ __forceinline__ void cp_commit() {
    asm volatile("cp.async.commit_group;" ::: "memory");
}
template <int N>
__device__ __forceinline__ void cp_wait() {
    asm volatile("cp.async.wait_group %0;" :: "n"(N) : "memory");
}
__device__ __forceinline__ void ldm_x4(uint32_t& r0, uint32_t& r1, uint32_t& r2,
                                       uint32_t& r3, uint32_t addr) {
    asm volatile("ldmatrix.sync.aligned.m8n8.x4.shared.b16 {%0,%1,%2,%3}, [%4];"
                 : "=r"(r0), "=r"(r1), "=r"(r2), "=r"(r3) : "r"(addr));
}
__device__ __forceinline__ void mma16816(float* c, const uint32_t* a,
                                         uint32_t b0, uint32_t b1) {
    asm volatile(
        "mma.sync.aligned.m16n8k16.row.col.f32.bf16.bf16.f32 "
        "{%0,%1,%2,%3}, {%4,%5,%6,%7}, {%8,%9}, {%0,%1,%2,%3};"
        : "+f"(c[0]), "+f"(c[1]), "+f"(c[2]), "+f"(c[3])
        : "r"(a[0]), "r"(a[1]), "r"(a[2]), "r"(a[3]), "r"(b0), "r"(b1));
}

// ==================== split fp32 -> concatenated bf16 planes ====================
// activations: dst[row][0:768]=Ah, [768:1536]=Ah, [1536:2304]=Al
__global__ __launch_bounds__(256) void split_cat_a(
    const float* __restrict__ src, __nv_bfloat16* __restrict__ dst, int total)
{
    int i = blockIdx.x * 256 + threadIdx.x;
    if (i < total) {
        int row = i / D_MODEL, col = i - row * D_MODEL;
        float v = src[i];
        __nv_bfloat16 h = __float2bfloat16(v);
        __nv_bfloat16 l = __float2bfloat16(v - __bfloat162float(h));
        size_t base = (size_t)row * K3;
        dst[base + col] = h;
        dst[base + D_MODEL + col] = h;
        dst[base + 2 * D_MODEL + col] = l;
    }
}
// weights: dst[row][0:768]=Wh, [768:1536]=Wl, [1536:2304]=Wh
__global__ __launch_bounds__(256) void split_cat_w(
    const float* __restrict__ src, __nv_bfloat16* __restrict__ dst, int total)
{
    int i = blockIdx.x * 256 + threadIdx.x;
    if (i < total) {
        int row = i / D_MODEL, col = i - row * D_MODEL;
        float v = src[i];
        __nv_bfloat16 h = __float2bfloat16(v);
        __nv_bfloat16 l = __float2bfloat16(v - __bfloat162float(h));
        size_t base = (size_t)row * K3;
        dst[base + col] = h;
        dst[base + D_MODEL + col] = l;
        dst[base + 2 * D_MODEL + col] = h;
    }
}

// ==================== bf16 NT GEMM via mma.sync (HMMA) ====================
// C[M,N] = A'[M,K3] @ W'[N,K3]^T + bias. CTA tile 128x128, BK=64, double-buffered.
#define GBK   64
#define GPIT  72                         // padded pitch (bf16 elems); 144B rows
#define GTILE (128 * GPIT)               // elems per tile
#define GBUF  (2 * GTILE)                // A + W per buffer (elems)
#define GSMEM (2 * GBUF * 2)             // bytes: 2 buffers

__global__ __launch_bounds__(256, 2) void gemm_mma(
    const __nv_bfloat16* __restrict__ A, const __nv_bfloat16* __restrict__ W,
    const float* __restrict__ bias, float* __restrict__ C, int N)
{
    extern __shared__ __nv_bfloat16 sm[];
    const uint32_t sbase = smem_u32(sm);
    const int tid  = threadIdx.x;
    const int lane = tid & 31;
    const int wid  = tid >> 5;
    const int wm   = wid >> 1;          // 0..3 -> m offset wm*32
    const int wn   = wid & 1;           // 0..1 -> n offset wn*64
    const int rowBase = blockIdx.y << 7;
    const int colBase = blockIdx.x << 7;
    const int NCH = K3 / GBK;           // 36

    // loader indices: 1024 16B segs per tile, 4 per thread
    const int lrow = tid >> 1;                    // reused pattern below
    (void)lrow;

    const __nv_bfloat16* Ag = A + (size_t)rowBase * K3;
    const __nv_bfloat16* Wg = W + (size_t)colBase * K3;

    // ldmatrix per-lane offsets (bytes)
    const uint32_t aoff = ((uint32_t)((wm * 32 + (lane & 15)) * GPIT + ((lane >> 4) * 8))) * 2;
    const uint32_t woff = ((uint32_t)((wn * 64 + ((lane >> 4) & 1) * 8 + (lane & 7)) * GPIT
                                     + (((lane >> 3) & 1) * 8))) * 2;

    float c[2][8][4];
    #pragma unroll
    for (int i = 0; i < 2; i++)
        #pragma unroll
        for (int j = 0; j < 8; j++)
            #pragma unroll
            for (int k = 0; k < 4; k++) c[i][j][k] = 0.0f;

    // ---- chunk loader ----
    auto load_chunk = [&](int ch, int b) {
        const uint32_t sA = sbase + (uint32_t)(b * GBUF) * 2;
        const uint32_t sW = sA + GTILE * 2;
        const __nv_bfloat16* Ac = Ag + ch * GBK;
        const __nv_bfloat16* Wc = Wg + ch * GBK;
        #pragma unroll
        for (int it = 0; it < 4; it++) {
            const int idx = it * 256 + tid;        // 0..1023
            const int row = idx >> 3;
            const int seg = (idx & 7) * 8;         // bf16 col
            const uint32_t so = (uint32_t)(row * GPIT + seg) * 2;
            cp16(sA + so, Ac + (size_t)row * K3 + seg);
            cp16(sW + so, Wc + (size_t)row * K3 + seg);
        }
    };

    load_chunk(0, 0);
    cp_commit();

    for (int ch = 0; ch < NCH; ch++) {
        if (ch + 1 < NCH) {
            load_chunk(ch + 1, (ch + 1) & 1);
            cp_commit();
            cp_wait<1>();
        } else {
            cp_wait<0>();
        }
        __syncthreads();

        const uint32_t sA = sbase + (uint32_t)((ch & 1) * GBUF) * 2;
        const uint32_t sW = sA + GTILE * 2;
        #pragma unroll
        for (int kk = 0; kk < GBK; kk += 16) {
            uint32_t a[2][4], b[4][4];
            #pragma unroll
            for (int fa = 0; fa < 2; fa++)
                ldm_x4(a[fa][0], a[fa][1], a[fa][2], a[fa][3],
                       sA + aoff + (uint32_t)(fa * 16 * GPIT + kk) * 2);
            #pragma unroll
            for (int fb = 0; fb < 4; fb++)
                ldm_x4(b[fb][0], b[fb][1], b[fb][2], b[fb][3],
                       sW + woff + (uint32_t)(fb * 16 * GPIT + kk) * 2);
            #pragma unroll
            for (int fa = 0; fa < 2; fa++)
                #pragma unroll
                for (int nf = 0; nf < 8; nf++) {
                    const int fb = nf >> 1, hf = (nf & 1) * 2;
                    mma16816(c[fa][nf], a[fa], b[fb][hf], b[fb][hf + 1]);
                }
        }
        __syncthreads();
    }

    // ---- epilogue: c[fa][nf][0..3] -> C + bias ----
    const int gq = lane >> 2, tq = lane & 3;
    #pragma unroll
    for (int fa = 0; fa < 2; fa++) {
        #pragma unroll
        for (int nf = 0; nf < 8; nf++) {
            const int row = rowBase + wm * 32 + fa * 16 + gq;
            const int col = colBase + wn * 64 + nf * 8 + tq * 2;
            const float b0 = bias[col], b1 = bias[col + 1];
            float2 v0 = make_float2(c[fa][nf][0] + b0, c[fa][nf][1] + b1);
            float2 v1 = make_float2(c[fa][nf][2] + b0, c[fa][nf][3] + b1);
            *(float2*)(C + (size_t)row * N + col) = v0;
            *(float2*)(C + (size_t)(row + 8) * N + col) = v1;
        }
    }
}

// ==================== build augmented Q/K + head-major V ====================
__global__ __launch_bounds__(256) void build_aug_kernel()
{
    const int idx = blockIdx.x * 256 + threadIdx.x;
    const int d  = idx & (DA - 1);
    const int l  = (idx >> 7) & (SEQ - 1);
    const int bh = idx >> 17;
    const int b  = bh / NHEAD;
    const int h  = bh - b * NHEAD;
    const size_t row = (size_t)b * SEQ + l;
    const float* qkvr = g_QKV + row * (3 * D_MODEL);
    const size_t aidx = (size_t)bh * SEQ * DA + (size_t)l * DA + d;

    if (d < HEAD_DIM) {
        const int c = h * HEAD_DIM + d;
        float q  = qkvr[c];
        float k  = qkvr[D_MODEL + c];
        float pq = g_PQ[row * D_MODEL + c];
        float v  = qkvr[2 * D_MODEL + c];
        g_Qaug[aidx] = q;
        g_Kaug[aidx] = k + pq;
        g_Vh[(size_t)bh * SEQ * HEAD_DIM + (size_t)l * HEAD_DIM + d] = v;
    } else {
        const int c = h * HEAD_DIM + (d - HEAD_DIM);
        float k  = qkvr[D_MODEL + c];
        float pk = g_PK[row * D_MODEL + c];
        g_Qaug[aidx] = k * INV_SCALE;
        g_Kaug[aidx] = pk;
    }
}

// ==================== fused flash attention (fp32) ====================
#define BM 64
#define BN 64
#define PITCH 68
#define SMEM_ATTN ((DA*PITCH + DA*PITCH + BN*HEAD_DIM + BN*PITCH) * 4)

__global__ __launch_bounds__(256) void attn_kernel(float* __restrict__ out)
{
    extern __shared__ float smf[];
    float* Qt = smf;
    float* Kt = Qt + DA * PITCH;
    float* Vs = Kt + DA * PITCH;
    float* Pt = Vs + BN * HEAD_DIM;

    const int tid = threadIdx.x;
    const int tr = tid >> 4;
    const int tc = tid & 15;
    const int qb = blockIdx.x;
    const int bh = blockIdx.y;

    const float* Qg = g_Qaug + (size_t)bh * SEQ * DA + (size_t)qb * BM * DA;
    const float* Kg = g_Kaug + (size_t)bh * SEQ * DA;
    const float* Vg = g_Vh   + (size_t)bh * SEQ * HEAD_DIM;

    {
        const int n = tid >> 2;
        const int c = (tid & 3) << 2;
        #pragma unroll
        for (int it = 0; it < 8; it++) {
            const int d4 = it * 16 + c;
            float4 v = *(const float4*)(Qg + (size_t)n * DA + d4);
            Qt[(d4 + 0) * PITCH + n] = v.x;
            Qt[(d4 + 1) * PITCH + n] = v.y;
            Qt[(d4 + 2) * PITCH + n] = v.z;
            Qt[(d4 + 3) * PITCH + n] = v.w;
        }
    }

    float o[4][4];
    float mrow[4], lrow[4];
    #pragma unroll
    for (int i = 0; i < 4; i++) {
        mrow[i] = -1e30f; lrow[i] = 0.0f;
        #pragma unroll
        for (int j = 0; j < 4; j++) o[i][j] = 0.0f;
    }

    for (int kb = 0; kb < SEQ / BN; kb++) {
        __syncthreads();
        {
            const int n = tid >> 2;
            const int c = (tid & 3) << 2;
            const float* Kgb = Kg + (size_t)(kb * BN) * DA;
            #pragma unroll
            for (int it = 0; it < 8; it++) {
                const int d4 = it * 16 + c;
                float4 v = *(const float4*)(Kgb + (size_t)n * DA + d4);
                Kt[(d4 + 0) * PITCH + n] = v.x;
                Kt[(d4 + 1) * PITCH + n] = v.y;
                Kt[(d4 + 2) * PITCH + n] = v.z;
                Kt[(d4 + 3) * PITCH + n] = v.w;
            }
            const float* Vgb = Vg + (size_t)(kb * BN) * HEAD_DIM;
            #pragma unroll
            for (int it = 0; it < 4; it++) {
                const int idx = it * 256 + tid;
                *(float4*)(Vs + idx * 4) = *(const float4*)(Vgb + idx * 4);
            }
        }
        __syncthreads();

        float s[4][4];
        #pragma unroll
        for (int i = 0; i < 4; i++)
            #pragma unroll
            for (int j = 0; j < 4; j++) s[i][j] = 0.0f;

        #pragma unroll 4
        for (int d = 0; d < DA; d++) {
            float a[4], b[4];
            *(float4*)a = *(const float4*)(Qt + d * PITCH + tr * 4);
            *(float4*)b = *(const float4*)(Kt + d * PITCH + tc * 4);
            #pragma unroll
            for (int i = 0; i < 4; i++)
                #pragma unroll
                for (int j = 0; j < 4; j++)
                    s[i][j] += a[i] * b[j];
        }

        #pragma unroll
        for (int i = 0; i < 4; i++) {
            float mx = fmaxf(fmaxf(s[i][0], s[i][1]), fmaxf(s[i][2], s[i][3]));
            #pragma unroll
            for (int msk = 8; msk >= 1; msk >>= 1)
                mx = fmaxf(mx, __shfl_xor_sync(0xffffffffu, mx, msk));
            const float mnew = fmaxf(mrow[i], mx);
            const float corr = __expf(mrow[i] - mnew);
            float rs = 0.0f;
            #pragma unroll
            for (int j = 0; j < 4; j++) {
                float p = __expf(s[i][j] - mnew);
                s[i][j] = p;
                rs += p;
            }
            #pragma unroll
            for (int msk = 8; msk >= 1; msk >>= 1)
                rs += __shfl_xor_sync(0xffffffffu, rs, msk);
            lrow[i] = lrow[i] * corr + rs;
            mrow[i] = mnew;
            #pragma unroll
            for (int j = 0; j < 4; j++) o[i][j] *= corr;
        }

        #pragma unroll
        for (int i = 0; i < 4; i++)
            #pragma unroll
            for (int j = 0; j < 4; j++)
                Pt[(tc * 4 + j) * PITCH + tr * 4 + i] = s[i][j];
        __syncthreads();

        #pragma unroll 4
        for (int l = 0; l < BN; l++) {
            float a[4], b[4];
            *(float4*)a = *(const float4*)(Pt + l * PITCH + tr * 4);
            *(float4*)b = *(const float4*)(Vs + l * HEAD_DIM + tc * 4);
            #pragma unroll
            for (int i = 0; i < 4; i++)
                #pragma unroll
                for (int j = 0; j < 4; j++)
                    o[i][j] += a[i] * b[j];
        }
    }

    const int b_ = bh / NHEAD;
    const int h  = bh - b_ * NHEAD;
    #pragma unroll
    for (int i = 0; i < 4; i++) {
        const int n = qb * BM + tr * 4 + i;
        const float inv = 1.0f / lrow[i];
        float* orow = out + (((size_t)(b_ * SEQ + n)) * NHEAD + h) * HEAD_DIM + tc * 4;
        float4 ov = make_float4(o[i][0] * inv, o[i][1] * inv,
                                o[i][2] * inv, o[i][3] * inv);
        *(float4*)orow = ov;
    }
}

// ====================================================================
extern "C" void kernel_launch(void* const* d_in, const int* in_sizes, int n_in,
                              void* d_out, int out_size)
{
    const float* x     = (const float*)d_in[0];
    const float* pos   = (const float*)d_in[1];
    const float* qkv_w = (const float*)d_in[2];
    const float* qkv_b = (const float*)d_in[3];
    const float* pq_w  = (const float*)d_in[4];
    const float* pq_b  = (const float*)d_in[5];
    const float* pk_w  = (const float*)d_in[6];
    const float* pk_b  = (const float*)d_in[7];
    float* out = (float*)d_out;

    float *qkv, *pq, *pk;
    cudaGetSymbolAddress((void**)&qkv, g_QKV);
    cudaGetSymbolAddress((void**)&pq,  g_PQ);
    cudaGetSymbolAddress((void**)&pk,  g_PK);
    __nv_bfloat16 *xs, *ps, *wq, *wpq, *wpk;
    cudaGetSymbolAddress((void**)&xs,  g_xs);
    cudaGetSymbolAddress((void**)&ps,  g_ps);
    cudaGetSymbolAddress((void**)&wq,  g_wq);
    cudaGetSymbolAddress((void**)&wpq, g_wpq);
    cudaGetSymbolAddress((void**)&wpk, g_wpk);

    // ---- split fp32 -> concatenated bf16 planes ----
    const int nx  = M_ROWS * D_MODEL;
    const int nwq = 3 * D_MODEL * D_MODEL;
    const int nw  = D_MODEL * D_MODEL;
    split_cat_a<<<(nx + 255) / 256, 256>>>(x, xs, nx);
    split_cat_a<<<(nx + 255) / 256, 256>>>(pos, ps, nx);
    split_cat_w<<<(nwq + 255) / 256, 256>>>(qkv_w, wq, nwq);
    split_cat_w<<<(nw + 255) / 256, 256>>>(pq_w, wpq, nw);
    split_cat_w<<<(nw + 255) / 256, 256>>>(pk_w, wpk, nw);

    // ---- projections via bf16 HMMA GEMM (K=2304 encodes the 3-term split) ----
    cudaFuncSetAttribute(gemm_mma, cudaFuncAttributeMaxDynamicSharedMemorySize, GSMEM);
    gemm_mma<<<dim3(3 * D_MODEL / 128, M_ROWS / 128), 256, GSMEM>>>(
        xs, wq, qkv_b, qkv, 3 * D_MODEL);
    gemm_mma<<<dim3(D_MODEL / 128, M_ROWS / 128), 256, GSMEM>>>(
        ps, wpq, pq_b, pq, D_MODEL);
    gemm_mma<<<dim3(D_MODEL / 128, M_ROWS / 128), 256, GSMEM>>>(
        ps, wpk, pk_b, pk, D_MODEL);

    // ---- build augmented Q/K + head-major V ----
    build_aug_kernel<<<(BH * SEQ * DA) / 256, 256>>>();

    // ---- fused flash attention (fp32) ----
    cudaFuncSetAttribute(attn_kernel, cudaFuncAttributeMaxDynamicSharedMemorySize, SMEM_ATTN);
    attn_kernel<<<dim3(SEQ / BM, BH), 256, SMEM_ATTN>>>(out);
}

// round 5
// speedup vs baseline: 3.2289x; 2.1869x over previous
#include <cuda_runtime.h>
#include <cuda_bf16.h>
#include <cuda_fp16.h>
#include <cstdint>
#include <cstddef>

#define D_MODEL 768
#define NHEAD   12
#define HEAD_DIM 64
#define BATCH   8
#define SEQ     1024
#define BH      (BATCH * NHEAD)     // 96
#define M_ROWS  (BATCH * SEQ)       // 8192
#define K3      2304                // 3 * D_MODEL (split-concat K for projections)
#define DQK     256                 // concat-split attention dim
#define INV_SCALE (1.0f / 48.0f)    // 1/sqrt(3*768)

// ---------------- scratch (static device allocation; no cudaMalloc) ----------------
__device__ float g_QKV [M_ROWS * 3 * D_MODEL];
__device__ float g_PQ  [M_ROWS * D_MODEL];
__device__ float g_PK  [M_ROWS * D_MODEL];

// attention operands
__device__ __nv_bfloat16 g_Qc[(size_t)BH * SEQ * DQK];   // [qh|qh|ql|k/48]
__device__ __nv_bfloat16 g_Kc[(size_t)BH * SEQ * DQK];   // [k'h|k'l|k'h|pk]
__device__ __half        g_Vt[(size_t)BH * HEAD_DIM * SEQ]; // transposed [bh][d][l]

// split-bf16 concatenated planes for projections
__device__ __nv_bfloat16 g_xs  [(size_t)M_ROWS * K3];
__device__ __nv_bfloat16 g_ps  [(size_t)M_ROWS * K3];
__device__ __nv_bfloat16 g_wq  [(size_t)(3 * D_MODEL) * K3];
__device__ __nv_bfloat16 g_wpq [(size_t)D_MODEL * K3];
__device__ __nv_bfloat16 g_wpk [(size_t)D_MODEL * K3];

// ==================== helpers ====================
__device__ __forceinline__ uint32_t smem_u32(const void* p) {
    uint32_t a;
    asm("{ .reg .u64 t; cvta.to.shared.u64 t, %1; cvt.u32.u64 %0, t; }" : "=r"(a) : "l"(p));
    return a;
}
__device__ __forceinline__ void cp16(uint32_t dst, const void* src) {
    asm volatile("cp.async.cg.shared.global [%0], [%1], 16;" :: "r"(dst), "l"(src));
}
__device__ __forceinline__ void cp_commit() {
    asm volatile("cp.async.commit_group;" ::: "memory");
}
template <int N>
__device__ __forceinline__ void cp_wait() {
    asm volatile("cp.async.wait_group %0;" :: "n"(N) : "memory");
}
__device__ __forceinline__ void ldm_x4(uint32_t& r0, uint32_t& r1, uint32_t& r2,
                                       uint32_t& r3, uint32_t addr) {
    asm volatile("ldmatrix.sync.aligned.m8n8.x4.shared.b16 {%0,%1,%2,%3}, [%4];"
                 : "=r"(r0), "=r"(r1), "=r"(r2), "=r"(r3) : "r"(addr));
}
__device__ __forceinline__ void mma16816(float* c, const uint32_t* a,
                                         uint32_t b0, uint32_t b1) {
    asm volatile(
        "mma.sync.aligned.m16n8k16.row.col.f32.bf16.bf16.f32 "
        "{%0,%1,%2,%3}, {%4,%5,%6,%7}, {%8,%9}, {%0,%1,%2,%3};"
        : "+f"(c[0]), "+f"(c[1]), "+f"(c[2]), "+f"(c[3])
        : "r"(a[0]), "r"(a[1]), "r"(a[2]), "r"(a[3]), "r"(b0), "r"(b1));
}
__device__ __forceinline__ void mma16816h(float* c, const uint32_t* a,
                                          uint32_t b0, uint32_t b1) {
    asm volatile(
        "mma.sync.aligned.m16n8k16.row.col.f32.f16.f16.f32 "
        "{%0,%1,%2,%3}, {%4,%5,%6,%7}, {%8,%9}, {%0,%1,%2,%3};"
        : "+f"(c[0]), "+f"(c[1]), "+f"(c[2]), "+f"(c[3])
        : "r"(a[0]), "r"(a[1]), "r"(a[2]), "r"(a[3]), "r"(b0), "r"(b1));
}
__device__ __forceinline__ uint32_t pack_h2(float lo, float hi) {
    __half2 h = __floats2half2_rn(lo, hi);
    return *(uint32_t*)&h;
}

// ==================== split fp32 -> concatenated bf16 planes ====================
__global__ __launch_bounds__(256) void split_cat_a(
    const float* __restrict__ src, __nv_bfloat16* __restrict__ dst, int total)
{
    int i = blockIdx.x * 256 + threadIdx.x;
    if (i < total) {
        int row = i / D_MODEL, col = i - row * D_MODEL;
        float v = src[i];
        __nv_bfloat16 h = __float2bfloat16(v);
        __nv_bfloat16 l = __float2bfloat16(v - __bfloat162float(h));
        size_t base = (size_t)row * K3;
        dst[base + col] = h;
        dst[base + D_MODEL + col] = h;
        dst[base + 2 * D_MODEL + col] = l;
    }
}
__global__ __launch_bounds__(256) void split_cat_w(
    const float* __restrict__ src, __nv_bfloat16* __restrict__ dst, int total)
{
    int i = blockIdx.x * 256 + threadIdx.x;
    if (i < total) {
        int row = i / D_MODEL, col = i - row * D_MODEL;
        float v = src[i];
        __nv_bfloat16 h = __float2bfloat16(v);
        __nv_bfloat16 l = __float2bfloat16(v - __bfloat162float(h));
        size_t base = (size_t)row * K3;
        dst[base + col] = h;
        dst[base + D_MODEL + col] = l;
        dst[base + 2 * D_MODEL + col] = h;
    }
}

// ==================== bf16 NT GEMM via mma.sync (projections) ====================
#define GBK   64
#define GPIT  72
#define GTILE (128 * GPIT)
#define GBUF  (2 * GTILE)
#define GSMEM (2 * GBUF * 2)

__global__ __launch_bounds__(256, 2) void gemm_mma(
    const __nv_bfloat16* __restrict__ A, const __nv_bfloat16* __restrict__ W,
    const float* __restrict__ bias, float* __restrict__ C, int N)
{
    extern __shared__ __nv_bfloat16 smg[];
    const uint32_t sbase = smem_u32(smg);
    const int tid  = threadIdx.x;
    const int lane = tid & 31;
    const int wid  = tid >> 5;
    const int wm   = wid >> 1;
    const int wn   = wid & 1;
    const int rowBase = blockIdx.y << 7;
    const int colBase = blockIdx.x << 7;
    const int NCH = K3 / GBK;

    const __nv_bfloat16* Ag = A + (size_t)rowBase * K3;
    const __nv_bfloat16* Wg = W + (size_t)colBase * K3;

    const uint32_t aoff = ((uint32_t)((wm * 32 + (lane & 15)) * GPIT + ((lane >> 4) * 8))) * 2;
    const uint32_t woff = ((uint32_t)((wn * 64 + ((lane >> 4) & 1) * 8 + (lane & 7)) * GPIT
                                     + (((lane >> 3) & 1) * 8))) * 2;

    float c[2][8][4];
    #pragma unroll
    for (int i = 0; i < 2; i++)
        #pragma unroll
        for (int j = 0; j < 8; j++)
            #pragma unroll
            for (int k = 0; k < 4; k++) c[i][j][k] = 0.0f;

    auto load_chunk = [&](int ch, int b) {
        const uint32_t sA = sbase + (uint32_t)(b * GBUF) * 2;
        const uint32_t sW = sA + GTILE * 2;
        const __nv_bfloat16* Ac = Ag + ch * GBK;
        const __nv_bfloat16* Wc = Wg + ch * GBK;
        #pragma unroll
        for (int it = 0; it < 4; it++) {
            const int idx = it * 256 + tid;
            const int row = idx >> 3;
            const int seg = (idx & 7) * 8;
            const uint32_t so = (uint32_t)(row * GPIT + seg) * 2;
            cp16(sA + so, Ac + (size_t)row * K3 + seg);
            cp16(sW + so, Wc + (size_t)row * K3 + seg);
        }
    };

    load_chunk(0, 0);
    cp_commit();

    for (int ch = 0; ch < NCH; ch++) {
        if (ch + 1 < NCH) {
            load_chunk(ch + 1, (ch + 1) & 1);
            cp_commit();
            cp_wait<1>();
        } else {
            cp_wait<0>();
        }
        __syncthreads();

        const uint32_t sA = sbase + (uint32_t)((ch & 1) * GBUF) * 2;
        const uint32_t sW = sA + GTILE * 2;
        #pragma unroll
        for (int kk = 0; kk < GBK; kk += 16) {
            uint32_t a[2][4], b[4][4];
            #pragma unroll
            for (int fa = 0; fa < 2; fa++)
                ldm_x4(a[fa][0], a[fa][1], a[fa][2], a[fa][3],
                       sA + aoff + (uint32_t)(fa * 16 * GPIT + kk) * 2);
            #pragma unroll
            for (int fb = 0; fb < 4; fb++)
                ldm_x4(b[fb][0], b[fb][1], b[fb][2], b[fb][3],
                       sW + woff + (uint32_t)(fb * 16 * GPIT + kk) * 2);
            #pragma unroll
            for (int fa = 0; fa < 2; fa++)
                #pragma unroll
                for (int nf = 0; nf < 8; nf++) {
                    const int fb = nf >> 1, hf = (nf & 1) * 2;
                    mma16816(c[fa][nf], a[fa], b[fb][hf], b[fb][hf + 1]);
                }
        }
        __syncthreads();
    }

    const int gq = lane >> 2, tq = lane & 3;
    #pragma unroll
    for (int fa = 0; fa < 2; fa++) {
        #pragma unroll
        for (int nf = 0; nf < 8; nf++) {
            const int row = rowBase + wm * 32 + fa * 16 + gq;
            const int col = colBase + wn * 64 + nf * 8 + tq * 2;
            const float b0 = bias[col], b1 = bias[col + 1];
            float2 v0 = make_float2(c[fa][nf][0] + b0, c[fa][nf][1] + b1);
            float2 v1 = make_float2(c[fa][nf][2] + b0, c[fa][nf][3] + b1);
            *(float2*)(C + (size_t)row * N + col) = v0;
            *(float2*)(C + (size_t)(row + 8) * N + col) = v1;
        }
    }
}

// ==================== build concat-split attention operands ====================
__global__ __launch_bounds__(256) void build_qc_kc()
{
    const int idx = blockIdx.x * 256 + threadIdx.x;     // BH*SEQ*64
    const int d  = idx & 63;
    const int l  = (idx >> 6) & (SEQ - 1);
    const int bh = idx >> 16;
    const int b  = bh / NHEAD, h = bh - b * NHEAD;
    const size_t row = (size_t)b * SEQ + l;
    const int c = h * HEAD_DIM + d;
    const float q  = g_QKV[row * 2304 + c];
    const float k  = g_QKV[row * 2304 + 768 + c];
    const float pq = g_PQ[row * 768 + c];
    const float pk = g_PK[row * 768 + c];
    const float k2 = k + pq;
    const __nv_bfloat16 qh = __float2bfloat16(q);
    const __nv_bfloat16 ql = __float2bfloat16(q - __bfloat162float(qh));
    const __nv_bfloat16 kh = __float2bfloat16(k2);
    const __nv_bfloat16 kl = __float2bfloat16(k2 - __bfloat162float(kh));
    const size_t base = ((size_t)bh * SEQ + l) * DQK;
    g_Qc[base + d]        = qh;
    g_Qc[base + 64 + d]   = qh;
    g_Qc[base + 128 + d]  = ql;
    g_Qc[base + 192 + d]  = __float2bfloat16(k * INV_SCALE);
    g_Kc[base + d]        = kh;
    g_Kc[base + 64 + d]   = kl;
    g_Kc[base + 128 + d]  = kh;
    g_Kc[base + 192 + d]  = __float2bfloat16(pk);
}

// V: fp16, transposed to [bh][d][l] via smem tile transpose
__global__ __launch_bounds__(256) void vtrans_kernel()
{
    __shared__ float ts[64][65];
    const int lt = blockIdx.x, bh = blockIdx.y;
    const int b = bh / NHEAD, h = bh - b * NHEAD;
    const int tid = threadIdx.x;
    {
        const int ll = tid >> 2, ds = (tid & 3) * 16;
        const float* src = g_QKV + ((size_t)(b * SEQ + lt * 64 + ll)) * 2304
                         + 1536 + h * HEAD_DIM + ds;
        #pragma unroll
        for (int i = 0; i < 4; i++) {
            float4 v = *(const float4*)(src + i * 4);
            ts[ll][ds + i * 4 + 0] = v.x;
            ts[ll][ds + i * 4 + 1] = v.y;
            ts[ll][ds + i * 4 + 2] = v.z;
            ts[ll][ds + i * 4 + 3] = v.w;
        }
    }
    __syncthreads();
    {
        const int d = tid >> 2, ls = (tid & 3) * 16;
        __half* dst = g_Vt + ((size_t)bh * HEAD_DIM + d) * SEQ + lt * 64 + ls;
        #pragma unroll
        for (int i = 0; i < 8; i++) {
            __half2 hv = __floats2half2_rn(ts[ls + 2 * i][d], ts[ls + 2 * i + 1][d]);
            *(__half2*)(dst + 2 * i) = hv;
        }
    }
}

// ==================== mma.sync flash attention ====================
// BM=128 q rows/CTA, 8 warps (16 rows each), BN=64 keys/tile, DQK=256.
#define ABM 128
#define ABN 64
#define AQP 264                         // Q/K smem pitch (bf16 elems); 528B rows
#define AVP 72                          // Vt smem pitch (half elems); 144B rows
#define SQ_OFF 0
#define SQ_BYTES (ABM * AQP * 2)        // 67584
#define SK_OFF SQ_BYTES
#define SK_BYTES (ABN * AQP * 2)        // 33792
#define SV_OFF (SK_OFF + 2 * SK_BYTES)
#define SV_BYTES (ABN * AVP * 2)        // 9216
#define ASMEM (SV_OFF + 2 * SV_BYTES)   // 153600

__global__ __launch_bounds__(256, 1) void attn_mma(float* __restrict__ out)
{
    extern __shared__ char smc[];
    const uint32_t sb = smem_u32(smc);
    const int tid = threadIdx.x, lane = tid & 31, w = tid >> 5;
    const int qb = blockIdx.x, bh = blockIdx.y;
    const int g = lane >> 2, t = lane & 3;

    const __nv_bfloat16* Qg = g_Qc + ((size_t)bh * SEQ + (size_t)qb * ABM) * DQK;
    const __nv_bfloat16* Kg = g_Kc + (size_t)bh * SEQ * DQK;
    const __half*        Vg = g_Vt + (size_t)bh * HEAD_DIM * SEQ;

    // ---- load Q (128 rows x 512B) ----
    #pragma unroll
    for (int it = 0; it < 16; it++) {
        const int idx = it * 256 + tid;
        const int r = idx >> 5, s = idx & 31;
        cp16(sb + SQ_OFF + (uint32_t)(r * AQP + s * 8) * 2, Qg + (size_t)r * DQK + s * 8);
    }

    auto loadKV = [&](int kt, int buf) {
        const __nv_bfloat16* Kt = Kg + (size_t)kt * ABN * DQK;
        #pragma unroll
        for (int it = 0; it < 8; it++) {
            const int idx = it * 256 + tid;
            const int r = idx >> 5, s = idx & 31;
            cp16(sb + SK_OFF + buf * SK_BYTES + (uint32_t)(r * AQP + s * 8) * 2,
                 Kt + (size_t)r * DQK + s * 8);
        }
        #pragma unroll
        for (int it = 0; it < 2; it++) {
            const int idx = it * 256 + tid;
            const int r = idx >> 3, s = idx & 7;
            cp16(sb + SV_OFF + buf * SV_BYTES + (uint32_t)(r * AVP + s * 8) * 2,
                 Vg + (size_t)r * SEQ + kt * ABN + s * 8);
        }
    };
    loadKV(0, 0);
    cp_commit();

    // ldmatrix per-lane offsets (bytes)
    const uint32_t aoff = (uint32_t)((w * 16 + (lane & 15)) * AQP + (lane >> 4) * 8) * 2;
    const uint32_t kfrag = (uint32_t)((((lane >> 4) & 1) * 8 + (lane & 7)) * AQP
                                     + ((lane >> 3) & 1) * 8) * 2;
    const uint32_t vfrag = (uint32_t)((((lane >> 4) & 1) * 8 + (lane & 7)) * AVP
                                     + ((lane >> 3) & 1) * 8) * 2;

    float m0 = -1e30f, m1 = -1e30f, l0 = 0.0f, l1 = 0.0f;
    float o[8][4];
    #pragma unroll
    for (int f = 0; f < 8; f++)
        #pragma unroll
        for (int j = 0; j < 4; j++) o[f][j] = 0.0f;

    for (int kt = 0; kt < SEQ / ABN; kt++) {
        if (kt + 1 < SEQ / ABN) {
            loadKV(kt + 1, (kt + 1) & 1);
            cp_commit();
            cp_wait<1>();
        } else {
            cp_wait<0>();
        }
        __syncthreads();

        const uint32_t sK = sb + SK_OFF + (kt & 1) * SK_BYTES;
        const uint32_t sV = sb + SV_OFF + (kt & 1) * SV_BYTES;

        // ---- S = Q'' @ K''^T  (m16 x n64 per warp, k=256) ----
        float c[8][4];
        #pragma unroll
        for (int f = 0; f < 8; f++)
            #pragma unroll
            for (int j = 0; j < 4; j++) c[f][j] = 0.0f;

        #pragma unroll
        for (int ks = 0; ks < DQK / 16; ks++) {
            uint32_t a[4];
            ldm_x4(a[0], a[1], a[2], a[3], sb + SQ_OFF + aoff + ks * 32);
            #pragma unroll
            for (int fb = 0; fb < 4; fb++) {
                uint32_t b[4];
                ldm_x4(b[0], b[1], b[2], b[3],
                       sK + kfrag + (uint32_t)(fb * 16 * AQP) * 2 + ks * 32);
                mma16816(c[fb * 2],     a, b[0], b[1]);
                mma16816(c[fb * 2 + 1], a, b[2], b[3]);
            }
        }

        // ---- online softmax (rows g and g+8; quad-lane reductions) ----
        float mx0 = c[0][0], mx1 = c[0][2];
        #pragma unroll
        for (int f = 0; f < 8; f++) {
            mx0 = fmaxf(mx0, fmaxf(c[f][0], c[f][1]));
            mx1 = fmaxf(mx1, fmaxf(c[f][2], c[f][3]));
        }
        mx0 = fmaxf(mx0, __shfl_xor_sync(0xffffffffu, mx0, 1));
        mx0 = fmaxf(mx0, __shfl_xor_sync(0xffffffffu, mx0, 2));
        mx1 = fmaxf(mx1, __shfl_xor_sync(0xffffffffu, mx1, 1));
        mx1 = fmaxf(mx1, __shfl_xor_sync(0xffffffffu, mx1, 2));
        const float nm0 = fmaxf(m0, mx0), nm1 = fmaxf(m1, mx1);
        const float cr0 = __expf(m0 - nm0), cr1 = __expf(m1 - nm1);
        m0 = nm0; m1 = nm1;
        float rs0 = 0.0f, rs1 = 0.0f;
        #pragma unroll
        for (int f = 0; f < 8; f++) {
            c[f][0] = __expf(c[f][0] - nm0); rs0 += c[f][0];
            c[f][1] = __expf(c[f][1] - nm0); rs0 += c[f][1];
            c[f][2] = __expf(c[f][2] - nm1); rs1 += c[f][2];
            c[f][3] = __expf(c[f][3] - nm1); rs1 += c[f][3];
        }
        l0 = l0 * cr0 + rs0;
        l1 = l1 * cr1 + rs1;
        #pragma unroll
        for (int f = 0; f < 8; f++) {
            o[f][0] *= cr0; o[f][1] *= cr0;
            o[f][2] *= cr1; o[f][3] *= cr1;
        }

        // ---- O += P @ V  (P from registers as fp16 A-frags; V fp16 in smem) ----
        #pragma unroll
        for (int ks = 0; ks < ABN / 16; ks++) {
            uint32_t pa[4];
            pa[0] = pack_h2(c[2 * ks][0],     c[2 * ks][1]);
            pa[1] = pack_h2(c[2 * ks][2],     c[2 * ks][3]);
            pa[2] = pack_h2(c[2 * ks + 1][0], c[2 * ks + 1][1]);
            pa[3] = pack_h2(c[2 * ks + 1][2], c[2 * ks + 1][3]);
            #pragma unroll
            for (int fb = 0; fb < 4; fb++) {
                uint32_t vb[4];
                ldm_x4(vb[0], vb[1], vb[2], vb[3],
                       sV + vfrag + (uint32_t)(fb * 16 * AVP) * 2 + ks * 32);
                mma16816h(o[fb * 2],     pa, vb[0], vb[1]);
                mma16816h(o[fb * 2 + 1], pa, vb[2], vb[3]);
            }
        }
        __syncthreads();
    }

    // ---- epilogue ----
    l0 += __shfl_xor_sync(0xffffffffu, l0, 1);
    l0 += __shfl_xor_sync(0xffffffffu, l0, 2);
    l1 += __shfl_xor_sync(0xffffffffu, l1, 1);
    l1 += __shfl_xor_sync(0xffffffffu, l1, 2);
    const float inv0 = 1.0f / l0, inv1 = 1.0f / l1;
    const int b_ = bh / NHEAD, h = bh - b_ * NHEAD;
    const int r0 = qb * ABM + w * 16 + g;
    float* p0 = out + (((size_t)(b_ * SEQ + r0)) * NHEAD + h) * HEAD_DIM;
    float* p1 = out + (((size_t)(b_ * SEQ + r0 + 8)) * NHEAD + h) * HEAD_DIM;
    #pragma unroll
    for (int f = 0; f < 8; f++) {
        const int col = f * 8 + t * 2;
        *(float2*)(p0 + col) = make_float2(o[f][0] * inv0, o[f][1] * inv0);
        *(float2*)(p1 + col) = make_float2(o[f][2] * inv1, o[f][3] * inv1);
    }
}

// ====================================================================
extern "C" void kernel_launch(void* const* d_in, const int* in_sizes, int n_in,
                              void* d_out, int out_size)
{
    const float* x     = (const float*)d_in[0];
    const float* pos   = (const float*)d_in[1];
    const float* qkv_w = (const float*)d_in[2];
    const float* qkv_b = (const float*)d_in[3];
    const float* pq_w  = (const float*)d_in[4];
    const float* pq_b  = (const float*)d_in[5];
    const float* pk_w  = (const float*)d_in[6];
    const float* pk_b  = (const float*)d_in[7];
    float* out = (float*)d_out;

    float *qkv, *pq, *pk;
    cudaGetSymbolAddress((void**)&qkv, g_QKV);
    cudaGetSymbolAddress((void**)&pq,  g_PQ);
    cudaGetSymbolAddress((void**)&pk,  g_PK);
    __nv_bfloat16 *xs, *ps, *wq, *wpq, *wpk;
    cudaGetSymbolAddress((void**)&xs,  g_xs);
    cudaGetSymbolAddress((void**)&ps,  g_ps);
    cudaGetSymbolAddress((void**)&wq,  g_wq);
    cudaGetSymbolAddress((void**)&wpq, g_wpq);
    cudaGetSymbolAddress((void**)&wpk, g_wpk);

    const int nx  = M_ROWS * D_MODEL;
    const int nwq = 3 * D_MODEL * D_MODEL;
    const int nw  = D_MODEL * D_MODEL;
    split_cat_a<<<(nx + 255) / 256, 256>>>(x, xs, nx);
    split_cat_a<<<(nx + 255) / 256, 256>>>(pos, ps, nx);
    split_cat_w<<<(nwq + 255) / 256, 256>>>(qkv_w, wq, nwq);
    split_cat_w<<<(nw + 255) / 256, 256>>>(pq_w, wpq, nw);
    split_cat_w<<<(nw + 255) / 256, 256>>>(pk_w, wpk, nw);

    cudaFuncSetAttribute(gemm_mma, cudaFuncAttributeMaxDynamicSharedMemorySize, GSMEM);
    gemm_mma<<<dim3(3 * D_MODEL / 128, M_ROWS / 128), 256, GSMEM>>>(
        xs, wq, qkv_b, qkv, 3 * D_MODEL);
    gemm_mma<<<dim3(D_MODEL / 128, M_ROWS / 128), 256, GSMEM>>>(
        ps, wpq, pq_b, pq, D_MODEL);
    gemm_mma<<<dim3(D_MODEL / 128, M_ROWS / 128), 256, GSMEM>>>(
        ps, wpk, pk_b, pk, D_MODEL);

    build_qc_kc<<<(BH * SEQ * 64) / 256, 256>>>();
    vtrans_kernel<<<dim3(SEQ / 64, BH), 256>>>();

    cudaFuncSetAttribute(attn_mma, cudaFuncAttributeMaxDynamicSharedMemorySize, ASMEM);
    attn_mma<<<dim3(SEQ / ABM, BH), 256, ASMEM>>>(out);
}

// round 7
// speedup vs baseline: 3.4690x; 1.0744x over previous
#include <cuda_runtime.h>
#include <cuda_bf16.h>
#include <cuda_fp16.h>
#include <cstdint>
#include <cstddef>

#define D_MODEL 768
#define NHEAD   12
#define HEAD_DIM 64
#define BATCH   8
#define SEQ     1024
#define BH      (BATCH * NHEAD)     // 96
#define M_ROWS  (BATCH * SEQ)       // 8192
#define DQK     256                 // concat-split attention dim
#define INV_SCALE (1.0f / 48.0f)    // 1/sqrt(3*768)

// ---------------- scratch (static device allocation; no cudaMalloc) ----------------
__device__ float g_QKV [M_ROWS * 3 * D_MODEL];
__device__ float g_PQ  [M_ROWS * D_MODEL];
__device__ float g_PK  [M_ROWS * D_MODEL];

// attention operands
__device__ __nv_bfloat16 g_Qc[(size_t)BH * SEQ * DQK];   // [qh|qh|ql|k/48]
__device__ __nv_bfloat16 g_Kc[(size_t)BH * SEQ * DQK];   // [k'h|k'l|k'h|pk]
__device__ __half        g_Vt[(size_t)BH * HEAD_DIM * SEQ]; // transposed [bh][d][l]

// split-bf16 hi/lo planes for projections
__device__ __nv_bfloat16 g_xh [M_ROWS * D_MODEL];
__device__ __nv_bfloat16 g_xl [M_ROWS * D_MODEL];
__device__ __nv_bfloat16 g_ph [M_ROWS * D_MODEL];
__device__ __nv_bfloat16 g_pl [M_ROWS * D_MODEL];
__device__ __nv_bfloat16 g_wqh[3 * D_MODEL * D_MODEL];
__device__ __nv_bfloat16 g_wql[3 * D_MODEL * D_MODEL];
__device__ __nv_bfloat16 g_wpqh[D_MODEL * D_MODEL];
__device__ __nv_bfloat16 g_wpql[D_MODEL * D_MODEL];
__device__ __nv_bfloat16 g_wpkh[D_MODEL * D_MODEL];
__device__ __nv_bfloat16 g_wpkl[D_MODEL * D_MODEL];

// ==================== helpers ====================
__device__ __forceinline__ uint32_t smem_u32(const void* p) {
    uint32_t a;
    asm("{ .reg .u64 t; cvta.to.shared.u64 t, %1; cvt.u32.u64 %0, t; }" : "=r"(a) : "l"(p));
    return a;
}
__device__ __forceinline__ void cp16(uint32_t dst, const void* src) {
    asm volatile("cp.async.cg.shared.global [%0], [%1], 16;" :: "r"(dst), "l"(src));
}
__device__ __forceinline__ void cp_commit() {
    asm volatile("cp.async.commit_group;" ::: "memory");
}
template <int N>
__device__ __forceinline__ void cp_wait() {
    asm volatile("cp.async.wait_group %0;" :: "n"(N) : "memory");
}
__device__ __forceinline__ void ldm_x4(uint32_t& r0, uint32_t& r1, uint32_t& r2,
                                       uint32_t& r3, uint32_t addr) {
    asm volatile("ldmatrix.sync.aligned.m8n8.x4.shared.b16 {%0,%1,%2,%3}, [%4];"
                 : "=r"(r0), "=r"(r1), "=r"(r2), "=r"(r3) : "r"(addr));
}
__device__ __forceinline__ void mma16816(float* c, const uint32_t* a,
                                         uint32_t b0, uint32_t b1) {
    asm volatile(
        "mma.sync.aligned.m16n8k16.row.col.f32.bf16.bf16.f32 "
        "{%0,%1,%2,%3}, {%4,%5,%6,%7}, {%8,%9}, {%0,%1,%2,%3};"
        : "+f"(c[0]), "+f"(c[1]), "+f"(c[2]), "+f"(c[3])
        : "r"(a[0]), "r"(a[1]), "r"(a[2]), "r"(a[3]), "r"(b0), "r"(b1));
}
__device__ __forceinline__ void mma16816h(float* c, const uint32_t* a,
                                          uint32_t b0, uint32_t b1) {
    asm volatile(
        "mma.sync.aligned.m16n8k16.row.col.f32.f16.f16.f32 "
        "{%0,%1,%2,%3}, {%4,%5,%6,%7}, {%8,%9}, {%0,%1,%2,%3};"
        : "+f"(c[0]), "+f"(c[1]), "+f"(c[2]), "+f"(c[3])
        : "r"(a[0]), "r"(a[1]), "r"(a[2]), "r"(a[3]), "r"(b0), "r"(b1));
}
__device__ __forceinline__ uint32_t pack_h2(float lo, float hi) {
    __half2 h = __floats2half2_rn(lo, hi);
    return *(uint32_t*)&h;
}

// ==================== launch 1: fused split fp32 -> (hi, lo) bf16 planes ====================
#define NXE (M_ROWS * D_MODEL)          // 6291456
#define NWQE (3 * D_MODEL * D_MODEL)    // 1769472
#define NWE (D_MODEL * D_MODEL)         // 589824
#define SPLIT_TOTAL (2 * NXE + NWQE + 2 * NWE)

__global__ __launch_bounds__(256) void split_all(
    const float* __restrict__ x, const float* __restrict__ pos,
    const float* __restrict__ wq, const float* __restrict__ wpq,
    const float* __restrict__ wpk)
{
    const int i = blockIdx.x * 256 + threadIdx.x;
    float v;
    __nv_bfloat16 *hi, *lo;
    int j;
    if (i < NXE)                       { j = i;                     v = x[j];   hi = g_xh;   lo = g_xl;   }
    else if (i < 2 * NXE)              { j = i - NXE;               v = pos[j]; hi = g_ph;   lo = g_pl;   }
    else if (i < 2 * NXE + NWQE)       { j = i - 2 * NXE;           v = wq[j];  hi = g_wqh;  lo = g_wql;  }
    else if (i < 2 * NXE + NWQE + NWE) { j = i - 2 * NXE - NWQE;    v = wpq[j]; hi = g_wpqh; lo = g_wpql; }
    else if (i < SPLIT_TOTAL)          { j = i - 2 * NXE - NWQE - NWE; v = wpk[j]; hi = g_wpkh; lo = g_wpkl; }
    else return;
    __nv_bfloat16 h = __float2bfloat16(v);
    hi[j] = h;
    lo[j] = __float2bfloat16(v - __bfloat162float(h));
}

// ==================== launch 2: fused split-bf16 GEMM, 256x128 tiles ====================
// C = Ah*Wh^T + Ah*Wl^T + Al*Wh^T + bias.  K=768, BK=64, 512 threads, 16 warps (8m x 2n).
#define GK    768
#define GBK   64
#define GPIT  72                          // padded pitch (elems), 144B rows
#define OFF_AH 0
#define OFF_AL (256 * GPIT * 2)           // 36864
#define OFF_WH (2 * 256 * GPIT * 2)       // 73728
#define OFF_WL (OFF_WH + 128 * GPIT * 2)  // 92160
#define GBUFB  (OFF_WL + 128 * GPIT * 2)  // 110592 bytes per buffer
#define GSMEM2 (2 * GBUFB)                // 221184

__global__ __launch_bounds__(512, 1) void gemm256(
    const __nv_bfloat16* __restrict__ xh, const __nv_bfloat16* __restrict__ xl,
    const __nv_bfloat16* __restrict__ ph, const __nv_bfloat16* __restrict__ pl,
    const __nv_bfloat16* __restrict__ wqh, const __nv_bfloat16* __restrict__ wql,
    const __nv_bfloat16* __restrict__ wpqh, const __nv_bfloat16* __restrict__ wpql,
    const __nv_bfloat16* __restrict__ wpkh, const __nv_bfloat16* __restrict__ wpkl,
    const float* __restrict__ qkv_b, const float* __restrict__ pq_b,
    const float* __restrict__ pk_b)
{
    extern __shared__ char smg[];
    const uint32_t sbase = smem_u32(smg);
    const int tid = threadIdx.x, lane = tid & 31, wid = tid >> 5;
    const int wm = wid >> 1;             // 0..7 -> m offset wm*32
    const int wn = wid & 1;              // 0..1 -> n offset wn*64
    const int bx = blockIdx.x;
    const int rowBase = blockIdx.y << 8; // *256

    const __nv_bfloat16 *Ah, *Al, *Wh, *Wl;
    const float* bias;
    float* C;
    int N, colBase;
    if (bx < 18)      { Ah = xh; Al = xl; Wh = wqh;  Wl = wql;  bias = qkv_b; C = g_QKV; N = 2304; colBase = bx * 128; }
    else if (bx < 24) { Ah = ph; Al = pl; Wh = wpqh; Wl = wpql; bias = pq_b;  C = g_PQ;  N = 768;  colBase = (bx - 18) * 128; }
    else              { Ah = ph; Al = pl; Wh = wpkh; Wl = wpkl; bias = pk_b;  C = g_PK;  N = 768;  colBase = (bx - 24) * 128; }

    const __nv_bfloat16* Ahg = Ah + (size_t)rowBase * GK;
    const __nv_bfloat16* Alg = Al + (size_t)rowBase * GK;
    const __nv_bfloat16* Whg = Wh + (size_t)colBase * GK;
    const __nv_bfloat16* Wlg = Wl + (size_t)colBase * GK;

    // ldmatrix per-lane offsets (bytes)
    const uint32_t aoff = ((uint32_t)((wm * 32 + (lane & 15)) * GPIT + ((lane >> 4) * 8))) * 2;
    const uint32_t woff = ((uint32_t)((wn * 64 + ((lane >> 4) & 1) * 8 + (lane & 7)) * GPIT
                                     + (((lane >> 3) & 1) * 8))) * 2;

    float c[2][8][4];
    #pragma unroll
    for (int i = 0; i < 2; i++)
        #pragma unroll
        for (int j = 0; j < 8; j++)
            #pragma unroll
            for (int k = 0; k < 4; k++) c[i][j][k] = 0.0f;

    auto load_chunk = [&](int ch, int buf) {
        const uint32_t base = sbase + (uint32_t)buf * GBUFB;
        const int k0 = ch * GBK;
        #pragma unroll
        for (int it = 0; it < 4; it++) {                 // A planes: 256 rows x 8 segs
            const int idx = it * 512 + tid;
            const int row = idx >> 3, seg = (idx & 7) * 8;
            const uint32_t so = (uint32_t)(row * GPIT + seg) * 2;
            cp16(base + OFF_AH + so, Ahg + (size_t)row * GK + k0 + seg);
            cp16(base + OFF_AL + so, Alg + (size_t)row * GK + k0 + seg);
        }
        #pragma unroll
        for (int it = 0; it < 2; it++) {                 // W planes: 128 rows x 8 segs
            const int idx = it * 512 + tid;
            const int row = idx >> 3, seg = (idx & 7) * 8;
            const uint32_t so = (uint32_t)(row * GPIT + seg) * 2;
            cp16(base + OFF_WH + so, Whg + (size_t)row * GK + k0 + seg);
            cp16(base + OFF_WL + so, Wlg + (size_t)row * GK + k0 + seg);
        }
    };

    load_chunk(0, 0);
    cp_commit();

    const int NCH = GK / GBK;   // 12
    for (int ch = 0; ch < NCH; ch++) {
        if (ch + 1 < NCH) {
            load_chunk(ch + 1, (ch + 1) & 1);
            cp_commit();
            cp_wait<1>();
        } else {
            cp_wait<0>();
        }
        __syncthreads();

        const uint32_t base = sbase + (uint32_t)(ch & 1) * GBUFB;
        #pragma unroll
        for (int kk = 0; kk < GBK; kk += 16) {
            uint32_t ah[2][4], al[2][4];
            #pragma unroll
            for (int fa = 0; fa < 2; fa++) {
                ldm_x4(ah[fa][0], ah[fa][1], ah[fa][2], ah[fa][3],
                       base + OFF_AH + aoff + (uint32_t)(fa * 16 * GPIT + kk) * 2);
                ldm_x4(al[fa][0], al[fa][1], al[fa][2], al[fa][3],
                       base + OFF_AL + aoff + (uint32_t)(fa * 16 * GPIT + kk) * 2);
            }
            #pragma unroll
            for (int fb = 0; fb < 4; fb++) {
                uint32_t b[4];
                ldm_x4(b[0], b[1], b[2], b[3],
                       base + OFF_WH + woff + (uint32_t)(fb * 16 * GPIT + kk) * 2);
                #pragma unroll
                for (int fa = 0; fa < 2; fa++) {
                    mma16816(c[fa][fb * 2],     ah[fa], b[0], b[1]);
                    mma16816(c[fa][fb * 2 + 1], ah[fa], b[2], b[3]);
                    mma16816(c[fa][fb * 2],     al[fa], b[0], b[1]);
                    mma16816(c[fa][fb * 2 + 1], al[fa], b[2], b[3]);
                }
                ldm_x4(b[0], b[1], b[2], b[3],
                       base + OFF_WL + woff + (uint32_t)(fb * 16 * GPIT + kk) * 2);
                #pragma unroll
                for (int fa = 0; fa < 2; fa++) {
                    mma16816(c[fa][fb * 2],     ah[fa], b[0], b[1]);
                    mma16816(c[fa][fb * 2 + 1], ah[fa], b[2], b[3]);
                }
            }
        }
        __syncthreads();
    }

    // ---- epilogue ----
    const int gq = lane >> 2, tq = lane & 3;
    #pragma unroll
    for (int fa = 0; fa < 2; fa++) {
        #pragma unroll
        for (int nf = 0; nf < 8; nf++) {
            const int row = rowBase + wm * 32 + fa * 16 + gq;
            const int col = colBase + wn * 64 + nf * 8 + tq * 2;
            const float b0 = bias[col], b1 = bias[col + 1];
            float2 v0 = make_float2(c[fa][nf][0] + b0, c[fa][nf][1] + b1);
            float2 v1 = make_float2(c[fa][nf][2] + b0, c[fa][nf][3] + b1);
            *(float2*)(C + (size_t)row * N + col) = v0;
            *(float2*)(C + (size_t)(row + 8) * N + col) = v1;
        }
    }
}

// ==================== launch 3: fused build (Qc/Kc) + V transpose ====================
#define BQK_BLOCKS ((BH * SEQ * 64) / 256)   // 24576
#define VT_BLOCKS  ((SEQ / 64) * BH)         // 1536

__global__ __launch_bounds__(256) void build_all()
{
    __shared__ float ts[64][65];
    const int bxall = blockIdx.x;
    const int tid = threadIdx.x;

    if (bxall < BQK_BLOCKS) {
        const int idx = bxall * 256 + tid;
        const int d  = idx & 63;
        const int l  = (idx >> 6) & (SEQ - 1);
        const int bh = idx >> 16;
        const int b  = bh / NHEAD, h = bh - b * NHEAD;
        const size_t row = (size_t)b * SEQ + l;
        const int c = h * HEAD_DIM + d;
        const float q  = g_QKV[row * 2304 + c];
        const float k  = g_QKV[row * 2304 + 768 + c];
        const float pq = g_PQ[row * 768 + c];
        const float pk = g_PK[row * 768 + c];
        const float k2 = k + pq;
        const __nv_bfloat16 qh = __float2bfloat16(q);
        const __nv_bfloat16 ql = __float2bfloat16(q - __bfloat162float(qh));
        const __nv_bfloat16 kh = __float2bfloat16(k2);
        const __nv_bfloat16 kl = __float2bfloat16(k2 - __bfloat162float(kh));
        const size_t base = ((size_t)bh * SEQ + l) * DQK;
        g_Qc[base + d]        = qh;
        g_Qc[base + 64 + d]   = qh;
        g_Qc[base + 128 + d]  = ql;
        g_Qc[base + 192 + d]  = __float2bfloat16(k * INV_SCALE);
        g_Kc[base + d]        = kh;
        g_Kc[base + 64 + d]   = kl;
        g_Kc[base + 128 + d]  = kh;
        g_Kc[base + 192 + d]  = __float2bfloat16(pk);
    } else {
        const int bx2 = bxall - BQK_BLOCKS;
        const int lt = bx2 & 15, bh = bx2 >> 4;
        const int b = bh / NHEAD, h = bh - b * NHEAD;
        {
            const int ll = tid >> 2, ds = (tid & 3) * 16;
            const float* src = g_QKV + ((size_t)(b * SEQ + lt * 64 + ll)) * 2304
                             + 1536 + h * HEAD_DIM + ds;
            #pragma unroll
            for (int i = 0; i < 4; i++) {
                float4 v = *(const float4*)(src + i * 4);
                ts[ll][ds + i * 4 + 0] = v.x;
                ts[ll][ds + i * 4 + 1] = v.y;
                ts[ll][ds + i * 4 + 2] = v.z;
                ts[ll][ds + i * 4 + 3] = v.w;
            }
        }
        __syncthreads();
        {
            const int d = tid >> 2, ls = (tid & 3) * 16;
            __half* dst = g_Vt + ((size_t)bh * HEAD_DIM + d) * SEQ + lt * 64 + ls;
            #pragma unroll
            for (int i = 0; i < 8; i++) {
                __half2 hv = __floats2half2_rn(ts[ls + 2 * i][d], ts[ls + 2 * i + 1][d]);
                *(__half2*)(dst + 2 * i) = hv;
            }
        }
    }
}

// ==================== launch 4: mma.sync flash attention (unchanged) ====================
#define ABM 128
#define ABN 64
#define AQP 264
#define AVP 72
#define SQ_OFF 0
#define SQ_BYTES (ABM * AQP * 2)
#define SK_OFF SQ_BYTES
#define SK_BYTES (ABN * AQP * 2)
#define SV_OFF (SK_OFF + 2 * SK_BYTES)
#define SV_BYTES (ABN * AVP * 2)
#define ASMEM (SV_OFF + 2 * SV_BYTES)

__global__ __launch_bounds__(256, 1) void attn_mma(float* __restrict__ out)
{
    extern __shared__ char smc[];
    const uint32_t sb = smem_u32(smc);
    const int tid = threadIdx.x, lane = tid & 31, w = tid >> 5;
    const int qb = blockIdx.x, bh = blockIdx.y;
    const int g = lane >> 2, t = lane & 3;

    const __nv_bfloat16* Qg = g_Qc + ((size_t)bh * SEQ + (size_t)qb * ABM) * DQK;
    const __nv_bfloat16* Kg = g_Kc + (size_t)bh * SEQ * DQK;
    const __half*        Vg = g_Vt + (size_t)bh * HEAD_DIM * SEQ;

    #pragma unroll
    for (int it = 0; it < 16; it++) {
        const int idx = it * 256 + tid;
        const int r = idx >> 5, s = idx & 31;
        cp16(sb + SQ_OFF + (uint32_t)(r * AQP + s * 8) * 2, Qg + (size_t)r * DQK + s * 8);
    }

    auto loadKV = [&](int kt, int buf) {
        const __nv_bfloat16* Kt = Kg + (size_t)kt * ABN * DQK;
        #pragma unroll
        for (int it = 0; it < 8; it++) {
            const int idx = it * 256 + tid;
            const int r = idx >> 5, s = idx & 31;
            cp16(sb + SK_OFF + buf * SK_BYTES + (uint32_t)(r * AQP + s * 8) * 2,
                 Kt + (size_t)r * DQK + s * 8);
        }
        #pragma unroll
        for (int it = 0; it < 2; it++) {
            const int idx = it * 256 + tid;
            const int r = idx >> 3, s = idx & 7;
            cp16(sb + SV_OFF + buf * SV_BYTES + (uint32_t)(r * AVP + s * 8) * 2,
                 Vg + (size_t)r * SEQ + kt * ABN + s * 8);
        }
    };
    loadKV(0, 0);
    cp_commit();

    const uint32_t aoff = (uint32_t)((w * 16 + (lane & 15)) * AQP + (lane >> 4) * 8) * 2;
    const uint32_t kfrag = (uint32_t)((((lane >> 4) & 1) * 8 + (lane & 7)) * AQP
                                     + ((lane >> 3) & 1) * 8) * 2;
    const uint32_t vfrag = (uint32_t)((((lane >> 4) & 1) * 8 + (lane & 7)) * AVP
                                     + ((lane >> 3) & 1) * 8) * 2;

    float m0 = -1e30f, m1 = -1e30f, l0 = 0.0f, l1 = 0.0f;
    float o[8][4];
    #pragma unroll
    for (int f = 0; f < 8; f++)
        #pragma unroll
        for (int j = 0; j < 4; j++) o[f][j] = 0.0f;

    for (int kt = 0; kt < SEQ / ABN; kt++) {
        if (kt + 1 < SEQ / ABN) {
            loadKV(kt + 1, (kt + 1) & 1);
            cp_commit();
            cp_wait<1>();
        } else {
            cp_wait<0>();
        }
        __syncthreads();

        const uint32_t sK = sb + SK_OFF + (kt & 1) * SK_BYTES;
        const uint32_t sV = sb + SV_OFF + (kt & 1) * SV_BYTES;

        float c[8][4];
        #pragma unroll
        for (int f = 0; f < 8; f++)
            #pragma unroll
            for (int j = 0; j < 4; j++) c[f][j] = 0.0f;

        #pragma unroll
        for (int ks = 0; ks < DQK / 16; ks++) {
            uint32_t a[4];
            ldm_x4(a[0], a[1], a[2], a[3], sb + SQ_OFF + aoff + ks * 32);
            #pragma unroll
            for (int fb = 0; fb < 4; fb++) {
                uint32_t b[4];
                ldm_x4(b[0], b[1], b[2], b[3],
                       sK + kfrag + (uint32_t)(fb * 16 * AQP) * 2 + ks * 32);
                mma16816(c[fb * 2],     a, b[0], b[1]);
                mma16816(c[fb * 2 + 1], a, b[2], b[3]);
            }
        }

        float mx0 = c[0][0], mx1 = c[0][2];
        #pragma unroll
        for (int f = 0; f < 8; f++) {
            mx0 = fmaxf(mx0, fmaxf(c[f][0], c[f][1]));
            mx1 = fmaxf(mx1, fmaxf(c[f][2], c[f][3]));
        }
        mx0 = fmaxf(mx0, __shfl_xor_sync(0xffffffffu, mx0, 1));
        mx0 = fmaxf(mx0, __shfl_xor_sync(0xffffffffu, mx0, 2));
        mx1 = fmaxf(mx1, __shfl_xor_sync(0xffffffffu, mx1, 1));
        mx1 = fmaxf(mx1, __shfl_xor_sync(0xffffffffu, mx1, 2));
        const float nm0 = fmaxf(m0, mx0), nm1 = fmaxf(m1, mx1);
        const float cr0 = __expf(m0 - nm0), cr1 = __expf(m1 - nm1);
        m0 = nm0; m1 = nm1;
        float rs0 = 0.0f, rs1 = 0.0f;
        #pragma unroll
        for (int f = 0; f < 8; f++) {
            c[f][0] = __expf(c[f][0] - nm0); rs0 += c[f][0];
            c[f][1] = __expf(c[f][1] - nm0); rs0 += c[f][1];
            c[f][2] = __expf(c[f][2] - nm1); rs1 += c[f][2];
            c[f][3] = __expf(c[f][3] - nm1); rs1 += c[f][3];
        }
        l0 = l0 * cr0 + rs0;
        l1 = l1 * cr1 + rs1;
        #pragma unroll
        for (int f = 0; f < 8; f++) {
            o[f][0] *= cr0; o[f][1] *= cr0;
            o[f][2] *= cr1; o[f][3] *= cr1;
        }

        #pragma unroll
        for (int ks = 0; ks < ABN / 16; ks++) {
            uint32_t pa[4];
            pa[0] = pack_h2(c[2 * ks][0],     c[2 * ks][1]);
            pa[1] = pack_h2(c[2 * ks][2],     c[2 * ks][3]);
            pa[2] = pack_h2(c[2 * ks + 1][0], c[2 * ks + 1][1]);
            pa[3] = pack_h2(c[2 * ks + 1][2], c[2 * ks + 1][3]);
            #pragma unroll
            for (int fb = 0; fb < 4; fb++) {
                uint32_t vb[4];
                ldm_x4(vb[0], vb[1], vb[2], vb[3],
                       sV + vfrag + (uint32_t)(fb * 16 * AVP) * 2 + ks * 32);
                mma16816h(o[fb * 2],     pa, vb[0], vb[1]);
                mma16816h(o[fb * 2 + 1], pa, vb[2], vb[3]);
            }
        }
        __syncthreads();
    }

    l0 += __shfl_xor_sync(0xffffffffu, l0, 1);
    l0 += __shfl_xor_sync(0xffffffffu, l0, 2);
    l1 += __shfl_xor_sync(0xffffffffu, l1, 1);
    l1 += __shfl_xor_sync(0xffffffffu, l1, 2);
    const float inv0 = 1.0f / l0, inv1 = 1.0f / l1;
    const int b_ = bh / NHEAD, h = bh - b_ * NHEAD;
    const int r0 = qb * ABM + w * 16 + g;
    float* p0 = out + (((size_t)(b_ * SEQ + r0)) * NHEAD + h) * HEAD_DIM;
    float* p1 = out + (((size_t)(b_ * SEQ + r0 + 8)) * NHEAD + h) * HEAD_DIM;
    #pragma unroll
    for (int f = 0; f < 8; f++) {
        const int col = f * 8 + t * 2;
        *(float2*)(p0 + col) = make_float2(o[f][0] * inv0, o[f][1] * inv0);
        *(float2*)(p1 + col) = make_float2(o[f][2] * inv1, o[f][3] * inv1);
    }
}

// ====================================================================
extern "C" void kernel_launch(void* const* d_in, const int* in_sizes, int n_in,
                              void* d_out, int out_size)
{
    const float* x     = (const float*)d_in[0];
    const float* pos   = (const float*)d_in[1];
    const float* qkv_w = (const float*)d_in[2];
    const float* qkv_b = (const float*)d_in[3];
    const float* pq_w  = (const float*)d_in[4];
    const float* pq_b  = (const float*)d_in[5];
    const float* pk_w  = (const float*)d_in[6];
    const float* pk_b  = (const float*)d_in[7];
    float* out = (float*)d_out;

    __nv_bfloat16 *xh, *xl, *ph, *pl, *wqh, *wql, *wpqh, *wpql, *wpkh, *wpkl;
    cudaGetSymbolAddress((void**)&xh,   g_xh);
    cudaGetSymbolAddress((void**)&xl,   g_xl);
    cudaGetSymbolAddress((void**)&ph,   g_ph);
    cudaGetSymbolAddress((void**)&pl,   g_pl);
    cudaGetSymbolAddress((void**)&wqh,  g_wqh);
    cudaGetSymbolAddress((void**)&wql,  g_wql);
    cudaGetSymbolAddress((void**)&wpqh, g_wpqh);
    cudaGetSymbolAddress((void**)&wpql, g_wpql);
    cudaGetSymbolAddress((void**)&wpkh, g_wpkh);
    cudaGetSymbolAddress((void**)&wpkl, g_wpkl);

    // 1) split into hi/lo bf16 planes
    split_all<<<(SPLIT_TOTAL + 255) / 256, 256>>>(x, pos, qkv_w, pq_w, pk_w);

    // 2) all three projections in one launch (256x128 tiles, 3-term split-bf16)
    cudaFuncSetAttribute(gemm256, cudaFuncAttributeMaxDynamicSharedMemorySize, GSMEM2);
    gemm256<<<dim3(30, 32), 512, GSMEM2>>>(xh, xl, ph, pl, wqh, wql,
                                           wpqh, wpql, wpkh, wpkl,
                                           qkv_b, pq_b, pk_b);

    // 3) build attention operands (Qc/Kc concat-split + V fp16 transpose)
    build_all<<<BQK_BLOCKS + VT_BLOCKS, 256>>>();

    // 4) flash attention
    cudaFuncSetAttribute(attn_mma, cudaFuncAttributeMaxDynamicSharedMemorySize, ASMEM);
    attn_mma<<<dim3(SEQ / ABM, BH), 256, ASMEM>>>(out);
}

// round 8
// speedup vs baseline: 3.6463x; 1.0511x over previous
#include <cuda_runtime.h>
#include <cuda_bf16.h>
#include <cuda_fp16.h>
#include <cstdint>
#include <cstddef>

#define D_MODEL 768
#define NHEAD   12
#define HEAD_DIM 64
#define BATCH   8
#define SEQ     1024
#define BH      (BATCH * NHEAD)     // 96
#define M_ROWS  (BATCH * SEQ)       // 8192
#define DQK     256                 // concat-split attention dim
#define INV_SCALE (1.0f / 48.0f)    // 1/sqrt(3*768)

// ---------------- scratch (static device allocation; no cudaMalloc) ----------------
__device__ float g_QKV [M_ROWS * 3 * D_MODEL];
__device__ float g_PQ  [M_ROWS * D_MODEL];
__device__ float g_PK  [M_ROWS * D_MODEL];

// attention operands
__device__ __nv_bfloat16 g_Qc[(size_t)BH * SEQ * DQK];   // [qh|qh|ql|k/48]
__device__ __nv_bfloat16 g_Kc[(size_t)BH * SEQ * DQK];   // [k'h|k'l|k'h|pk]
__device__ __half        g_Vt[(size_t)BH * HEAD_DIM * SEQ]; // transposed [bh][d][l]

// split-bf16 hi/lo planes for projections
__device__ __nv_bfloat16 g_xh [M_ROWS * D_MODEL];
__device__ __nv_bfloat16 g_xl [M_ROWS * D_MODEL];
__device__ __nv_bfloat16 g_ph [M_ROWS * D_MODEL];
__device__ __nv_bfloat16 g_pl [M_ROWS * D_MODEL];
__device__ __nv_bfloat16 g_wqh[3 * D_MODEL * D_MODEL];
__device__ __nv_bfloat16 g_wql[3 * D_MODEL * D_MODEL];
__device__ __nv_bfloat16 g_wpqh[D_MODEL * D_MODEL];
__device__ __nv_bfloat16 g_wpql[D_MODEL * D_MODEL];
__device__ __nv_bfloat16 g_wpkh[D_MODEL * D_MODEL];
__device__ __nv_bfloat16 g_wpkl[D_MODEL * D_MODEL];

// ==================== helpers ====================
__device__ __forceinline__ uint32_t smem_u32(const void* p) {
    uint32_t a;
    asm("{ .reg .u64 t; cvta.to.shared.u64 t, %1; cvt.u32.u64 %0, t; }" : "=r"(a) : "l"(p));
    return a;
}
__device__ __forceinline__ void cp16(uint32_t dst, const void* src) {
    asm volatile("cp.async.cg.shared.global [%0], [%1], 16;" :: "r"(dst), "l"(src));
}
__device__ __forceinline__ void cp_commit() {
    asm volatile("cp.async.commit_group;" ::: "memory");
}
template <int N>
__device__ __forceinline__ void cp_wait() {
    asm volatile("cp.async.wait_group %0;" :: "n"(N) : "memory");
}
__device__ __forceinline__ void ldm_x4(uint32_t& r0, uint32_t& r1, uint32_t& r2,
                                       uint32_t& r3, uint32_t addr) {
    asm volatile("ldmatrix.sync.aligned.m8n8.x4.shared.b16 {%0,%1,%2,%3}, [%4];"
                 : "=r"(r0), "=r"(r1), "=r"(r2), "=r"(r3) : "r"(addr));
}
__device__ __forceinline__ void mma16816(float* c, const uint32_t* a,
                                         uint32_t b0, uint32_t b1) {
    asm volatile(
        "mma.sync.aligned.m16n8k16.row.col.f32.bf16.bf16.f32 "
        "{%0,%1,%2,%3}, {%4,%5,%6,%7}, {%8,%9}, {%0,%1,%2,%3};"
        : "+f"(c[0]), "+f"(c[1]), "+f"(c[2]), "+f"(c[3])
        : "r"(a[0]), "r"(a[1]), "r"(a[2]), "r"(a[3]), "r"(b0), "r"(b1));
}
__device__ __forceinline__ void mma16816h(float* c, const uint32_t* a,
                                          uint32_t b0, uint32_t b1) {
    asm volatile(
        "mma.sync.aligned.m16n8k16.row.col.f32.f16.f16.f32 "
        "{%0,%1,%2,%3}, {%4,%5,%6,%7}, {%8,%9}, {%0,%1,%2,%3};"
        : "+f"(c[0]), "+f"(c[1]), "+f"(c[2]), "+f"(c[3])
        : "r"(a[0]), "r"(a[1]), "r"(a[2]), "r"(a[3]), "r"(b0), "r"(b1));
}
__device__ __forceinline__ uint32_t pack_h2(float lo, float hi) {
    __half2 h = __floats2half2_rn(lo, hi);
    return *(uint32_t*)&h;
}

// ==================== launch 1: fused split fp32 -> (hi, lo) bf16 planes ====================
#define NXE (M_ROWS * D_MODEL)          // 6291456
#define NWQE (3 * D_MODEL * D_MODEL)    // 1769472
#define NWE (D_MODEL * D_MODEL)         // 589824
#define SPLIT_TOTAL (2 * NXE + NWQE + 2 * NWE)
#define SPLIT_V4 (SPLIT_TOTAL / 4)

__global__ __launch_bounds__(256) void split_all(
    const float* __restrict__ x, const float* __restrict__ pos,
    const float* __restrict__ wq, const float* __restrict__ wpq,
    const float* __restrict__ wpk)
{
    const int i4 = blockIdx.x * 256 + threadIdx.x;
    if (i4 >= SPLIT_V4) return;
    const int i = i4 * 4;
    const float* src;
    __nv_bfloat16 *hi, *lo;
    int j;
    if (i < NXE)                       { j = i;                        src = x;   hi = g_xh;   lo = g_xl;   }
    else if (i < 2 * NXE)              { j = i - NXE;                  src = pos; hi = g_ph;   lo = g_pl;   }
    else if (i < 2 * NXE + NWQE)       { j = i - 2 * NXE;              src = wq;  hi = g_wqh;  lo = g_wql;  }
    else if (i < 2 * NXE + NWQE + NWE) { j = i - 2 * NXE - NWQE;       src = wpq; hi = g_wpqh; lo = g_wpql; }
    else                               { j = i - 2 * NXE - NWQE - NWE; src = wpk; hi = g_wpkh; lo = g_wpkl; }

    const float4 v = *(const float4*)(src + j);
    union { __nv_bfloat162 h2[2]; uint2 u; } H, L;
    __nv_bfloat16 h0 = __float2bfloat16(v.x), h1 = __float2bfloat16(v.y);
    __nv_bfloat16 h2 = __float2bfloat16(v.z), h3 = __float2bfloat16(v.w);
    H.h2[0] = __nv_bfloat162(h0, h1);
    H.h2[1] = __nv_bfloat162(h2, h3);
    L.h2[0] = __nv_bfloat162(__float2bfloat16(v.x - __bfloat162float(h0)),
                             __float2bfloat16(v.y - __bfloat162float(h1)));
    L.h2[1] = __nv_bfloat162(__float2bfloat16(v.z - __bfloat162float(h2)),
                             __float2bfloat16(v.w - __bfloat162float(h3)));
    *(uint2*)(hi + j) = H.u;
    *(uint2*)(lo + j) = L.u;
}

// ==================== launch 2: split-bf16 GEMM, 128x128 tiles, 2 CTAs/SM ====================
// C = Ah*Wh^T + Ah*Wl^T + Al*Wh^T + bias.  K=768, BK=32, 256 threads, 8 warps (4m x 2n).
#define GK    768
#define GBK2  32
#define GP2   40                          // pitch (elems): 80B rows, conflict-free LDSM
#define PL2B  (128 * GP2 * 2)             // 10240 bytes per plane
#define OFF2_AH 0
#define OFF2_AL PL2B
#define OFF2_WH (2 * PL2B)
#define OFF2_WL (3 * PL2B)
#define GBUF2  (4 * PL2B)                 // 40960 per buffer
#define GSM2   (2 * GBUF2)                // 81920 total -> 2 CTAs/SM

__global__ __launch_bounds__(256, 2) void gemm128(
    const __nv_bfloat16* __restrict__ xh, const __nv_bfloat16* __restrict__ xl,
    const __nv_bfloat16* __restrict__ ph, const __nv_bfloat16* __restrict__ pl,
    const __nv_bfloat16* __restrict__ wqh, const __nv_bfloat16* __restrict__ wql,
    const __nv_bfloat16* __restrict__ wpqh, const __nv_bfloat16* __restrict__ wpql,
    const __nv_bfloat16* __restrict__ wpkh, const __nv_bfloat16* __restrict__ wpkl,
    const float* __restrict__ qkv_b, const float* __restrict__ pq_b,
    const float* __restrict__ pk_b)
{
    extern __shared__ char smg[];
    const uint32_t sbase = smem_u32(smg);
    const int tid = threadIdx.x, lane = tid & 31, wid = tid >> 5;
    const int wm = wid >> 1;             // 0..3 -> m offset wm*32
    const int wn = wid & 1;              // 0..1 -> n offset wn*64
    const int bx = blockIdx.x;
    const int rowBase = blockIdx.y << 7; // *128

    const __nv_bfloat16 *Ah, *Al, *Wh, *Wl;
    const float* bias;
    float* C;
    int N, colBase;
    if (bx < 18)      { Ah = xh; Al = xl; Wh = wqh;  Wl = wql;  bias = qkv_b; C = g_QKV; N = 2304; colBase = bx * 128; }
    else if (bx < 24) { Ah = ph; Al = pl; Wh = wpqh; Wl = wpql; bias = pq_b;  C = g_PQ;  N = 768;  colBase = (bx - 18) * 128; }
    else              { Ah = ph; Al = pl; Wh = wpkh; Wl = wpkl; bias = pk_b;  C = g_PK;  N = 768;  colBase = (bx - 24) * 128; }

    const __nv_bfloat16* Ahg = Ah + (size_t)rowBase * GK;
    const __nv_bfloat16* Alg = Al + (size_t)rowBase * GK;
    const __nv_bfloat16* Whg = Wh + (size_t)colBase * GK;
    const __nv_bfloat16* Wlg = Wl + (size_t)colBase * GK;

    const uint32_t aoff = ((uint32_t)((wm * 32 + (lane & 15)) * GP2 + ((lane >> 4) * 8))) * 2;
    const uint32_t woff = ((uint32_t)((wn * 64 + ((lane >> 4) & 1) * 8 + (lane & 7)) * GP2
                                     + (((lane >> 3) & 1) * 8))) * 2;

    float c[2][8][4];
    #pragma unroll
    for (int i = 0; i < 2; i++)
        #pragma unroll
        for (int j = 0; j < 8; j++)
            #pragma unroll
            for (int k = 0; k < 4; k++) c[i][j][k] = 0.0f;

    auto load_chunk = [&](int ch, int buf) {
        const uint32_t base = sbase + (uint32_t)buf * GBUF2;
        const int k0 = ch * GBK2;
        #pragma unroll
        for (int it = 0; it < 2; it++) {         // 128 rows x 4 segs per plane
            const int idx = it * 256 + tid;      // 0..511
            const int row = idx >> 2, seg = (idx & 3) * 8;
            const uint32_t so = (uint32_t)(row * GP2 + seg) * 2;
            const size_t go = (size_t)row * GK + k0 + seg;
            cp16(base + OFF2_AH + so, Ahg + go);
            cp16(base + OFF2_AL + so, Alg + go);
            cp16(base + OFF2_WH + so, Whg + go);
            cp16(base + OFF2_WL + so, Wlg + go);
        }
    };

    load_chunk(0, 0);
    cp_commit();

    const int NCH = GK / GBK2;   // 24
    for (int ch = 0; ch < NCH; ch++) {
        if (ch + 1 < NCH) {
            load_chunk(ch + 1, (ch + 1) & 1);
            cp_commit();
            cp_wait<1>();
        } else {
            cp_wait<0>();
        }
        __syncthreads();

        const uint32_t base = sbase + (uint32_t)(ch & 1) * GBUF2;
        #pragma unroll
        for (int kk = 0; kk < GBK2; kk += 16) {
            uint32_t ah[2][4], al[2][4];
            #pragma unroll
            for (int fa = 0; fa < 2; fa++) {
                ldm_x4(ah[fa][0], ah[fa][1], ah[fa][2], ah[fa][3],
                       base + OFF2_AH + aoff + (uint32_t)(fa * 16 * GP2 + kk) * 2);
                ldm_x4(al[fa][0], al[fa][1], al[fa][2], al[fa][3],
                       base + OFF2_AL + aoff + (uint32_t)(fa * 16 * GP2 + kk) * 2);
            }
            #pragma unroll
            for (int fb = 0; fb < 4; fb++) {
                uint32_t b[4];
                ldm_x4(b[0], b[1], b[2], b[3],
                       base + OFF2_WH + woff + (uint32_t)(fb * 16 * GP2 + kk) * 2);
                #pragma unroll
                for (int fa = 0; fa < 2; fa++) {
                    mma16816(c[fa][fb * 2],     ah[fa], b[0], b[1]);
                    mma16816(c[fa][fb * 2 + 1], ah[fa], b[2], b[3]);
                    mma16816(c[fa][fb * 2],     al[fa], b[0], b[1]);
                    mma16816(c[fa][fb * 2 + 1], al[fa], b[2], b[3]);
                }
                ldm_x4(b[0], b[1], b[2], b[3],
                       base + OFF2_WL + woff + (uint32_t)(fb * 16 * GP2 + kk) * 2);
                #pragma unroll
                for (int fa = 0; fa < 2; fa++) {
                    mma16816(c[fa][fb * 2],     ah[fa], b[0], b[1]);
                    mma16816(c[fa][fb * 2 + 1], ah[fa], b[2], b[3]);
                }
            }
        }
        __syncthreads();
    }

    // ---- epilogue ----
    const int gq = lane >> 2, tq = lane & 3;
    #pragma unroll
    for (int fa = 0; fa < 2; fa++) {
        #pragma unroll
        for (int nf = 0; nf < 8; nf++) {
            const int row = rowBase + wm * 32 + fa * 16 + gq;
            const int col = colBase + wn * 64 + nf * 8 + tq * 2;
            const float b0 = bias[col], b1 = bias[col + 1];
            float2 v0 = make_float2(c[fa][nf][0] + b0, c[fa][nf][1] + b1);
            float2 v1 = make_float2(c[fa][nf][2] + b0, c[fa][nf][3] + b1);
            *(float2*)(C + (size_t)row * N + col) = v0;
            *(float2*)(C + (size_t)(row + 8) * N + col) = v1;
        }
    }
}

// ==================== launch 3: fused build (Qc/Kc) + V transpose ====================
#define BQK_BLOCKS ((BH * SEQ * 64) / 256)   // 24576
#define VT_BLOCKS  ((SEQ / 64) * BH)         // 1536

__global__ __launch_bounds__(256) void build_all()
{
    __shared__ float ts[64][65];
    const int bxall = blockIdx.x;
    const int tid = threadIdx.x;

    if (bxall < BQK_BLOCKS) {
        const int idx = bxall * 256 + tid;
        const int d  = idx & 63;
        const int l  = (idx >> 6) & (SEQ - 1);
        const int bh = idx >> 16;
        const int b  = bh / NHEAD, h = bh - b * NHEAD;
        const size_t row = (size_t)b * SEQ + l;
        const int c = h * HEAD_DIM + d;
        const float q  = g_QKV[row * 2304 + c];
        const float k  = g_QKV[row * 2304 + 768 + c];
        const float pq = g_PQ[row * 768 + c];
        const float pk = g_PK[row * 768 + c];
        const float k2 = k + pq;
        const __nv_bfloat16 qh = __float2bfloat16(q);
        const __nv_bfloat16 ql = __float2bfloat16(q - __bfloat162float(qh));
        const __nv_bfloat16 kh = __float2bfloat16(k2);
        const __nv_bfloat16 kl = __float2bfloat16(k2 - __bfloat162float(kh));
        const size_t base = ((size_t)bh * SEQ + l) * DQK;
        g_Qc[base + d]        = qh;
        g_Qc[base + 64 + d]   = qh;
        g_Qc[base + 128 + d]  = ql;
        g_Qc[base + 192 + d]  = __float2bfloat16(k * INV_SCALE);
        g_Kc[base + d]        = kh;
        g_Kc[base + 64 + d]   = kl;
        g_Kc[base + 128 + d]  = kh;
        g_Kc[base + 192 + d]  = __float2bfloat16(pk);
    } else {
        const int bx2 = bxall - BQK_BLOCKS;
        const int lt = bx2 & 15, bh = bx2 >> 4;
        const int b = bh / NHEAD, h = bh - b * NHEAD;
        {
            const int ll = tid >> 2, ds = (tid & 3) * 16;
            const float* src = g_QKV + ((size_t)(b * SEQ + lt * 64 + ll)) * 2304
                             + 1536 + h * HEAD_DIM + ds;
            #pragma unroll
            for (int i = 0; i < 4; i++) {
                float4 v = *(const float4*)(src + i * 4);
                ts[ll][ds + i * 4 + 0] = v.x;
                ts[ll][ds + i * 4 + 1] = v.y;
                ts[ll][ds + i * 4 + 2] = v.z;
                ts[ll][ds + i * 4 + 3] = v.w;
            }
        }
        __syncthreads();
        {
            const int d = tid >> 2, ls = (tid & 3) * 16;
            __half* dst = g_Vt + ((size_t)bh * HEAD_DIM + d) * SEQ + lt * 64 + ls;
            #pragma unroll
            for (int i = 0; i < 8; i++) {
                __half2 hv = __floats2half2_rn(ts[ls + 2 * i][d], ts[ls + 2 * i + 1][d]);
                *(__half2*)(dst + 2 * i) = hv;
            }
        }
    }
}

// ==================== launch 4: mma.sync flash attention (Q hoisted to regs) ====================
#define ABM 128
#define ABN 64
#define AQP 264
#define AVP 72
#define SK_OFF 0
#define SK_BYTES (ABN * AQP * 2)        // 33792
#define SV_OFF (SK_OFF + 2 * SK_BYTES)  // 67584
#define SV_BYTES (ABN * AVP * 2)        // 9216
#define ASMEM (SV_OFF + 2 * SV_BYTES)   // 86016

__global__ __launch_bounds__(256, 1) void attn_mma(float* __restrict__ out)
{
    extern __shared__ char smc[];
    const uint32_t sb = smem_u32(smc);
    const int tid = threadIdx.x, lane = tid & 31, w = tid >> 5;
    const int qb = blockIdx.x, bh = blockIdx.y;
    const int g = lane >> 2, t = lane & 3;

    const __nv_bfloat16* Qg = g_Qc + ((size_t)bh * SEQ + (size_t)qb * ABM) * DQK;
    const __nv_bfloat16* Kg = g_Kc + (size_t)bh * SEQ * DQK;
    const __half*        Vg = g_Vt + (size_t)bh * HEAD_DIM * SEQ;

    const uint32_t aoff = (uint32_t)((w * 16 + (lane & 15)) * AQP + (lane >> 4) * 8) * 2;
    const uint32_t kfrag = (uint32_t)((((lane >> 4) & 1) * 8 + (lane & 7)) * AQP
                                     + ((lane >> 3) & 1) * 8) * 2;
    const uint32_t vfrag = (uint32_t)((((lane >> 4) & 1) * 8 + (lane & 7)) * AVP
                                     + ((lane >> 3) & 1) * 8) * 2;

    // ---- stage Q (128 rows x 512B) through the two K buffers, hoist frags to regs ----
    #pragma unroll
    for (int it = 0; it < 16; it++) {
        const int idx = it * 256 + tid;
        const int r = idx >> 5, s = idx & 31;
        cp16(sb + SK_OFF + (uint32_t)(r * AQP + s * 8) * 2, Qg + (size_t)r * DQK + s * 8);
    }
    cp_commit();
    cp_wait<0>();
    __syncthreads();

    uint32_t qr[16][4];
    #pragma unroll
    for (int ks = 0; ks < DQK / 16; ks++)
        ldm_x4(qr[ks][0], qr[ks][1], qr[ks][2], qr[ks][3],
               sb + SK_OFF + aoff + ks * 32);
    __syncthreads();    // all warps done reading staged Q before K overwrites

    auto loadKV = [&](int kt, int buf) {
        const __nv_bfloat16* Kt = Kg + (size_t)kt * ABN * DQK;
        #pragma unroll
        for (int it = 0; it < 8; it++) {
            const int idx = it * 256 + tid;
            const int r = idx >> 5, s = idx & 31;
            cp16(sb + SK_OFF + buf * SK_BYTES + (uint32_t)(r * AQP + s * 8) * 2,
                 Kt + (size_t)r * DQK + s * 8);
        }
        #pragma unroll
        for (int it = 0; it < 2; it++) {
            const int idx = it * 256 + tid;
            const int r = idx >> 3, s = idx & 7;
            cp16(sb + SV_OFF + buf * SV_BYTES + (uint32_t)(r * AVP + s * 8) * 2,
                 Vg + (size_t)r * SEQ + kt * ABN + s * 8);
        }
    };
    loadKV(0, 0);
    cp_commit();

    float m0 = -1e30f, m1 = -1e30f, l0 = 0.0f, l1 = 0.0f;
    float o[8][4];
    #pragma unroll
    for (int f = 0; f < 8; f++)
        #pragma unroll
        for (int j = 0; j < 4; j++) o[f][j] = 0.0f;

    for (int kt = 0; kt < SEQ / ABN; kt++) {
        if (kt + 1 < SEQ / ABN) {
            loadKV(kt + 1, (kt + 1) & 1);
            cp_commit();
            cp_wait<1>();
        } else {
            cp_wait<0>();
        }
        __syncthreads();

        const uint32_t sK = sb + SK_OFF + (kt & 1) * SK_BYTES;
        const uint32_t sV = sb + SV_OFF + (kt & 1) * SV_BYTES;

        float c[8][4];
        #pragma unroll
        for (int f = 0; f < 8; f++)
            #pragma unroll
            for (int j = 0; j < 4; j++) c[f][j] = 0.0f;

        #pragma unroll
        for (int ks = 0; ks < DQK / 16; ks++) {
            #pragma unroll
            for (int fb = 0; fb < 4; fb++) {
                uint32_t b[4];
                ldm_x4(b[0], b[1], b[2], b[3],
                       sK + kfrag + (uint32_t)(fb * 16 * AQP) * 2 + ks * 32);
                mma16816(c[fb * 2],     qr[ks], b[0], b[1]);
                mma16816(c[fb * 2 + 1], qr[ks], b[2], b[3]);
            }
        }

        float mx0 = c[0][0], mx1 = c[0][2];
        #pragma unroll
        for (int f = 0; f < 8; f++) {
            mx0 = fmaxf(mx0, fmaxf(c[f][0], c[f][1]));
            mx1 = fmaxf(mx1, fmaxf(c[f][2], c[f][3]));
        }
        mx0 = fmaxf(mx0, __shfl_xor_sync(0xffffffffu, mx0, 1));
        mx0 = fmaxf(mx0, __shfl_xor_sync(0xffffffffu, mx0, 2));
        mx1 = fmaxf(mx1, __shfl_xor_sync(0xffffffffu, mx1, 1));
        mx1 = fmaxf(mx1, __shfl_xor_sync(0xffffffffu, mx1, 2));
        const float nm0 = fmaxf(m0, mx0), nm1 = fmaxf(m1, mx1);
        const float cr0 = __expf(m0 - nm0), cr1 = __expf(m1 - nm1);
        m0 = nm0; m1 = nm1;
        float rs0 = 0.0f, rs1 = 0.0f;
        #pragma unroll
        for (int f = 0; f < 8; f++) {
            c[f][0] = __expf(c[f][0] - nm0); rs0 += c[f][0];
            c[f][1] = __expf(c[f][1] - nm0); rs0 += c[f][1];
            c[f][2] = __expf(c[f][2] - nm1); rs1 += c[f][2];
            c[f][3] = __expf(c[f][3] - nm1); rs1 += c[f][3];
        }
        l0 = l0 * cr0 + rs0;
        l1 = l1 * cr1 + rs1;
        #pragma unroll
        for (int f = 0; f < 8; f++) {
            o[f][0] *= cr0; o[f][1] *= cr0;
            o[f][2] *= cr1; o[f][3] *= cr1;
        }

        #pragma unroll
        for (int ks = 0; ks < ABN / 16; ks++) {
            uint32_t pa[4];
            pa[0] = pack_h2(c[2 * ks][0],     c[2 * ks][1]);
            pa[1] = pack_h2(c[2 * ks][2],     c[2 * ks][3]);
            pa[2] = pack_h2(c[2 * ks + 1][0], c[2 * ks + 1][1]);
            pa[3] = pack_h2(c[2 * ks + 1][2], c[2 * ks + 1][3]);
            #pragma unroll
            for (int fb = 0; fb < 4; fb++) {
                uint32_t vb[4];
                ldm_x4(vb[0], vb[1], vb[2], vb[3],
                       sV + vfrag + (uint32_t)(fb * 16 * AVP) * 2 + ks * 32);
                mma16816h(o[fb * 2],     pa, vb[0], vb[1]);
                mma16816h(o[fb * 2 + 1], pa, vb[2], vb[3]);
            }
        }
        __syncthreads();
    }

    l0 += __shfl_xor_sync(0xffffffffu, l0, 1);
    l0 += __shfl_xor_sync(0xffffffffu, l0, 2);
    l1 += __shfl_xor_sync(0xffffffffu, l1, 1);
    l1 += __shfl_xor_sync(0xffffffffu, l1, 2);
    const float inv0 = 1.0f / l0, inv1 = 1.0f / l1;
    const int b_ = bh / NHEAD, h = bh - b_ * NHEAD;
    const int r0 = qb * ABM + w * 16 + g;
    float* p0 = out + (((size_t)(b_ * SEQ + r0)) * NHEAD + h) * HEAD_DIM;
    float* p1 = out + (((size_t)(b_ * SEQ + r0 + 8)) * NHEAD + h) * HEAD_DIM;
    #pragma unroll
    for (int f = 0; f < 8; f++) {
        const int col = f * 8 + t * 2;
        *(float2*)(p0 + col) = make_float2(o[f][0] * inv0, o[f][1] * inv0);
        *(float2*)(p1 + col) = make_float2(o[f][2] * inv1, o[f][3] * inv1);
    }
}

// ====================================================================
extern "C" void kernel_launch(void* const* d_in, const int* in_sizes, int n_in,
                              void* d_out, int out_size)
{
    const float* x     = (const float*)d_in[0];
    const float* pos   = (const float*)d_in[1];
    const float* qkv_w = (const float*)d_in[2];
    const float* qkv_b = (const float*)d_in[3];
    const float* pq_w  = (const float*)d_in[4];
    const float* pq_b  = (const float*)d_in[5];
    const float* pk_w  = (const float*)d_in[6];
    const float* pk_b  = (const float*)d_in[7];
    float* out = (float*)d_out;

    __nv_bfloat16 *xh, *xl, *ph, *pl, *wqh, *wql, *wpqh, *wpql, *wpkh, *wpkl;
    cudaGetSymbolAddress((void**)&xh,   g_xh);
    cudaGetSymbolAddress((void**)&xl,   g_xl);
    cudaGetSymbolAddress((void**)&ph,   g_ph);
    cudaGetSymbolAddress((void**)&pl,   g_pl);
    cudaGetSymbolAddress((void**)&wqh,  g_wqh);
    cudaGetSymbolAddress((void**)&wql,  g_wql);
    cudaGetSymbolAddress((void**)&wpqh, g_wpqh);
    cudaGetSymbolAddress((void**)&wpql, g_wpql);
    cudaGetSymbolAddress((void**)&wpkh, g_wpkh);
    cudaGetSymbolAddress((void**)&wpkl, g_wpkl);

    // 1) split into hi/lo bf16 planes (float4 vectorized)
    split_all<<<(SPLIT_V4 + 255) / 256, 256>>>(x, pos, qkv_w, pq_w, pk_w);

    // 2) all three projections in one launch (128x128 tiles, 2 CTAs/SM)
    cudaFuncSetAttribute(gemm128, cudaFuncAttributeMaxDynamicSharedMemorySize, GSM2);
    gemm128<<<dim3(30, 64), 256, GSM2>>>(xh, xl, ph, pl, wqh, wql,
                                         wpqh, wpql, wpkh, wpkl,
                                         qkv_b, pq_b, pk_b);

    // 3) build attention operands (Qc/Kc concat-split + V fp16 transpose)
    build_all<<<BQK_BLOCKS + VT_BLOCKS, 256>>>();

    // 4) flash attention (Q register-resident)
    cudaFuncSetAttribute(attn_mma, cudaFuncAttributeMaxDynamicSharedMemorySize, ASMEM);
    attn_mma<<<dim3(SEQ / ABM, BH), 256, ASMEM>>>(out);
}

// round 10
// speedup vs baseline: 3.6894x; 1.0118x over previous
#include <cuda_runtime.h>
#include <cuda_bf16.h>
#include <cuda_fp16.h>
#include <cstdint>
#include <cstddef>

#define D_MODEL 768
#define NHEAD   12
#define HEAD_DIM 64
#define BATCH   8
#define SEQ     1024
#define BH      (BATCH * NHEAD)     // 96
#define M_ROWS  (BATCH * SEQ)       // 8192
#define DQK     256                 // concat-split attention dim
#define INV_SCALE (1.0f / 48.0f)    // 1/sqrt(3*768)

// ---------------- scratch (static device allocation; no cudaMalloc) ----------------
__device__ float g_QKV [M_ROWS * 3 * D_MODEL];
__device__ float g_PQ  [M_ROWS * D_MODEL];
__device__ float g_PK  [M_ROWS * D_MODEL];

// attention operands
__device__ __nv_bfloat16 g_Qc[(size_t)BH * SEQ * DQK];   // [qh|qh|ql|k/48]
__device__ __nv_bfloat16 g_Kc[(size_t)BH * SEQ * DQK];   // [k'h|k'l|k'h|pk]
__device__ __half        g_Vt[(size_t)BH * HEAD_DIM * SEQ]; // transposed [bh][d][l]

// split-bf16 hi/lo planes for projections
__device__ __nv_bfloat16 g_xh [M_ROWS * D_MODEL];
__device__ __nv_bfloat16 g_xl [M_ROWS * D_MODEL];
__device__ __nv_bfloat16 g_ph [M_ROWS * D_MODEL];
__device__ __nv_bfloat16 g_pl [M_ROWS * D_MODEL];
__device__ __nv_bfloat16 g_wqh[3 * D_MODEL * D_MODEL];
__device__ __nv_bfloat16 g_wql[3 * D_MODEL * D_MODEL];
__device__ __nv_bfloat16 g_wpqh[D_MODEL * D_MODEL];
__device__ __nv_bfloat16 g_wpql[D_MODEL * D_MODEL];
__device__ __nv_bfloat16 g_wpkh[D_MODEL * D_MODEL];
__device__ __nv_bfloat16 g_wpkl[D_MODEL * D_MODEL];

// ==================== helpers ====================
__device__ __forceinline__ uint32_t smem_u32(const void* p) {
    uint32_t a;
    asm("{ .reg .u64 t; cvta.to.shared.u64 t, %1; cvt.u32.u64 %0, t; }" : "=r"(a) : "l"(p));
    return a;
}
__device__ __forceinline__ void cp16(uint32_t dst, const void* src) {
    asm volatile("cp.async.cg.shared.global [%0], [%1], 16;" :: "r"(dst), "l"(src));
}
__device__ __forceinline__ void cp_commit() {
    asm volatile("cp.async.commit_group;" ::: "memory");
}
template <int N>
__device__ __forceinline__ void cp_wait() {
    asm volatile("cp.async.wait_group %0;" :: "n"(N) : "memory");
}
__device__ __forceinline__ void ldm_x4(uint32_t& r0, uint32_t& r1, uint32_t& r2,
                                       uint32_t& r3, uint32_t addr) {
    asm volatile("ldmatrix.sync.aligned.m8n8.x4.shared.b16 {%0,%1,%2,%3}, [%4];"
                 : "=r"(r0), "=r"(r1), "=r"(r2), "=r"(r3) : "r"(addr));
}
__device__ __forceinline__ void mma16816(float* c, const uint32_t* a,
                                         uint32_t b0, uint32_t b1) {
    asm volatile(
        "mma.sync.aligned.m16n8k16.row.col.f32.bf16.bf16.f32 "
        "{%0,%1,%2,%3}, {%4,%5,%6,%7}, {%8,%9}, {%0,%1,%2,%3};"
        : "+f"(c[0]), "+f"(c[1]), "+f"(c[2]), "+f"(c[3])
        : "r"(a[0]), "r"(a[1]), "r"(a[2]), "r"(a[3]), "r"(b0), "r"(b1));
}
__device__ __forceinline__ void mma16816h(float* c, const uint32_t* a,
                                          uint32_t b0, uint32_t b1) {
    asm volatile(
        "mma.sync.aligned.m16n8k16.row.col.f32.f16.f16.f32 "
        "{%0,%1,%2,%3}, {%4,%5,%6,%7}, {%8,%9}, {%0,%1,%2,%3};"
        : "+f"(c[0]), "+f"(c[1]), "+f"(c[2]), "+f"(c[3])
        : "r"(a[0]), "r"(a[1]), "r"(a[2]), "r"(a[3]), "r"(b0), "r"(b1));
}

// ==================== launch 1: fused split fp32 -> (hi, lo) bf16 planes ====================
#define NXE (M_ROWS * D_MODEL)          // 6291456
#define NWQE (3 * D_MODEL * D_MODEL)    // 1769472
#define NWE (D_MODEL * D_MODEL)         // 589824
#define SPLIT_TOTAL (2 * NXE + NWQE + 2 * NWE)
#define SPLIT_V4 (SPLIT_TOTAL / 4)

__global__ __launch_bounds__(256) void split_all(
    const float* __restrict__ x, const float* __restrict__ pos,
    const float* __restrict__ wq, const float* __restrict__ wpq,
    const float* __restrict__ wpk)
{
    const int i4 = blockIdx.x * 256 + threadIdx.x;
    if (i4 >= SPLIT_V4) return;
    const int i = i4 * 4;
    const float* src;
    __nv_bfloat16 *hi, *lo;
    int j;
    if (i < NXE)                       { j = i;                        src = x;   hi = g_xh;   lo = g_xl;   }
    else if (i < 2 * NXE)              { j = i - NXE;                  src = pos; hi = g_ph;   lo = g_pl;   }
    else if (i < 2 * NXE + NWQE)       { j = i - 2 * NXE;              src = wq;  hi = g_wqh;  lo = g_wql;  }
    else if (i < 2 * NXE + NWQE + NWE) { j = i - 2 * NXE - NWQE;       src = wpq; hi = g_wpqh; lo = g_wpql; }
    else                               { j = i - 2 * NXE - NWQE - NWE; src = wpk; hi = g_wpkh; lo = g_wpkl; }

    const float4 v = *(const float4*)(src + j);
    union { __nv_bfloat162 h2[2]; uint2 u; } H, L;
    __nv_bfloat16 h0 = __float2bfloat16(v.x), h1 = __float2bfloat16(v.y);
    __nv_bfloat16 h2 = __float2bfloat16(v.z), h3 = __float2bfloat16(v.w);
    H.h2[0] = __nv_bfloat162(h0, h1);
    H.h2[1] = __nv_bfloat162(h2, h3);
    L.h2[0] = __nv_bfloat162(__float2bfloat16(v.x - __bfloat162float(h0)),
                             __float2bfloat16(v.y - __bfloat162float(h1)));
    L.h2[1] = __nv_bfloat162(__float2bfloat16(v.z - __bfloat162float(h2)),
                             __float2bfloat16(v.w - __bfloat162float(h3)));
    *(uint2*)(hi + j) = H.u;
    *(uint2*)(lo + j) = L.u;
}

// ==================== launch 2: split-bf16 GEMM, 128x128 tiles, 2 CTAs/SM ====================
// qkv/pq tiles: C = Ah*Wh^T + Ah*Wl^T + Al*Wh^T + bias (3-term).
// pk tiles: single-plane (score contribution is /48 -> bf16 error negligible).
#define GK    768
#define GBK2  32
#define GP2   40                          // pitch (elems): 80B rows, conflict-free LDSM
#define PL2B  (128 * GP2 * 2)             // 10240 bytes per plane
#define OFF2_AH 0
#define OFF2_AL PL2B
#define OFF2_WH (2 * PL2B)
#define OFF2_WL (3 * PL2B)
#define GBUF2  (4 * PL2B)                 // 40960 per buffer
#define GSM2   (2 * GBUF2)                // 81920 total -> 2 CTAs/SM

__global__ __launch_bounds__(256, 2) void gemm128(
    const __nv_bfloat16* __restrict__ xh, const __nv_bfloat16* __restrict__ xl,
    const __nv_bfloat16* __restrict__ ph, const __nv_bfloat16* __restrict__ pl,
    const __nv_bfloat16* __restrict__ wqh, const __nv_bfloat16* __restrict__ wql,
    const __nv_bfloat16* __restrict__ wpqh, const __nv_bfloat16* __restrict__ wpql,
    const __nv_bfloat16* __restrict__ wpkh, const __nv_bfloat16* __restrict__ wpkl,
    const float* __restrict__ qkv_b, const float* __restrict__ pq_b,
    const float* __restrict__ pk_b)
{
    extern __shared__ char smg[];
    const uint32_t sbase = smem_u32(smg);
    const int tid = threadIdx.x, lane = tid & 31, wid = tid >> 5;
    const int wm = wid >> 1;             // 0..3 -> m offset wm*32
    const int wn = wid & 1;              // 0..1 -> n offset wn*64
    const int bx = blockIdx.x;
    const int rowBase = blockIdx.y << 7; // *128

    const __nv_bfloat16 *Ah, *Al, *Wh, *Wl;
    const float* bias;
    float* C;
    int N, colBase;
    bool three = true;
    if (bx < 18)      { Ah = xh; Al = xl; Wh = wqh;  Wl = wql;  bias = qkv_b; C = g_QKV; N = 2304; colBase = bx * 128; }
    else if (bx < 24) { Ah = ph; Al = pl; Wh = wpqh; Wl = wpql; bias = pq_b;  C = g_PQ;  N = 768;  colBase = (bx - 18) * 128; }
    else              { Ah = ph; Al = pl; Wh = wpkh; Wl = wpkl; bias = pk_b;  C = g_PK;  N = 768;  colBase = (bx - 24) * 128; three = false; }

    const __nv_bfloat16* Ahg = Ah + (size_t)rowBase * GK;
    const __nv_bfloat16* Alg = Al + (size_t)rowBase * GK;
    const __nv_bfloat16* Whg = Wh + (size_t)colBase * GK;
    const __nv_bfloat16* Wlg = Wl + (size_t)colBase * GK;

    const uint32_t aoff = ((uint32_t)((wm * 32 + (lane & 15)) * GP2 + ((lane >> 4) * 8))) * 2;
    const uint32_t woff = ((uint32_t)((wn * 64 + ((lane >> 4) & 1) * 8 + (lane & 7)) * GP2
                                     + (((lane >> 3) & 1) * 8))) * 2;

    float c[2][8][4];
    #pragma unroll
    for (int i = 0; i < 2; i++)
        #pragma unroll
        for (int j = 0; j < 8; j++)
            #pragma unroll
            for (int k = 0; k < 4; k++) c[i][j][k] = 0.0f;

    auto load_chunk = [&](int ch, int buf) {
        const uint32_t base = sbase + (uint32_t)buf * GBUF2;
        const int k0 = ch * GBK2;
        #pragma unroll
        for (int it = 0; it < 2; it++) {         // 128 rows x 4 segs per plane
            const int idx = it * 256 + tid;      // 0..511
            const int row = idx >> 2, seg = (idx & 3) * 8;
            const uint32_t so = (uint32_t)(row * GP2 + seg) * 2;
            const size_t go = (size_t)row * GK + k0 + seg;
            cp16(base + OFF2_AH + so, Ahg + go);
            cp16(base + OFF2_WH + so, Whg + go);
            if (three) {
                cp16(base + OFF2_AL + so, Alg + go);
                cp16(base + OFF2_WL + so, Wlg + go);
            }
        }
    };

    load_chunk(0, 0);
    cp_commit();

    const int NCH = GK / GBK2;   // 24
    for (int ch = 0; ch < NCH; ch++) {
        if (ch + 1 < NCH) {
            load_chunk(ch + 1, (ch + 1) & 1);
            cp_commit();
            cp_wait<1>();
        } else {
            cp_wait<0>();
        }
        __syncthreads();

        const uint32_t base = sbase + (uint32_t)(ch & 1) * GBUF2;
        #pragma unroll
        for (int kk = 0; kk < GBK2; kk += 16) {
            uint32_t ah[2][4], al[2][4];
            #pragma unroll
            for (int fa = 0; fa < 2; fa++) {
                ldm_x4(ah[fa][0], ah[fa][1], ah[fa][2], ah[fa][3],
                       base + OFF2_AH + aoff + (uint32_t)(fa * 16 * GP2 + kk) * 2);
                if (three)
                    ldm_x4(al[fa][0], al[fa][1], al[fa][2], al[fa][3],
                           base + OFF2_AL + aoff + (uint32_t)(fa * 16 * GP2 + kk) * 2);
            }
            #pragma unroll
            for (int fb = 0; fb < 4; fb++) {
                uint32_t b[4];
                ldm_x4(b[0], b[1], b[2], b[3],
                       base + OFF2_WH + woff + (uint32_t)(fb * 16 * GP2 + kk) * 2);
                #pragma unroll
                for (int fa = 0; fa < 2; fa++) {
                    mma16816(c[fa][fb * 2],     ah[fa], b[0], b[1]);
                    mma16816(c[fa][fb * 2 + 1], ah[fa], b[2], b[3]);
                    if (three) {
                        mma16816(c[fa][fb * 2],     al[fa], b[0], b[1]);
                        mma16816(c[fa][fb * 2 + 1], al[fa], b[2], b[3]);
                    }
                }
                if (three) {
                    ldm_x4(b[0], b[1], b[2], b[3],
                           base + OFF2_WL + woff + (uint32_t)(fb * 16 * GP2 + kk) * 2);
                    #pragma unroll
                    for (int fa = 0; fa < 2; fa++) {
                        mma16816(c[fa][fb * 2],     ah[fa], b[0], b[1]);
                        mma16816(c[fa][fb * 2 + 1], ah[fa], b[2], b[3]);
                    }
                }
            }
        }
        __syncthreads();
    }

    // ---- epilogue ----
    const int gq = lane >> 2, tq = lane & 3;
    #pragma unroll
    for (int fa = 0; fa < 2; fa++) {
        #pragma unroll
        for (int nf = 0; nf < 8; nf++) {
            const int row = rowBase + wm * 32 + fa * 16 + gq;
            const int col = colBase + wn * 64 + nf * 8 + tq * 2;
            const float b0 = bias[col], b1 = bias[col + 1];
            float2 v0 = make_float2(c[fa][nf][0] + b0, c[fa][nf][1] + b1);
            float2 v1 = make_float2(c[fa][nf][2] + b0, c[fa][nf][3] + b1);
            *(float2*)(C + (size_t)row * N + col) = v0;
            *(float2*)(C + (size_t)(row + 8) * N + col) = v1;
        }
    }
}

// ==================== launch 3: fused build (Qc/Kc) + V transpose ====================
#define BQK_BLOCKS ((BH * SEQ * 64) / 256)   // 24576
#define VT_BLOCKS  ((SEQ / 64) * BH)         // 1536

__global__ __launch_bounds__(256) void build_all()
{
    __shared__ float ts[64][65];
    const int bxall = blockIdx.x;
    const int tid = threadIdx.x;

    if (bxall < BQK_BLOCKS) {
        const int idx = bxall * 256 + tid;
        const int d  = idx & 63;
        const int l  = (idx >> 6) & (SEQ - 1);
        const int bh = idx >> 16;
        const int b  = bh / NHEAD, h = bh - b * NHEAD;
        const size_t row = (size_t)b * SEQ + l;
        const int c = h * HEAD_DIM + d;
        const float q  = g_QKV[row * 2304 + c];
        const float k  = g_QKV[row * 2304 + 768 + c];
        const float pq = g_PQ[row * 768 + c];
        const float pk = g_PK[row * 768 + c];
        const float k2 = k + pq;
        const __nv_bfloat16 qh = __float2bfloat16(q);
        const __nv_bfloat16 ql = __float2bfloat16(q - __bfloat162float(qh));
        const __nv_bfloat16 kh = __float2bfloat16(k2);
        const __nv_bfloat16 kl = __float2bfloat16(k2 - __bfloat162float(kh));
        const size_t base = ((size_t)bh * SEQ + l) * DQK;
        g_Qc[base + d]        = qh;
        g_Qc[base + 64 + d]   = qh;
        g_Qc[base + 128 + d]  = ql;
        g_Qc[base + 192 + d]  = __float2bfloat16(k * INV_SCALE);
        g_Kc[base + d]        = kh;
        g_Kc[base + 64 + d]   = kl;
        g_Kc[base + 128 + d]  = kh;
        g_Kc[base + 192 + d]  = __float2bfloat16(pk);
    } else {
        const int bx2 = bxall - BQK_BLOCKS;
        const int lt = bx2 & 15, bh = bx2 >> 4;
        const int b = bh / NHEAD, h = bh - b * NHEAD;
        {
            const int ll = tid >> 2, ds = (tid & 3) * 16;
            const float* src = g_QKV + ((size_t)(b * SEQ + lt * 64 + ll)) * 2304
                             + 1536 + h * HEAD_DIM + ds;
            #pragma unroll
            for (int i = 0; i < 4; i++) {
                float4 v = *(const float4*)(src + i * 4);
                ts[ll][ds + i * 4 + 0] = v.x;
                ts[ll][ds + i * 4 + 1] = v.y;
                ts[ll][ds + i * 4 + 2] = v.z;
                ts[ll][ds + i * 4 + 3] = v.w;
            }
        }
        __syncthreads();
        {
            const int d = tid >> 2, ls = (tid & 3) * 16;
            __half* dst = g_Vt + ((size_t)bh * HEAD_DIM + d) * SEQ + lt * 64 + ls;
            #pragma unroll
            for (int i = 0; i < 8; i++) {
                __half2 hv = __floats2half2_rn(ts[ls + 2 * i][d], ts[ls + 2 * i + 1][d]);
                *(__half2*)(dst + 2 * i) = hv;
            }
        }
    }
}

// ==================== launch 4: mma.sync flash attention (Q regs + h2exp softmax) ====================
#define ABM 128
#define ABN 64
#define AQP 264
#define AVP 72
#define SK_OFF 0
#define SK_BYTES (ABN * AQP * 2)        // 33792
#define SV_OFF (SK_OFF + 2 * SK_BYTES)  // 67584
#define SV_BYTES (ABN * AVP * 2)        // 9216
#define ASMEM (SV_OFF + 2 * SV_BYTES)   // 86016

__global__ __launch_bounds__(256, 1) void attn_mma(float* __restrict__ out)
{
    extern __shared__ char smc[];
    const uint32_t sb = smem_u32(smc);
    const int tid = threadIdx.x, lane = tid & 31, w = tid >> 5;
    const int qb = blockIdx.x, bh = blockIdx.y;
    const int g = lane >> 2, t = lane & 3;

    const __nv_bfloat16* Qg = g_Qc + ((size_t)bh * SEQ + (size_t)qb * ABM) * DQK;
    const __nv_bfloat16* Kg = g_Kc + (size_t)bh * SEQ * DQK;
    const __half*        Vg = g_Vt + (size_t)bh * HEAD_DIM * SEQ;

    const uint32_t aoff = (uint32_t)((w * 16 + (lane & 15)) * AQP + (lane >> 4) * 8) * 2;
    const uint32_t kfrag = (uint32_t)((((lane >> 4) & 1) * 8 + (lane & 7)) * AQP
                                     + ((lane >> 3) & 1) * 8) * 2;
    const uint32_t vfrag = (uint32_t)((((lane >> 4) & 1) * 8 + (lane & 7)) * AVP
                                     + ((lane >> 3) & 1) * 8) * 2;

    // ---- stage Q (128 rows x 512B) through the two K buffers, hoist frags to regs ----
    #pragma unroll
    for (int it = 0; it < 16; it++) {
        const int idx = it * 256 + tid;
        const int r = idx >> 5, s = idx & 31;
        cp16(sb + SK_OFF + (uint32_t)(r * AQP + s * 8) * 2, Qg + (size_t)r * DQK + s * 8);
    }
    cp_commit();
    cp_wait<0>();
    __syncthreads();

    uint32_t qr[16][4];
    #pragma unroll
    for (int ks = 0; ks < DQK / 16; ks++)
        ldm_x4(qr[ks][0], qr[ks][1], qr[ks][2], qr[ks][3],
               sb + SK_OFF + aoff + ks * 32);
    __syncthreads();    // all warps done reading staged Q before K overwrites

    auto loadKV = [&](int kt, int buf) {
        const __nv_bfloat16* Kt = Kg + (size_t)kt * ABN * DQK;
        #pragma unroll
        for (int it = 0; it < 8; it++) {
            const int idx = it * 256 + tid;
            const int r = idx >> 5, s = idx & 31;
            cp16(sb + SK_OFF + buf * SK_BYTES + (uint32_t)(r * AQP + s * 8) * 2,
                 Kt + (size_t)r * DQK + s * 8);
        }
        #pragma unroll
        for (int it = 0; it < 2; it++) {
            const int idx = it * 256 + tid;
            const int r = idx >> 3, s = idx & 7;
            cp16(sb + SV_OFF + buf * SV_BYTES + (uint32_t)(r * AVP + s * 8) * 2,
                 Vg + (size_t)r * SEQ + kt * ABN + s * 8);
        }
    };
    loadKV(0, 0);
    cp_commit();

    float m0 = -1e30f, m1 = -1e30f, l0 = 0.0f, l1 = 0.0f;
    float o[8][4];
    #pragma unroll
    for (int f = 0; f < 8; f++)
        #pragma unroll
        for (int j = 0; j < 4; j++) o[f][j] = 0.0f;

    for (int kt = 0; kt < SEQ / ABN; kt++) {
        if (kt + 1 < SEQ / ABN) {
            loadKV(kt + 1, (kt + 1) & 1);
            cp_commit();
            cp_wait<1>();
        } else {
            cp_wait<0>();
        }
        __syncthreads();

        const uint32_t sK = sb + SK_OFF + (kt & 1) * SK_BYTES;
        const uint32_t sV = sb + SV_OFF + (kt & 1) * SV_BYTES;

        // ---- S = Q'' @ K''^T ----
        float c[8][4];
        #pragma unroll
        for (int f = 0; f < 8; f++)
            #pragma unroll
            for (int j = 0; j < 4; j++) c[f][j] = 0.0f;

        #pragma unroll
        for (int ks = 0; ks < DQK / 16; ks++) {
            #pragma unroll
            for (int fb = 0; fb < 4; fb++) {
                uint32_t b[4];
                ldm_x4(b[0], b[1], b[2], b[3],
                       sK + kfrag + (uint32_t)(fb * 16 * AQP) * 2 + ks * 32);
                mma16816(c[fb * 2],     qr[ks], b[0], b[1]);
                mma16816(c[fb * 2 + 1], qr[ks], b[2], b[3]);
            }
        }

        // ---- online softmax: max + correction in fp32, exp via fp16x2 MUFU ----
        float mx0 = c[0][0], mx1 = c[0][2];
        #pragma unroll
        for (int f = 0; f < 8; f++) {
            mx0 = fmaxf(mx0, fmaxf(c[f][0], c[f][1]));
            mx1 = fmaxf(mx1, fmaxf(c[f][2], c[f][3]));
        }
        mx0 = fmaxf(mx0, __shfl_xor_sync(0xffffffffu, mx0, 1));
        mx0 = fmaxf(mx0, __shfl_xor_sync(0xffffffffu, mx0, 2));
        mx1 = fmaxf(mx1, __shfl_xor_sync(0xffffffffu, mx1, 1));
        mx1 = fmaxf(mx1, __shfl_xor_sync(0xffffffffu, mx1, 2));
        const float nm0 = fmaxf(m0, mx0), nm1 = fmaxf(m1, mx1);
        const float cr0 = __expf(m0 - nm0), cr1 = __expf(m1 - nm1);
        m0 = nm0; m1 = nm1;
        #pragma unroll
        for (int f = 0; f < 8; f++) {
            o[f][0] *= cr0; o[f][1] *= cr0;
            o[f][2] *= cr1; o[f][3] *= cr1;
        }

        // ---- P = exp(S-m) directly in fp16 A-frag layout; O += P @ V ----
        float rs0 = 0.0f, rs1 = 0.0f;
        #pragma unroll
        for (int ks = 0; ks < ABN / 16; ks++) {
            __half2 e0 = h2exp(__floats2half2_rn(c[2 * ks][0] - nm0,     c[2 * ks][1] - nm0));
            __half2 e1 = h2exp(__floats2half2_rn(c[2 * ks][2] - nm1,     c[2 * ks][3] - nm1));
            __half2 e2 = h2exp(__floats2half2_rn(c[2 * ks + 1][0] - nm0, c[2 * ks + 1][1] - nm0));
            __half2 e3 = h2exp(__floats2half2_rn(c[2 * ks + 1][2] - nm1, c[2 * ks + 1][3] - nm1));
            float2 f0 = __half22float2(e0), f1 = __half22float2(e1);
            float2 f2 = __half22float2(e2), f3 = __half22float2(e3);
            rs0 += f0.x + f0.y + f2.x + f2.y;
            rs1 += f1.x + f1.y + f3.x + f3.y;
            uint32_t pa[4];
            pa[0] = *(uint32_t*)&e0;
            pa[1] = *(uint32_t*)&e1;
            pa[2] = *(uint32_t*)&e2;
            pa[3] = *(uint32_t*)&e3;
            #pragma unroll
            for (int fb = 0; fb < 4; fb++) {
                uint32_t vb[4];
                ldm_x4(vb[0], vb[1], vb[2], vb[3],
                       sV + vfrag + (uint32_t)(fb * 16 * AVP) * 2 + ks * 32);
                mma16816h(o[fb * 2],     pa, vb[0], vb[1]);
                mma16816h(o[fb * 2 + 1], pa, vb[2], vb[3]);
            }
        }
        l0 = l0 * cr0 + rs0;
        l1 = l1 * cr1 + rs1;
        __syncthreads();
    }

    l0 += __shfl_xor_sync(0xffffffffu, l0, 1);
    l0 += __shfl_xor_sync(0xffffffffu, l0, 2);
    l1 += __shfl_xor_sync(0xffffffffu, l1, 1);
    l1 += __shfl_xor_sync(0xffffffffu, l1, 2);
    const float inv0 = 1.0f / l0, inv1 = 1.0f / l1;
    const int b_ = bh / NHEAD, h = bh - b_ * NHEAD;
    const int r0 = qb * ABM + w * 16 + g;
    float* p0 = out + (((size_t)(b_ * SEQ + r0)) * NHEAD + h) * HEAD_DIM;
    float* p1 = out + (((size_t)(b_ * SEQ + r0 + 8)) * NHEAD + h) * HEAD_DIM;
    #pragma unroll
    for (int f = 0; f < 8; f++) {
        const int col = f * 8 + t * 2;
        *(float2*)(p0 + col) = make_float2(o[f][0] * inv0, o[f][1] * inv0);
        *(float2*)(p1 + col) = make_float2(o[f][2] * inv1, o[f][3] * inv1);
    }
}

// ====================================================================
extern "C" void kernel_launch(void* const* d_in, const int* in_sizes, int n_in,
                              void* d_out, int out_size)
{
    const float* x     = (const float*)d_in[0];
    const float* pos   = (const float*)d_in[1];
    const float* qkv_w = (const float*)d_in[2];
    const float* qkv_b = (const float*)d_in[3];
    const float* pq_w  = (const float*)d_in[4];
    const float* pq_b  = (const float*)d_in[5];
    const float* pk_w  = (const float*)d_in[6];
    const float* pk_b  = (const float*)d_in[7];
    float* out = (float*)d_out;

    __nv_bfloat16 *xh, *xl, *ph, *pl, *wqh, *wql, *wpqh, *wpql, *wpkh, *wpkl;
    cudaGetSymbolAddress((void**)&xh,   g_xh);
    cudaGetSymbolAddress((void**)&xl,   g_xl);
    cudaGetSymbolAddress((void**)&ph,   g_ph);
    cudaGetSymbolAddress((void**)&pl,   g_pl);
    cudaGetSymbolAddress((void**)&wqh,  g_wqh);
    cudaGetSymbolAddress((void**)&wql,  g_wql);
    cudaGetSymbolAddress((void**)&wpqh, g_wpqh);
    cudaGetSymbolAddress((void**)&wpql, g_wpql);
    cudaGetSymbolAddress((void**)&wpkh, g_wpkh);
    cudaGetSymbolAddress((void**)&wpkl, g_wpkl);

    // 1) split into hi/lo bf16 planes (float4 vectorized)
    split_all<<<(SPLIT_V4 + 255) / 256, 256>>>(x, pos, qkv_w, pq_w, pk_w);

    // 2) all three projections in one launch (pk single-plane)
    cudaFuncSetAttribute(gemm128, cudaFuncAttributeMaxDynamicSharedMemorySize, GSM2);
    gemm128<<<dim3(30, 64), 256, GSM2>>>(xh, xl, ph, pl, wqh, wql,
                                         wpqh, wpql, wpkh, wpkl,
                                         qkv_b, pq_b, pk_b);

    // 3) build attention operands (Qc/Kc concat-split + V fp16 transpose)
    build_all<<<BQK_BLOCKS + VT_BLOCKS, 256>>>();

    // 4) flash attention (Q register-resident, fp16x2 softmax)
    cudaFuncSetAttribute(attn_mma, cudaFuncAttributeMaxDynamicSharedMemorySize, ASMEM);
    attn_mma<<<dim3(SEQ / ABM, BH), 256, ASMEM>>>(out);
}

// round 11
// speedup vs baseline: 3.8491x; 1.0433x over previous
#include <cuda_runtime.h>
#include <cuda_bf16.h>
#include <cuda_fp16.h>
#include <cstdint>
#include <cstddef>

#define D_MODEL 768
#define NHEAD   12
#define HEAD_DIM 64
#define BATCH   8
#define SEQ     1024
#define BH      (BATCH * NHEAD)     // 96
#define M_ROWS  (BATCH * SEQ)       // 8192
#define DQK     256                 // concat-split attention dim
#define INV_SCALE (1.0f / 48.0f)    // 1/sqrt(3*768)

// ---------------- scratch (static device allocation; no cudaMalloc) ----------------
__device__ float g_QKV [M_ROWS * 3 * D_MODEL];
__device__ float g_PQ  [M_ROWS * D_MODEL];
__device__ float g_PK  [M_ROWS * D_MODEL];

// attention operands
__device__ __nv_bfloat16 g_Qc[(size_t)BH * SEQ * DQK];   // [qh|qh|ql|k/48]
__device__ __nv_bfloat16 g_Kc[(size_t)BH * SEQ * DQK];   // [k'h|k'l|k'h|pk]
__device__ __half        g_Vt[(size_t)BH * HEAD_DIM * SEQ]; // transposed [bh][d][l]

// split-bf16 hi/lo planes for projections
__device__ __nv_bfloat16 g_xh [M_ROWS * D_MODEL];
__device__ __nv_bfloat16 g_xl [M_ROWS * D_MODEL];
__device__ __nv_bfloat16 g_ph [M_ROWS * D_MODEL];
__device__ __nv_bfloat16 g_pl [M_ROWS * D_MODEL];
__device__ __nv_bfloat16 g_wqh[3 * D_MODEL * D_MODEL];
__device__ __nv_bfloat16 g_wql[3 * D_MODEL * D_MODEL];
__device__ __nv_bfloat16 g_wpqh[D_MODEL * D_MODEL];
__device__ __nv_bfloat16 g_wpql[D_MODEL * D_MODEL];
__device__ __nv_bfloat16 g_wpkh[D_MODEL * D_MODEL];
__device__ __nv_bfloat16 g_wpkl[D_MODEL * D_MODEL];

// ==================== helpers ====================
__device__ __forceinline__ uint32_t smem_u32(const void* p) {
    uint32_t a;
    asm("{ .reg .u64 t; cvta.to.shared.u64 t, %1; cvt.u32.u64 %0, t; }" : "=r"(a) : "l"(p));
    return a;
}
__device__ __forceinline__ void cp16(uint32_t dst, const void* src) {
    asm volatile("cp.async.cg.shared.global [%0], [%1], 16;" :: "r"(dst), "l"(src));
}
__device__ __forceinline__ void cp_commit() {
    asm volatile("cp.async.commit_group;" ::: "memory");
}
template <int N>
__device__ __forceinline__ void cp_wait() {
    asm volatile("cp.async.wait_group %0;" :: "n"(N) : "memory");
}
__device__ __forceinline__ void ldm_x4(uint32_t& r0, uint32_t& r1, uint32_t& r2,
                                       uint32_t& r3, uint32_t addr) {
    asm volatile("ldmatrix.sync.aligned.m8n8.x4.shared.b16 {%0,%1,%2,%3}, [%4];"
                 : "=r"(r0), "=r"(r1), "=r"(r2), "=r"(r3) : "r"(addr));
}
__device__ __forceinline__ void mma16816(float* c, const uint32_t* a,
                                         uint32_t b0, uint32_t b1) {
    asm volatile(
        "mma.sync.aligned.m16n8k16.row.col.f32.bf16.bf16.f32 "
        "{%0,%1,%2,%3}, {%4,%5,%6,%7}, {%8,%9}, {%0,%1,%2,%3};"
        : "+f"(c[0]), "+f"(c[1]), "+f"(c[2]), "+f"(c[3])
        : "r"(a[0]), "r"(a[1]), "r"(a[2]), "r"(a[3]), "r"(b0), "r"(b1));
}
__device__ __forceinline__ void mma16816h(float* c, const uint32_t* a,
                                          uint32_t b0, uint32_t b1) {
    asm volatile(
        "mma.sync.aligned.m16n8k16.row.col.f32.f16.f16.f32 "
        "{%0,%1,%2,%3}, {%4,%5,%6,%7}, {%8,%9}, {%0,%1,%2,%3};"
        : "+f"(c[0]), "+f"(c[1]), "+f"(c[2]), "+f"(c[3])
        : "r"(a[0]), "r"(a[1]), "r"(a[2]), "r"(a[3]), "r"(b0), "r"(b1));
}
__device__ __forceinline__ uint32_t pack_h2(float lo, float hi) {
    __half2 h = __floats2half2_rn(lo, hi);
    return *(uint32_t*)&h;
}

// ==================== launch 1: fused split fp32 -> (hi, lo) bf16 planes ====================
#define NXE (M_ROWS * D_MODEL)          // 6291456
#define NWQE (3 * D_MODEL * D_MODEL)    // 1769472
#define NWE (D_MODEL * D_MODEL)         // 589824
#define SPLIT_TOTAL (2 * NXE + NWQE + 2 * NWE)
#define SPLIT_V4 (SPLIT_TOTAL / 4)

__global__ __launch_bounds__(256) void split_all(
    const float* __restrict__ x, const float* __restrict__ pos,
    const float* __restrict__ wq, const float* __restrict__ wpq,
    const float* __restrict__ wpk)
{
    const int i4 = blockIdx.x * 256 + threadIdx.x;
    if (i4 >= SPLIT_V4) return;
    const int i = i4 * 4;
    const float* src;
    __nv_bfloat16 *hi, *lo;
    int j;
    if (i < NXE)                       { j = i;                        src = x;   hi = g_xh;   lo = g_xl;   }
    else if (i < 2 * NXE)              { j = i - NXE;                  src = pos; hi = g_ph;   lo = g_pl;   }
    else if (i < 2 * NXE + NWQE)       { j = i - 2 * NXE;              src = wq;  hi = g_wqh;  lo = g_wql;  }
    else if (i < 2 * NXE + NWQE + NWE) { j = i - 2 * NXE - NWQE;       src = wpq; hi = g_wpqh; lo = g_wpql; }
    else                               { j = i - 2 * NXE - NWQE - NWE; src = wpk; hi = g_wpkh; lo = g_wpkl; }

    const float4 v = *(const float4*)(src + j);
    union { __nv_bfloat162 h2[2]; uint2 u; } H, L;
    __nv_bfloat16 h0 = __float2bfloat16(v.x), h1 = __float2bfloat16(v.y);
    __nv_bfloat16 h2 = __float2bfloat16(v.z), h3 = __float2bfloat16(v.w);
    H.h2[0] = __nv_bfloat162(h0, h1);
    H.h2[1] = __nv_bfloat162(h2, h3);
    L.h2[0] = __nv_bfloat162(__float2bfloat16(v.x - __bfloat162float(h0)),
                             __float2bfloat16(v.y - __bfloat162float(h1)));
    L.h2[1] = __nv_bfloat162(__float2bfloat16(v.z - __bfloat162float(h2)),
                             __float2bfloat16(v.w - __bfloat162float(h3)));
    *(uint2*)(hi + j) = H.u;
    *(uint2*)(lo + j) = L.u;
}

// ==================== launch 2: split-bf16 GEMM, 128x128 tiles, 2 CTAs/SM ====================
// qkv/pq tiles: C = Ah*Wh^T + Ah*Wl^T + Al*Wh^T + bias (3-term).
// pk tiles: single-plane (score contribution is /48 -> bf16 error negligible).
#define GK    768
#define GBK2  32
#define GP2   40                          // pitch (elems): 80B rows, conflict-free LDSM
#define PL2B  (128 * GP2 * 2)             // 10240 bytes per plane
#define OFF2_AH 0
#define OFF2_AL PL2B
#define OFF2_WH (2 * PL2B)
#define OFF2_WL (3 * PL2B)
#define GBUF2  (4 * PL2B)                 // 40960 per buffer
#define GSM2   (2 * GBUF2)                // 81920 total -> 2 CTAs/SM

__global__ __launch_bounds__(256, 2) void gemm128(
    const __nv_bfloat16* __restrict__ xh, const __nv_bfloat16* __restrict__ xl,
    const __nv_bfloat16* __restrict__ ph, const __nv_bfloat16* __restrict__ pl,
    const __nv_bfloat16* __restrict__ wqh, const __nv_bfloat16* __restrict__ wql,
    const __nv_bfloat16* __restrict__ wpqh, const __nv_bfloat16* __restrict__ wpql,
    const __nv_bfloat16* __restrict__ wpkh, const __nv_bfloat16* __restrict__ wpkl,
    const float* __restrict__ qkv_b, const float* __restrict__ pq_b,
    const float* __restrict__ pk_b)
{
    extern __shared__ char smg[];
    const uint32_t sbase = smem_u32(smg);
    const int tid = threadIdx.x, lane = tid & 31, wid = tid >> 5;
    const int wm = wid >> 1;             // 0..3 -> m offset wm*32
    const int wn = wid & 1;              // 0..1 -> n offset wn*64
    const int bx = blockIdx.x;
    const int rowBase = blockIdx.y << 7; // *128

    const __nv_bfloat16 *Ah, *Al, *Wh, *Wl;
    const float* bias;
    float* C;
    int N, colBase;
    bool three = true;
    if (bx < 18)      { Ah = xh; Al = xl; Wh = wqh;  Wl = wql;  bias = qkv_b; C = g_QKV; N = 2304; colBase = bx * 128; }
    else if (bx < 24) { Ah = ph; Al = pl; Wh = wpqh; Wl = wpql; bias = pq_b;  C = g_PQ;  N = 768;  colBase = (bx - 18) * 128; }
    else              { Ah = ph; Al = pl; Wh = wpkh; Wl = wpkl; bias = pk_b;  C = g_PK;  N = 768;  colBase = (bx - 24) * 128; three = false; }

    const __nv_bfloat16* Ahg = Ah + (size_t)rowBase * GK;
    const __nv_bfloat16* Alg = Al + (size_t)rowBase * GK;
    const __nv_bfloat16* Whg = Wh + (size_t)colBase * GK;
    const __nv_bfloat16* Wlg = Wl + (size_t)colBase * GK;

    const uint32_t aoff = ((uint32_t)((wm * 32 + (lane & 15)) * GP2 + ((lane >> 4) * 8))) * 2;
    const uint32_t woff = ((uint32_t)((wn * 64 + ((lane >> 4) & 1) * 8 + (lane & 7)) * GP2
                                     + (((lane >> 3) & 1) * 8))) * 2;

    float c[2][8][4];
    #pragma unroll
    for (int i = 0; i < 2; i++)
        #pragma unroll
        for (int j = 0; j < 8; j++)
            #pragma unroll
            for (int k = 0; k < 4; k++) c[i][j][k] = 0.0f;

    auto load_chunk = [&](int ch, int buf) {
        const uint32_t base = sbase + (uint32_t)buf * GBUF2;
        const int k0 = ch * GBK2;
        #pragma unroll
        for (int it = 0; it < 2; it++) {         // 128 rows x 4 segs per plane
            const int idx = it * 256 + tid;      // 0..511
            const int row = idx >> 2, seg = (idx & 3) * 8;
            const uint32_t so = (uint32_t)(row * GP2 + seg) * 2;
            const size_t go = (size_t)row * GK + k0 + seg;
            cp16(base + OFF2_AH + so, Ahg + go);
            cp16(base + OFF2_WH + so, Whg + go);
            if (three) {
                cp16(base + OFF2_AL + so, Alg + go);
                cp16(base + OFF2_WL + so, Wlg + go);
            }
        }
    };

    load_chunk(0, 0);
    cp_commit();

    const int NCH = GK / GBK2;   // 24
    for (int ch = 0; ch < NCH; ch++) {
        if (ch + 1 < NCH) {
            load_chunk(ch + 1, (ch + 1) & 1);
            cp_commit();
            cp_wait<1>();
        } else {
            cp_wait<0>();
        }
        __syncthreads();

        const uint32_t base = sbase + (uint32_t)(ch & 1) * GBUF2;
        #pragma unroll
        for (int kk = 0; kk < GBK2; kk += 16) {
            uint32_t ah[2][4], al[2][4];
            #pragma unroll
            for (int fa = 0; fa < 2; fa++) {
                ldm_x4(ah[fa][0], ah[fa][1], ah[fa][2], ah[fa][3],
                       base + OFF2_AH + aoff + (uint32_t)(fa * 16 * GP2 + kk) * 2);
                if (three)
                    ldm_x4(al[fa][0], al[fa][1], al[fa][2], al[fa][3],
                           base + OFF2_AL + aoff + (uint32_t)(fa * 16 * GP2 + kk) * 2);
            }
            #pragma unroll
            for (int fb = 0; fb < 4; fb++) {
                uint32_t b[4];
                ldm_x4(b[0], b[1], b[2], b[3],
                       base + OFF2_WH + woff + (uint32_t)(fb * 16 * GP2 + kk) * 2);
                #pragma unroll
                for (int fa = 0; fa < 2; fa++) {
                    mma16816(c[fa][fb * 2],     ah[fa], b[0], b[1]);
                    mma16816(c[fa][fb * 2 + 1], ah[fa], b[2], b[3]);
                    if (three) {
                        mma16816(c[fa][fb * 2],     al[fa], b[0], b[1]);
                        mma16816(c[fa][fb * 2 + 1], al[fa], b[2], b[3]);
                    }
                }
                if (three) {
                    ldm_x4(b[0], b[1], b[2], b[3],
                           base + OFF2_WL + woff + (uint32_t)(fb * 16 * GP2 + kk) * 2);
                    #pragma unroll
                    for (int fa = 0; fa < 2; fa++) {
                        mma16816(c[fa][fb * 2],     ah[fa], b[0], b[1]);
                        mma16816(c[fa][fb * 2 + 1], ah[fa], b[2], b[3]);
                    }
                }
            }
        }
        __syncthreads();
    }

    // ---- epilogue ----
    const int gq = lane >> 2, tq = lane & 3;
    #pragma unroll
    for (int fa = 0; fa < 2; fa++) {
        #pragma unroll
        for (int nf = 0; nf < 8; nf++) {
            const int row = rowBase + wm * 32 + fa * 16 + gq;
            const int col = colBase + wn * 64 + nf * 8 + tq * 2;
            const float b0 = bias[col], b1 = bias[col + 1];
            float2 v0 = make_float2(c[fa][nf][0] + b0, c[fa][nf][1] + b1);
            float2 v1 = make_float2(c[fa][nf][2] + b0, c[fa][nf][3] + b1);
            *(float2*)(C + (size_t)row * N + col) = v0;
            *(float2*)(C + (size_t)(row + 8) * N + col) = v1;
        }
    }
}

// ==================== launch 3: fused build (Qc/Kc) + V transpose ====================
#define BQK_BLOCKS ((BH * SEQ * 64) / 256)   // 24576
#define VT_BLOCKS  ((SEQ / 64) * BH)         // 1536

__global__ __launch_bounds__(256) void build_all()
{
    __shared__ float ts[64][65];
    const int bxall = blockIdx.x;
    const int tid = threadIdx.x;

    if (bxall < BQK_BLOCKS) {
        const int idx = bxall * 256 + tid;
        const int d  = idx & 63;
        const int l  = (idx >> 6) & (SEQ - 1);
        const int bh = idx >> 16;
        const int b  = bh / NHEAD, h = bh - b * NHEAD;
        const size_t row = (size_t)b * SEQ + l;
        const int c = h * HEAD_DIM + d;
        const float q  = g_QKV[row * 2304 + c];
        const float k  = g_QKV[row * 2304 + 768 + c];
        const float pq = g_PQ[row * 768 + c];
        const float pk = g_PK[row * 768 + c];
        const float k2 = k + pq;
        const __nv_bfloat16 qh = __float2bfloat16(q);
        const __nv_bfloat16 ql = __float2bfloat16(q - __bfloat162float(qh));
        const __nv_bfloat16 kh = __float2bfloat16(k2);
        const __nv_bfloat16 kl = __float2bfloat16(k2 - __bfloat162float(kh));
        const size_t base = ((size_t)bh * SEQ + l) * DQK;
        g_Qc[base + d]        = qh;
        g_Qc[base + 64 + d]   = qh;
        g_Qc[base + 128 + d]  = ql;
        g_Qc[base + 192 + d]  = __float2bfloat16(k * INV_SCALE);
        g_Kc[base + d]        = kh;
        g_Kc[base + 64 + d]   = kl;
        g_Kc[base + 128 + d]  = kh;
        g_Kc[base + 192 + d]  = __float2bfloat16(pk);
    } else {
        const int bx2 = bxall - BQK_BLOCKS;
        const int lt = bx2 & 15, bh = bx2 >> 4;
        const int b = bh / NHEAD, h = bh - b * NHEAD;
        {
            const int ll = tid >> 2, ds = (tid & 3) * 16;
            const float* src = g_QKV + ((size_t)(b * SEQ + lt * 64 + ll)) * 2304
                             + 1536 + h * HEAD_DIM + ds;
            #pragma unroll
            for (int i = 0; i < 4; i++) {
                float4 v = *(const float4*)(src + i * 4);
                ts[ll][ds + i * 4 + 0] = v.x;
                ts[ll][ds + i * 4 + 1] = v.y;
                ts[ll][ds + i * 4 + 2] = v.z;
                ts[ll][ds + i * 4 + 3] = v.w;
            }
        }
        __syncthreads();
        {
            const int d = tid >> 2, ls = (tid & 3) * 16;
            __half* dst = g_Vt + ((size_t)bh * HEAD_DIM + d) * SEQ + lt * 64 + ls;
            #pragma unroll
            for (int i = 0; i < 8; i++) {
                __half2 hv = __floats2half2_rn(ts[ls + 2 * i][d], ts[ls + 2 * i + 1][d]);
                *(__half2*)(dst + 2 * i) = hv;
            }
        }
    }
}

// ==================== launch 4: flash attention, 4-warp CTAs, 2 CTAs/SM ====================
// ABM=64 q rows per CTA (4 warps x m16), ABN=64 keys/tile. Two independent CTAs
// per SM de-phase-lock the QK -> softmax -> PV pipeline across the tensor pipe.
#define ABM 64
#define ABN 64
#define AQP 264
#define AVP 72
#define SK_OFF 0
#define SK_BYTES (ABN * AQP * 2)        // 33792
#define SV_OFF (SK_OFF + 2 * SK_BYTES)  // 67584
#define SV_BYTES (ABN * AVP * 2)        // 9216
#define ASMEM (SV_OFF + 2 * SV_BYTES)   // 86016  -> 2 CTAs/SM (172KB < 227KB)

__global__ __launch_bounds__(128, 2) void attn_mma(float* __restrict__ out)
{
    extern __shared__ char smc[];
    const uint32_t sb = smem_u32(smc);
    const int tid = threadIdx.x, lane = tid & 31, w = tid >> 5;   // w in 0..3
    const int qb = blockIdx.x, bh = blockIdx.y;
    const int g = lane >> 2, t = lane & 3;

    const __nv_bfloat16* Qg = g_Qc + ((size_t)bh * SEQ + (size_t)qb * ABM) * DQK;
    const __nv_bfloat16* Kg = g_Kc + (size_t)bh * SEQ * DQK;
    const __half*        Vg = g_Vt + (size_t)bh * HEAD_DIM * SEQ;

    const uint32_t aoff = (uint32_t)((w * 16 + (lane & 15)) * AQP + (lane >> 4) * 8) * 2;
    const uint32_t kfrag = (uint32_t)((((lane >> 4) & 1) * 8 + (lane & 7)) * AQP
                                     + ((lane >> 3) & 1) * 8) * 2;
    const uint32_t vfrag = (uint32_t)((((lane >> 4) & 1) * 8 + (lane & 7)) * AVP
                                     + ((lane >> 3) & 1) * 8) * 2;

    // ---- stage Q (64 rows x 512B) through the first K buffer, hoist frags to regs ----
    #pragma unroll
    for (int it = 0; it < 16; it++) {
        const int idx = it * 128 + tid;             // 0..2047
        const int r = idx >> 5, s = idx & 31;
        cp16(sb + SK_OFF + (uint32_t)(r * AQP + s * 8) * 2, Qg + (size_t)r * DQK + s * 8);
    }
    cp_commit();
    cp_wait<0>();
    __syncthreads();

    uint32_t qr[16][4];
    #pragma unroll
    for (int ks = 0; ks < DQK / 16; ks++)
        ldm_x4(qr[ks][0], qr[ks][1], qr[ks][2], qr[ks][3],
               sb + SK_OFF + aoff + ks * 32);
    __syncthreads();    // all warps done reading staged Q before K overwrites

    auto loadKV = [&](int kt, int buf) {
        const __nv_bfloat16* Kt = Kg + (size_t)kt * ABN * DQK;
        #pragma unroll
        for (int it = 0; it < 16; it++) {
            const int idx = it * 128 + tid;
            const int r = idx >> 5, s = idx & 31;
            cp16(sb + SK_OFF + buf * SK_BYTES + (uint32_t)(r * AQP + s * 8) * 2,
                 Kt + (size_t)r * DQK + s * 8);
        }
        #pragma unroll
        for (int it = 0; it < 4; it++) {
            const int idx = it * 128 + tid;
            const int r = idx >> 3, s = idx & 7;
            cp16(sb + SV_OFF + buf * SV_BYTES + (uint32_t)(r * AVP + s * 8) * 2,
                 Vg + (size_t)r * SEQ + kt * ABN + s * 8);
        }
    };
    loadKV(0, 0);
    cp_commit();

    float m0 = -1e30f, m1 = -1e30f, l0 = 0.0f, l1 = 0.0f;
    float o[8][4];
    #pragma unroll
    for (int f = 0; f < 8; f++)
        #pragma unroll
        for (int j = 0; j < 4; j++) o[f][j] = 0.0f;

    for (int kt = 0; kt < SEQ / ABN; kt++) {
        if (kt + 1 < SEQ / ABN) {
            loadKV(kt + 1, (kt + 1) & 1);
            cp_commit();
            cp_wait<1>();
        } else {
            cp_wait<0>();
        }
        __syncthreads();

        const uint32_t sK = sb + SK_OFF + (kt & 1) * SK_BYTES;
        const uint32_t sV = sb + SV_OFF + (kt & 1) * SV_BYTES;

        // ---- S = Q'' @ K''^T (m16 x n64 per warp, k=256) ----
        float c[8][4];
        #pragma unroll
        for (int f = 0; f < 8; f++)
            #pragma unroll
            for (int j = 0; j < 4; j++) c[f][j] = 0.0f;

        #pragma unroll
        for (int ks = 0; ks < DQK / 16; ks++) {
            #pragma unroll
            for (int fb = 0; fb < 4; fb++) {
                uint32_t b[4];
                ldm_x4(b[0], b[1], b[2], b[3],
                       sK + kfrag + (uint32_t)(fb * 16 * AQP) * 2 + ks * 32);
                mma16816(c[fb * 2],     qr[ks], b[0], b[1]);
                mma16816(c[fb * 2 + 1], qr[ks], b[2], b[3]);
            }
        }

        // ---- online softmax (fp32 __expf, round-8 form) ----
        float mx0 = c[0][0], mx1 = c[0][2];
        #pragma unroll
        for (int f = 0; f < 8; f++) {
            mx0 = fmaxf(mx0, fmaxf(c[f][0], c[f][1]));
            mx1 = fmaxf(mx1, fmaxf(c[f][2], c[f][3]));
        }
        mx0 = fmaxf(mx0, __shfl_xor_sync(0xffffffffu, mx0, 1));
        mx0 = fmaxf(mx0, __shfl_xor_sync(0xffffffffu, mx0, 2));
        mx1 = fmaxf(mx1, __shfl_xor_sync(0xffffffffu, mx1, 1));
        mx1 = fmaxf(mx1, __shfl_xor_sync(0xffffffffu, mx1, 2));
        const float nm0 = fmaxf(m0, mx0), nm1 = fmaxf(m1, mx1);
        const float cr0 = __expf(m0 - nm0), cr1 = __expf(m1 - nm1);
        m0 = nm0; m1 = nm1;
        float rs0 = 0.0f, rs1 = 0.0f;
        #pragma unroll
        for (int f = 0; f < 8; f++) {
            c[f][0] = __expf(c[f][0] - nm0); rs0 += c[f][0];
            c[f][1] = __expf(c[f][1] - nm0); rs0 += c[f][1];
            c[f][2] = __expf(c[f][2] - nm1); rs1 += c[f][2];
            c[f][3] = __expf(c[f][3] - nm1); rs1 += c[f][3];
        }
        l0 = l0 * cr0 + rs0;
        l1 = l1 * cr1 + rs1;
        #pragma unroll
        for (int f = 0; f < 8; f++) {
            o[f][0] *= cr0; o[f][1] *= cr0;
            o[f][2] *= cr1; o[f][3] *= cr1;
        }

        // ---- O += P @ V (P packed to fp16 A-frags from registers) ----
        #pragma unroll
        for (int ks = 0; ks < ABN / 16; ks++) {
            uint32_t pa[4];
            pa[0] = pack_h2(c[2 * ks][0],     c[2 * ks][1]);
            pa[1] = pack_h2(c[2 * ks][2],     c[2 * ks][3]);
            pa[2] = pack_h2(c[2 * ks + 1][0], c[2 * ks + 1][1]);
            pa[3] = pack_h2(c[2 * ks + 1][2], c[2 * ks + 1][3]);
            #pragma unroll
            for (int fb = 0; fb < 4; fb++) {
                uint32_t vb[4];
                ldm_x4(vb[0], vb[1], vb[2], vb[3],
                       sV + vfrag + (uint32_t)(fb * 16 * AVP) * 2 + ks * 32);
                mma16816h(o[fb * 2],     pa, vb[0], vb[1]);
                mma16816h(o[fb * 2 + 1], pa, vb[2], vb[3]);
            }
        }
        __syncthreads();
    }

    l0 += __shfl_xor_sync(0xffffffffu, l0, 1);
    l0 += __shfl_xor_sync(0xffffffffu, l0, 2);
    l1 += __shfl_xor_sync(0xffffffffu, l1, 1);
    l1 += __shfl_xor_sync(0xffffffffu, l1, 2);
    const float inv0 = 1.0f / l0, inv1 = 1.0f / l1;
    const int b_ = bh / NHEAD, h = bh - b_ * NHEAD;
    const int r0 = qb * ABM + w * 16 + g;
    float* p0 = out + (((size_t)(b_ * SEQ + r0)) * NHEAD + h) * HEAD_DIM;
    float* p1 = out + (((size_t)(b_ * SEQ + r0 + 8)) * NHEAD + h) * HEAD_DIM;
    #pragma unroll
    for (int f = 0; f < 8; f++) {
        const int col = f * 8 + t * 2;
        *(float2*)(p0 + col) = make_float2(o[f][0] * inv0, o[f][1] * inv0);
        *(float2*)(p1 + col) = make_float2(o[f][2] * inv1, o[f][3] * inv1);
    }
}

// ====================================================================
extern "C" void kernel_launch(void* const* d_in, const int* in_sizes, int n_in,
                              void* d_out, int out_size)
{
    const float* x     = (const float*)d_in[0];
    const float* pos   = (const float*)d_in[1];
    const float* qkv_w = (const float*)d_in[2];
    const float* qkv_b = (const float*)d_in[3];
    const float* pq_w  = (const float*)d_in[4];
    const float* pq_b  = (const float*)d_in[5];
    const float* pk_w  = (const float*)d_in[6];
    const float* pk_b  = (const float*)d_in[7];
    float* out = (float*)d_out;

    __nv_bfloat16 *xh, *xl, *ph, *pl, *wqh, *wql, *wpqh, *wpql, *wpkh, *wpkl;
    cudaGetSymbolAddress((void**)&xh,   g_xh);
    cudaGetSymbolAddress((void**)&xl,   g_xl);
    cudaGetSymbolAddress((void**)&ph,   g_ph);
    cudaGetSymbolAddress((void**)&pl,   g_pl);
    cudaGetSymbolAddress((void**)&wqh,  g_wqh);
    cudaGetSymbolAddress((void**)&wql,  g_wql);
    cudaGetSymbolAddress((void**)&wpqh, g_wpqh);
    cudaGetSymbolAddress((void**)&wpql, g_wpql);
    cudaGetSymbolAddress((void**)&wpkh, g_wpkh);
    cudaGetSymbolAddress((void**)&wpkl, g_wpkl);

    // 1) split into hi/lo bf16 planes (float4 vectorized)
    split_all<<<(SPLIT_V4 + 255) / 256, 256>>>(x, pos, qkv_w, pq_w, pk_w);

    // 2) all three projections in one launch (pk single-plane)
    cudaFuncSetAttribute(gemm128, cudaFuncAttributeMaxDynamicSharedMemorySize, GSM2);
    gemm128<<<dim3(30, 64), 256, GSM2>>>(xh, xl, ph, pl, wqh, wql,
                                         wpqh, wpql, wpkh, wpkl,
                                         qkv_b, pq_b, pk_b);

    // 3) build attention operands (Qc/Kc concat-split + V fp16 transpose)
    build_all<<<BQK_BLOCKS + VT_BLOCKS, 256>>>();

    // 4) flash attention (4-warp CTAs, 2 CTAs/SM, Q register-resident)
    cudaFuncSetAttribute(attn_mma, cudaFuncAttributeMaxDynamicSharedMemorySize, ASMEM);
    attn_mma<<<dim3(SEQ / ABM, BH), 128, ASMEM>>>(out);
}

// round 12
// speedup vs baseline: 3.9222x; 1.0190x over previous
#include <cuda_runtime.h>
#include <cuda_bf16.h>
#include <cuda_fp16.h>
#include <cstdint>
#include <cstddef>

#define D_MODEL 768
#define NHEAD   12
#define HEAD_DIM 64
#define BATCH   8
#define SEQ     1024
#define BH      (BATCH * NHEAD)     // 96
#define M_ROWS  (BATCH * SEQ)       // 8192
#define DQK     256                 // concat-split attention dim
#define INV_SCALE (1.0f / 48.0f)    // 1/sqrt(3*768)

// ---------------- scratch (static device allocation; no cudaMalloc) ----------------
__device__ float g_QKV [M_ROWS * 3 * D_MODEL];   // only k-part [768:1536) written/read now
__device__ float g_PQ  [M_ROWS * D_MODEL];

// attention operands
__device__ __nv_bfloat16 g_Qc[(size_t)BH * SEQ * DQK];   // [qh|qh|ql|k/48]
__device__ __nv_bfloat16 g_Kc[(size_t)BH * SEQ * DQK];   // [k'h|k'l|k'h|pk]
__device__ __half        g_Vt[(size_t)BH * HEAD_DIM * SEQ]; // transposed [bh][d][l]

// split-bf16 hi/lo planes for projections
__device__ __nv_bfloat16 g_xh [M_ROWS * D_MODEL];
__device__ __nv_bfloat16 g_xl [M_ROWS * D_MODEL];
__device__ __nv_bfloat16 g_ph [M_ROWS * D_MODEL];
__device__ __nv_bfloat16 g_pl [M_ROWS * D_MODEL];
__device__ __nv_bfloat16 g_wqh[3 * D_MODEL * D_MODEL];
__device__ __nv_bfloat16 g_wql[3 * D_MODEL * D_MODEL];
__device__ __nv_bfloat16 g_wpqh[D_MODEL * D_MODEL];
__device__ __nv_bfloat16 g_wpql[D_MODEL * D_MODEL];
__device__ __nv_bfloat16 g_wpkh[D_MODEL * D_MODEL];
__device__ __nv_bfloat16 g_wpkl[D_MODEL * D_MODEL];

// ==================== helpers ====================
__device__ __forceinline__ uint32_t smem_u32(const void* p) {
    uint32_t a;
    asm("{ .reg .u64 t; cvta.to.shared.u64 t, %1; cvt.u32.u64 %0, t; }" : "=r"(a) : "l"(p));
    return a;
}
__device__ __forceinline__ void cp16(uint32_t dst, const void* src) {
    asm volatile("cp.async.cg.shared.global [%0], [%1], 16;" :: "r"(dst), "l"(src));
}
__device__ __forceinline__ void cp_commit() {
    asm volatile("cp.async.commit_group;" ::: "memory");
}
template <int N>
__device__ __forceinline__ void cp_wait() {
    asm volatile("cp.async.wait_group %0;" :: "n"(N) : "memory");
}
__device__ __forceinline__ void ldm_x4(uint32_t& r0, uint32_t& r1, uint32_t& r2,
                                       uint32_t& r3, uint32_t addr) {
    asm volatile("ldmatrix.sync.aligned.m8n8.x4.shared.b16 {%0,%1,%2,%3}, [%4];"
                 : "=r"(r0), "=r"(r1), "=r"(r2), "=r"(r3) : "r"(addr));
}
__device__ __forceinline__ void mma16816(float* c, const uint32_t* a,
                                         uint32_t b0, uint32_t b1) {
    asm volatile(
        "mma.sync.aligned.m16n8k16.row.col.f32.bf16.bf16.f32 "
        "{%0,%1,%2,%3}, {%4,%5,%6,%7}, {%8,%9}, {%0,%1,%2,%3};"
        : "+f"(c[0]), "+f"(c[1]), "+f"(c[2]), "+f"(c[3])
        : "r"(a[0]), "r"(a[1]), "r"(a[2]), "r"(a[3]), "r"(b0), "r"(b1));
}
__device__ __forceinline__ void mma16816h(float* c, const uint32_t* a,
                                          uint32_t b0, uint32_t b1) {
    asm volatile(
        "mma.sync.aligned.m16n8k16.row.col.f32.f16.f16.f32 "
        "{%0,%1,%2,%3}, {%4,%5,%6,%7}, {%8,%9}, {%0,%1,%2,%3};"
        : "+f"(c[0]), "+f"(c[1]), "+f"(c[2]), "+f"(c[3])
        : "r"(a[0]), "r"(a[1]), "r"(a[2]), "r"(a[3]), "r"(b0), "r"(b1));
}
__device__ __forceinline__ uint32_t pack_h2(float lo, float hi) {
    __half2 h = __floats2half2_rn(lo, hi);
    return *(uint32_t*)&h;
}

// ==================== launch 1: fused split fp32 -> (hi, lo) bf16 planes ====================
#define NXE (M_ROWS * D_MODEL)          // 6291456
#define NWQE (3 * D_MODEL * D_MODEL)    // 1769472
#define NWE (D_MODEL * D_MODEL)         // 589824
#define SPLIT_TOTAL (2 * NXE + NWQE + 2 * NWE)
#define SPLIT_V4 (SPLIT_TOTAL / 4)

__global__ __launch_bounds__(256) void split_all(
    const float* __restrict__ x, const float* __restrict__ pos,
    const float* __restrict__ wq, const float* __restrict__ wpq,
    const float* __restrict__ wpk)
{
    const int i4 = blockIdx.x * 256 + threadIdx.x;
    if (i4 >= SPLIT_V4) return;
    const int i = i4 * 4;
    const float* src;
    __nv_bfloat16 *hi, *lo;
    int j;
    if (i < NXE)                       { j = i;                        src = x;   hi = g_xh;   lo = g_xl;   }
    else if (i < 2 * NXE)              { j = i - NXE;                  src = pos; hi = g_ph;   lo = g_pl;   }
    else if (i < 2 * NXE + NWQE)       { j = i - 2 * NXE;              src = wq;  hi = g_wqh;  lo = g_wql;  }
    else if (i < 2 * NXE + NWQE + NWE) { j = i - 2 * NXE - NWQE;       src = wpq; hi = g_wpqh; lo = g_wpql; }
    else                               { j = i - 2 * NXE - NWQE - NWE; src = wpk; hi = g_wpkh; lo = g_wpkl; }

    const float4 v = *(const float4*)(src + j);
    union { __nv_bfloat162 h2[2]; uint2 u; } H, L;
    __nv_bfloat16 h0 = __float2bfloat16(v.x), h1 = __float2bfloat16(v.y);
    __nv_bfloat16 h2 = __float2bfloat16(v.z), h3 = __float2bfloat16(v.w);
    H.h2[0] = __nv_bfloat162(h0, h1);
    H.h2[1] = __nv_bfloat162(h2, h3);
    L.h2[0] = __nv_bfloat162(__float2bfloat16(v.x - __bfloat162float(h0)),
                             __float2bfloat16(v.y - __bfloat162float(h1)));
    L.h2[1] = __nv_bfloat162(__float2bfloat16(v.z - __bfloat162float(h2)),
                             __float2bfloat16(v.w - __bfloat162float(h3)));
    *(uint2*)(hi + j) = H.u;
    *(uint2*)(lo + j) = L.u;
}

// ==================== launch 2: split-bf16 GEMM with fused operand-build epilogue ====
// qkv/pq tiles: C = Ah*Wh^T + Ah*Wl^T + Al*Wh^T + bias (3-term).
// pk tiles: single-plane. Epilogues write final attention operand formats directly:
//   bx  0-5  (q):  qh/qh/ql bf16 -> g_Qc[0|64|128]
//   bx  6-11 (k):  fp32 k -> g_QKV (for k'=k+pq in build) AND bf16 k/48 -> g_Qc[192]
//   bx 12-17 (v):  fp16 transposed -> g_Vt
//   bx 18-23 (pq): fp32 -> g_PQ
//   bx 24-29 (pk): bf16 -> g_Kc[192]
#define GK    768
#define GBK2  32
#define GP2   40                          // pitch (elems): 80B rows, conflict-free LDSM
#define PL2B  (128 * GP2 * 2)             // 10240 bytes per plane
#define OFF2_AH 0
#define OFF2_AL PL2B
#define OFF2_WH (2 * PL2B)
#define OFF2_WL (3 * PL2B)
#define GBUF2  (4 * PL2B)                 // 40960 per buffer
#define GSM2   (2 * GBUF2)                // 81920 total -> 2 CTAs/SM

__global__ __launch_bounds__(256, 2) void gemm128(
    const __nv_bfloat16* __restrict__ xh, const __nv_bfloat16* __restrict__ xl,
    const __nv_bfloat16* __restrict__ ph, const __nv_bfloat16* __restrict__ pl,
    const __nv_bfloat16* __restrict__ wqh, const __nv_bfloat16* __restrict__ wql,
    const __nv_bfloat16* __restrict__ wpqh, const __nv_bfloat16* __restrict__ wpql,
    const __nv_bfloat16* __restrict__ wpkh, const __nv_bfloat16* __restrict__ wpkl,
    const float* __restrict__ qkv_b, const float* __restrict__ pq_b,
    const float* __restrict__ pk_b)
{
    extern __shared__ char smg[];
    const uint32_t sbase = smem_u32(smg);
    const int tid = threadIdx.x, lane = tid & 31, wid = tid >> 5;
    const int wm = wid >> 1;             // 0..3 -> m offset wm*32
    const int wn = wid & 1;              // 0..1 -> n offset wn*64
    const int bx = blockIdx.x;
    const int rowBase = blockIdx.y << 7; // *128

    const __nv_bfloat16 *Ah, *Al, *Wh, *Wl;
    const float* bias;
    int colBase;
    bool three = true;
    if (bx < 18)      { Ah = xh; Al = xl; Wh = wqh;  Wl = wql;  bias = qkv_b; colBase = bx * 128; }
    else if (bx < 24) { Ah = ph; Al = pl; Wh = wpqh; Wl = wpql; bias = pq_b;  colBase = (bx - 18) * 128; }
    else              { Ah = ph; Al = pl; Wh = wpkh; Wl = wpkl; bias = pk_b;  colBase = (bx - 24) * 128; three = false; }

    const __nv_bfloat16* Ahg = Ah + (size_t)rowBase * GK;
    const __nv_bfloat16* Alg = Al + (size_t)rowBase * GK;
    const __nv_bfloat16* Whg = Wh + (size_t)colBase * GK;
    const __nv_bfloat16* Wlg = Wl + (size_t)colBase * GK;

    const uint32_t aoff = ((uint32_t)((wm * 32 + (lane & 15)) * GP2 + ((lane >> 4) * 8))) * 2;
    const uint32_t woff = ((uint32_t)((wn * 64 + ((lane >> 4) & 1) * 8 + (lane & 7)) * GP2
                                     + (((lane >> 3) & 1) * 8))) * 2;

    float c[2][8][4];
    #pragma unroll
    for (int i = 0; i < 2; i++)
        #pragma unroll
        for (int j = 0; j < 8; j++)
            #pragma unroll
            for (int k = 0; k < 4; k++) c[i][j][k] = 0.0f;

    auto load_chunk = [&](int ch, int buf) {
        const uint32_t base = sbase + (uint32_t)buf * GBUF2;
        const int k0 = ch * GBK2;
        #pragma unroll
        for (int it = 0; it < 2; it++) {
            const int idx = it * 256 + tid;
            const int row = idx >> 2, seg = (idx & 3) * 8;
            const uint32_t so = (uint32_t)(row * GP2 + seg) * 2;
            const size_t go = (size_t)row * GK + k0 + seg;
            cp16(base + OFF2_AH + so, Ahg + go);
            cp16(base + OFF2_WH + so, Whg + go);
            if (three) {
                cp16(base + OFF2_AL + so, Alg + go);
                cp16(base + OFF2_WL + so, Wlg + go);
            }
        }
    };

    load_chunk(0, 0);
    cp_commit();

    const int NCH = GK / GBK2;   // 24
    for (int ch = 0; ch < NCH; ch++) {
        if (ch + 1 < NCH) {
            load_chunk(ch + 1, (ch + 1) & 1);
            cp_commit();
            cp_wait<1>();
        } else {
            cp_wait<0>();
        }
        __syncthreads();

        const uint32_t base = sbase + (uint32_t)(ch & 1) * GBUF2;
        #pragma unroll
        for (int kk = 0; kk < GBK2; kk += 16) {
            uint32_t ah[2][4], al[2][4];
            #pragma unroll
            for (int fa = 0; fa < 2; fa++) {
                ldm_x4(ah[fa][0], ah[fa][1], ah[fa][2], ah[fa][3],
                       base + OFF2_AH + aoff + (uint32_t)(fa * 16 * GP2 + kk) * 2);
                if (three)
                    ldm_x4(al[fa][0], al[fa][1], al[fa][2], al[fa][3],
                           base + OFF2_AL + aoff + (uint32_t)(fa * 16 * GP2 + kk) * 2);
            }
            #pragma unroll
            for (int fb = 0; fb < 4; fb++) {
                uint32_t b[4];
                ldm_x4(b[0], b[1], b[2], b[3],
                       base + OFF2_WH + woff + (uint32_t)(fb * 16 * GP2 + kk) * 2);
                #pragma unroll
                for (int fa = 0; fa < 2; fa++) {
                    mma16816(c[fa][fb * 2],     ah[fa], b[0], b[1]);
                    mma16816(c[fa][fb * 2 + 1], ah[fa], b[2], b[3]);
                    if (three) {
                        mma16816(c[fa][fb * 2],     al[fa], b[0], b[1]);
                        mma16816(c[fa][fb * 2 + 1], al[fa], b[2], b[3]);
                    }
                }
                if (three) {
                    ldm_x4(b[0], b[1], b[2], b[3],
                           base + OFF2_WL + woff + (uint32_t)(fb * 16 * GP2 + kk) * 2);
                    #pragma unroll
                    for (int fa = 0; fa < 2; fa++) {
                        mma16816(c[fa][fb * 2],     ah[fa], b[0], b[1]);
                        mma16816(c[fa][fb * 2 + 1], ah[fa], b[2], b[3]);
                    }
                }
            }
        }
        __syncthreads();
    }

    // ---- fused epilogue ----
    const int gq = lane >> 2, tq = lane & 3;
    #pragma unroll
    for (int fa = 0; fa < 2; fa++) {
        #pragma unroll
        for (int nf = 0; nf < 8; nf++) {
            const int row0 = rowBase + wm * 32 + fa * 16 + gq;    // and row0+8
            const int col = colBase + wn * 64 + nf * 8 + tq * 2;  // even
            const float b0 = bias[col], b1 = bias[col + 1];
            const float v0a = c[fa][nf][0] + b0, v1a = c[fa][nf][1] + b1;   // row0
            const float v0b = c[fa][nf][2] + b0, v1b = c[fa][nf][3] + b1;   // row0+8

            if (bx < 6) {
                // ---- q -> Qc[0|64|128] ----
                const int h = col >> 6, d = col & 63;
                #pragma unroll
                for (int rr = 0; rr < 2; rr++) {
                    const int row = row0 + rr * 8;
                    const float u0 = rr ? v0b : v0a, u1 = rr ? v1b : v1a;
                    const int b_ = row >> 10, l = row & (SEQ - 1);
                    const size_t baseQ = ((size_t)(b_ * NHEAD + h) * SEQ + l) * DQK;
                    __nv_bfloat16 h0 = __float2bfloat16(u0), h1 = __float2bfloat16(u1);
                    __nv_bfloat162 H(h0, h1);
                    __nv_bfloat162 L(__float2bfloat16(u0 - __bfloat162float(h0)),
                                     __float2bfloat16(u1 - __bfloat162float(h1)));
                    *(__nv_bfloat162*)&g_Qc[baseQ + d]       = H;
                    *(__nv_bfloat162*)&g_Qc[baseQ + 64 + d]  = H;
                    *(__nv_bfloat162*)&g_Qc[baseQ + 128 + d] = L;
                }
            } else if (bx < 12) {
                // ---- k -> fp32 g_QKV (for k'=k+pq) AND bf16 k/48 -> Qc[192] ----
                *(float2*)(g_QKV + (size_t)row0 * 2304 + col) = make_float2(v0a, v1a);
                *(float2*)(g_QKV + (size_t)(row0 + 8) * 2304 + col) = make_float2(v0b, v1b);
                const int ch = col - 768, h = ch >> 6, d = ch & 63;
                #pragma unroll
                for (int rr = 0; rr < 2; rr++) {
                    const int row = row0 + rr * 8;
                    const float u0 = rr ? v0b : v0a, u1 = rr ? v1b : v1a;
                    const int b_ = row >> 10, l = row & (SEQ - 1);
                    const size_t baseQ = ((size_t)(b_ * NHEAD + h) * SEQ + l) * DQK;
                    *(__nv_bfloat162*)&g_Qc[baseQ + 192 + d] =
                        __nv_bfloat162(__float2bfloat16(u0 * INV_SCALE),
                                       __float2bfloat16(u1 * INV_SCALE));
                }
            } else if (bx < 18) {
                // ---- v -> fp16 transposed g_Vt[bh][d][l] ----
                const int ch = col - 1536, h = ch >> 6, d = ch & 63;
                #pragma unroll
                for (int rr = 0; rr < 2; rr++) {
                    const int row = row0 + rr * 8;
                    const float u0 = rr ? v0b : v0a, u1 = rr ? v1b : v1a;
                    const int b_ = row >> 10, l = row & (SEQ - 1);
                    const size_t bh = (size_t)(b_ * NHEAD + h);
                    g_Vt[(bh * HEAD_DIM + d) * SEQ + l]     = __float2half(u0);
                    g_Vt[(bh * HEAD_DIM + d + 1) * SEQ + l] = __float2half(u1);
                }
            } else if (bx < 24) {
                // ---- pq -> fp32 g_PQ ----
                *(float2*)(g_PQ + (size_t)row0 * 768 + col) = make_float2(v0a, v1a);
                *(float2*)(g_PQ + (size_t)(row0 + 8) * 768 + col) = make_float2(v0b, v1b);
            } else {
                // ---- pk -> bf16 Kc[192] ----
                const int h = col >> 6, d = col & 63;
                #pragma unroll
                for (int rr = 0; rr < 2; rr++) {
                    const int row = row0 + rr * 8;
                    const float u0 = rr ? v0b : v0a, u1 = rr ? v1b : v1a;
                    const int b_ = row >> 10, l = row & (SEQ - 1);
                    const size_t baseK = ((size_t)(b_ * NHEAD + h) * SEQ + l) * DQK;
                    *(__nv_bfloat162*)&g_Kc[baseK + 192 + d] =
                        __nv_bfloat162(__float2bfloat16(u0), __float2bfloat16(u1));
                }
            }
        }
    }
}

// ==================== launch 3: build Kc[0..191] = split(k + pq) ====================
#define BQK_BLOCKS ((BH * SEQ * 64) / 256)   // 24576

__global__ __launch_bounds__(256) void build_all()
{
    const int idx = blockIdx.x * 256 + threadIdx.x;
    const int d  = idx & 63;
    const int l  = (idx >> 6) & (SEQ - 1);
    const int bh = idx >> 16;
    const int b  = bh / NHEAD, h = bh - b * NHEAD;
    const size_t row = (size_t)b * SEQ + l;
    const int c = h * HEAD_DIM + d;
    const float k  = g_QKV[row * 2304 + 768 + c];
    const float pq = g_PQ[row * 768 + c];
    const float k2 = k + pq;
    const __nv_bfloat16 kh = __float2bfloat16(k2);
    const __nv_bfloat16 kl = __float2bfloat16(k2 - __bfloat162float(kh));
    const size_t base = ((size_t)bh * SEQ + l) * DQK;
    g_Kc[base + d]        = kh;
    g_Kc[base + 64 + d]   = kl;
    g_Kc[base + 128 + d]  = kh;
}

// ==================== launch 4: flash attention, 4-warp CTAs, 2 CTAs/SM ====================
#define ABM 64
#define ABN 64
#define AQP 264
#define AVP 72
#define SK_OFF 0
#define SK_BYTES (ABN * AQP * 2)        // 33792
#define SV_OFF (SK_OFF + 2 * SK_BYTES)  // 67584
#define SV_BYTES (ABN * AVP * 2)        // 9216
#define ASMEM (SV_OFF + 2 * SV_BYTES)   // 86016  -> 2 CTAs/SM

__global__ __launch_bounds__(128, 2) void attn_mma(float* __restrict__ out)
{
    extern __shared__ char smc[];
    const uint32_t sb = smem_u32(smc);
    const int tid = threadIdx.x, lane = tid & 31, w = tid >> 5;
    const int qb = blockIdx.x, bh = blockIdx.y;
    const int g = lane >> 2, t = lane & 3;

    const __nv_bfloat16* Qg = g_Qc + ((size_t)bh * SEQ + (size_t)qb * ABM) * DQK;
    const __nv_bfloat16* Kg = g_Kc + (size_t)bh * SEQ * DQK;
    const __half*        Vg = g_Vt + (size_t)bh * HEAD_DIM * SEQ;

    const uint32_t aoff = (uint32_t)((w * 16 + (lane & 15)) * AQP + (lane >> 4) * 8) * 2;
    const uint32_t kfrag = (uint32_t)((((lane >> 4) & 1) * 8 + (lane & 7)) * AQP
                                     + ((lane >> 3) & 1) * 8) * 2;
    const uint32_t vfrag = (uint32_t)((((lane >> 4) & 1) * 8 + (lane & 7)) * AVP
                                     + ((lane >> 3) & 1) * 8) * 2;

    // ---- stage Q (64 rows x 512B) through the first K buffer, hoist frags to regs ----
    #pragma unroll
    for (int it = 0; it < 16; it++) {
        const int idx = it * 128 + tid;
        const int r = idx >> 5, s = idx & 31;
        cp16(sb + SK_OFF + (uint32_t)(r * AQP + s * 8) * 2, Qg + (size_t)r * DQK + s * 8);
    }
    cp_commit();
    cp_wait<0>();
    __syncthreads();

    uint32_t qr[16][4];
    #pragma unroll
    for (int ks = 0; ks < DQK / 16; ks++)
        ldm_x4(qr[ks][0], qr[ks][1], qr[ks][2], qr[ks][3],
               sb + SK_OFF + aoff + ks * 32);
    __syncthreads();

    auto loadKV = [&](int kt, int buf) {
        const __nv_bfloat16* Kt = Kg + (size_t)kt * ABN * DQK;
        #pragma unroll
        for (int it = 0; it < 16; it++) {
            const int idx = it * 128 + tid;
            const int r = idx >> 5, s = idx & 31;
            cp16(sb + SK_OFF + buf * SK_BYTES + (uint32_t)(r * AQP + s * 8) * 2,
                 Kt + (size_t)r * DQK + s * 8);
        }
        #pragma unroll
        for (int it = 0; it < 4; it++) {
            const int idx = it * 128 + tid;
            const int r = idx >> 3, s = idx & 7;
            cp16(sb + SV_OFF + buf * SV_BYTES + (uint32_t)(r * AVP + s * 8) * 2,
                 Vg + (size_t)r * SEQ + kt * ABN + s * 8);
        }
    };
    loadKV(0, 0);
    cp_commit();

    float m0 = -1e30f, m1 = -1e30f, l0 = 0.0f, l1 = 0.0f;
    float o[8][4];
    #pragma unroll
    for (int f = 0; f < 8; f++)
        #pragma unroll
        for (int j = 0; j < 4; j++) o[f][j] = 0.0f;

    for (int kt = 0; kt < SEQ / ABN; kt++) {
        if (kt + 1 < SEQ / ABN) {
            loadKV(kt + 1, (kt + 1) & 1);
            cp_commit();
            cp_wait<1>();
        } else {
            cp_wait<0>();
        }
        __syncthreads();

        const uint32_t sK = sb + SK_OFF + (kt & 1) * SK_BYTES;
        const uint32_t sV = sb + SV_OFF + (kt & 1) * SV_BYTES;

        float c[8][4];
        #pragma unroll
        for (int f = 0; f < 8; f++)
            #pragma unroll
            for (int j = 0; j < 4; j++) c[f][j] = 0.0f;

        #pragma unroll
        for (int ks = 0; ks < DQK / 16; ks++) {
            #pragma unroll
            for (int fb = 0; fb < 4; fb++) {
                uint32_t b[4];
                ldm_x4(b[0], b[1], b[2], b[3],
                       sK + kfrag + (uint32_t)(fb * 16 * AQP) * 2 + ks * 32);
                mma16816(c[fb * 2],     qr[ks], b[0], b[1]);
                mma16816(c[fb * 2 + 1], qr[ks], b[2], b[3]);
            }
        }

        float mx0 = c[0][0], mx1 = c[0][2];
        #pragma unroll
        for (int f = 0; f < 8; f++) {
            mx0 = fmaxf(mx0, fmaxf(c[f][0], c[f][1]));
            mx1 = fmaxf(mx1, fmaxf(c[f][2], c[f][3]));
        }
        mx0 = fmaxf(mx0, __shfl_xor_sync(0xffffffffu, mx0, 1));
        mx0 = fmaxf(mx0, __shfl_xor_sync(0xffffffffu, mx0, 2));
        mx1 = fmaxf(mx1, __shfl_xor_sync(0xffffffffu, mx1, 1));
        mx1 = fmaxf(mx1, __shfl_xor_sync(0xffffffffu, mx1, 2));
        const float nm0 = fmaxf(m0, mx0), nm1 = fmaxf(m1, mx1);
        const float cr0 = __expf(m0 - nm0), cr1 = __expf(m1 - nm1);
        m0 = nm0; m1 = nm1;
        float rs0 = 0.0f, rs1 = 0.0f;
        #pragma unroll
        for (int f = 0; f < 8; f++) {
            c[f][0] = __expf(c[f][0] - nm0); rs0 += c[f][0];
            c[f][1] = __expf(c[f][1] - nm0); rs0 += c[f][1];
            c[f][2] = __expf(c[f][2] - nm1); rs1 += c[f][2];
            c[f][3] = __expf(c[f][3] - nm1); rs1 += c[f][3];
        }
        l0 = l0 * cr0 + rs0;
        l1 = l1 * cr1 + rs1;
        #pragma unroll
        for (int f = 0; f < 8; f++) {
            o[f][0] *= cr0; o[f][1] *= cr0;
            o[f][2] *= cr1; o[f][3] *= cr1;
        }

        #pragma unroll
        for (int ks = 0; ks < ABN / 16; ks++) {
            uint32_t pa[4];
            pa[0] = pack_h2(c[2 * ks][0],     c[2 * ks][1]);
            pa[1] = pack_h2(c[2 * ks][2],     c[2 * ks][3]);
            pa[2] = pack_h2(c[2 * ks + 1][0], c[2 * ks + 1][1]);
            pa[3] = pack_h2(c[2 * ks + 1][2], c[2 * ks + 1][3]);
            #pragma unroll
            for (int fb = 0; fb < 4; fb++) {
                uint32_t vb[4];
                ldm_x4(vb[0], vb[1], vb[2], vb[3],
                       sV + vfrag + (uint32_t)(fb * 16 * AVP) * 2 + ks * 32);
                mma16816h(o[fb * 2],     pa, vb[0], vb[1]);
                mma16816h(o[fb * 2 + 1], pa, vb[2], vb[3]);
            }
        }
        __syncthreads();
    }

    l0 += __shfl_xor_sync(0xffffffffu, l0, 1);
    l0 += __shfl_xor_sync(0xffffffffu, l0, 2);
    l1 += __shfl_xor_sync(0xffffffffu, l1, 1);
    l1 += __shfl_xor_sync(0xffffffffu, l1, 2);
    const float inv0 = 1.0f / l0, inv1 = 1.0f / l1;
    const int b_ = bh / NHEAD, h = bh - b_ * NHEAD;
    const int r0 = qb * ABM + w * 16 + g;
    float* p0 = out + (((size_t)(b_ * SEQ + r0)) * NHEAD + h) * HEAD_DIM;
    float* p1 = out + (((size_t)(b_ * SEQ + r0 + 8)) * NHEAD + h) * HEAD_DIM;
    #pragma unroll
    for (int f = 0; f < 8; f++) {
        const int col = f * 8 + t * 2;
        *(float2*)(p0 + col) = make_float2(o[f][0] * inv0, o[f][1] * inv0);
        *(float2*)(p1 + col) = make_float2(o[f][2] * inv1, o[f][3] * inv1);
    }
}

// ====================================================================
extern "C" void kernel_launch(void* const* d_in, const int* in_sizes, int n_in,
                              void* d_out, int out_size)
{
    const float* x     = (const float*)d_in[0];
    const float* pos   = (const float*)d_in[1];
    const float* qkv_w = (const float*)d_in[2];
    const float* qkv_b = (const float*)d_in[3];
    const float* pq_w  = (const float*)d_in[4];
    const float* pq_b  = (const float*)d_in[5];
    const float* pk_w  = (const float*)d_in[6];
    const float* pk_b  = (const float*)d_in[7];
    float* out = (float*)d_out;

    __nv_bfloat16 *xh, *xl, *ph, *pl, *wqh, *wql, *wpqh, *wpql, *wpkh, *wpkl;
    cudaGetSymbolAddress((void**)&xh,   g_xh);
    cudaGetSymbolAddress((void**)&xl,   g_xl);
    cudaGetSymbolAddress((void**)&ph,   g_ph);
    cudaGetSymbolAddress((void**)&pl,   g_pl);
    cudaGetSymbolAddress((void**)&wqh,  g_wqh);
    cudaGetSymbolAddress((void**)&wql,  g_wql);
    cudaGetSymbolAddress((void**)&wpqh, g_wpqh);
    cudaGetSymbolAddress((void**)&wpql, g_wpql);
    cudaGetSymbolAddress((void**)&wpkh, g_wpkh);
    cudaGetSymbolAddress((void**)&wpkl, g_wpkl);

    // 1) split into hi/lo bf16 planes (float4 vectorized)
    split_all<<<(SPLIT_V4 + 255) / 256, 256>>>(x, pos, qkv_w, pq_w, pk_w);

    // 2) all projections + fused operand-build epilogues
    cudaFuncSetAttribute(gemm128, cudaFuncAttributeMaxDynamicSharedMemorySize, GSM2);
    gemm128<<<dim3(30, 64), 256, GSM2>>>(xh, xl, ph, pl, wqh, wql,
                                         wpqh, wpql, wpkh, wpkl,
                                         qkv_b, pq_b, pk_b);

    // 3) build Kc[0..191] = split(k + pq)
    build_all<<<BQK_BLOCKS, 256>>>();

    // 4) flash attention (4-warp CTAs, 2 CTAs/SM, Q register-resident)
    cudaFuncSetAttribute(attn_mma, cudaFuncAttributeMaxDynamicSharedMemorySize, ASMEM);
    attn_mma<<<dim3(SEQ / ABM, BH), 128, ASMEM>>>(out);
}

// round 13
// speedup vs baseline: 4.6199x; 1.1779x over previous
#include <cuda_runtime.h>
#include <cuda_bf16.h>
#include <cuda_fp16.h>
#include <cstdint>
#include <cstddef>

#define D_MODEL 768
#define NHEAD   12
#define HEAD_DIM 64
#define BATCH   8
#define SEQ     1024
#define BH      (BATCH * NHEAD)     // 96
#define M_ROWS  (BATCH * SEQ)       // 8192
#define ADQ     128                 // fp16 attention dim: [q | k/48] vs [k' | pk]
#define INV_SCALE (1.0f / 48.0f)    // 1/sqrt(3*768)

// ---------------- scratch (static device allocation; no cudaMalloc) ----------------
__device__ float g_QKV [M_ROWS * 3 * D_MODEL];   // only k-part [768:1536) used now
__device__ float g_PQ  [M_ROWS * D_MODEL];

// attention operands (fp16)
__device__ __half g_Qc[(size_t)BH * SEQ * ADQ];      // [q | k/48]
__device__ __half g_Kc[(size_t)BH * SEQ * ADQ];      // [k' | pk]
__device__ __half g_Vt[(size_t)BH * HEAD_DIM * SEQ]; // transposed [bh][d][l]

// split-bf16 hi/lo planes for projections
__device__ __nv_bfloat16 g_xh [M_ROWS * D_MODEL];
__device__ __nv_bfloat16 g_xl [M_ROWS * D_MODEL];
__device__ __nv_bfloat16 g_ph [M_ROWS * D_MODEL];
__device__ __nv_bfloat16 g_pl [M_ROWS * D_MODEL];
__device__ __nv_bfloat16 g_wqh[3 * D_MODEL * D_MODEL];
__device__ __nv_bfloat16 g_wql[3 * D_MODEL * D_MODEL];
__device__ __nv_bfloat16 g_wpqh[D_MODEL * D_MODEL];
__device__ __nv_bfloat16 g_wpql[D_MODEL * D_MODEL];
__device__ __nv_bfloat16 g_wpkh[D_MODEL * D_MODEL];
__device__ __nv_bfloat16 g_wpkl[D_MODEL * D_MODEL];

// ==================== helpers ====================
__device__ __forceinline__ uint32_t smem_u32(const void* p) {
    uint32_t a;
    asm("{ .reg .u64 t; cvta.to.shared.u64 t, %1; cvt.u32.u64 %0, t; }" : "=r"(a) : "l"(p));
    return a;
}
__device__ __forceinline__ void cp16(uint32_t dst, const void* src) {
    asm volatile("cp.async.cg.shared.global [%0], [%1], 16;" :: "r"(dst), "l"(src));
}
__device__ __forceinline__ void cp_commit() {
    asm volatile("cp.async.commit_group;" ::: "memory");
}
template <int N>
__device__ __forceinline__ void cp_wait() {
    asm volatile("cp.async.wait_group %0;" :: "n"(N) : "memory");
}
__device__ __forceinline__ void ldm_x4(uint32_t& r0, uint32_t& r1, uint32_t& r2,
                                       uint32_t& r3, uint32_t addr) {
    asm volatile("ldmatrix.sync.aligned.m8n8.x4.shared.b16 {%0,%1,%2,%3}, [%4];"
                 : "=r"(r0), "=r"(r1), "=r"(r2), "=r"(r3) : "r"(addr));
}
__device__ __forceinline__ void mma16816(float* c, const uint32_t* a,
                                         uint32_t b0, uint32_t b1) {
    asm volatile(
        "mma.sync.aligned.m16n8k16.row.col.f32.bf16.bf16.f32 "
        "{%0,%1,%2,%3}, {%4,%5,%6,%7}, {%8,%9}, {%0,%1,%2,%3};"
        : "+f"(c[0]), "+f"(c[1]), "+f"(c[2]), "+f"(c[3])
        : "r"(a[0]), "r"(a[1]), "r"(a[2]), "r"(a[3]), "r"(b0), "r"(b1));
}
__device__ __forceinline__ void mma16816h(float* c, const uint32_t* a,
                                          uint32_t b0, uint32_t b1) {
    asm volatile(
        "mma.sync.aligned.m16n8k16.row.col.f32.f16.f16.f32 "
        "{%0,%1,%2,%3}, {%4,%5,%6,%7}, {%8,%9}, {%0,%1,%2,%3};"
        : "+f"(c[0]), "+f"(c[1]), "+f"(c[2]), "+f"(c[3])
        : "r"(a[0]), "r"(a[1]), "r"(a[2]), "r"(a[3]), "r"(b0), "r"(b1));
}
__device__ __forceinline__ uint32_t pack_h2(float lo, float hi) {
    __half2 h = __floats2half2_rn(lo, hi);
    return *(uint32_t*)&h;
}

// ==================== launch 1: fused split fp32 -> (hi, lo) bf16 planes ====================
#define NXE (M_ROWS * D_MODEL)          // 6291456
#define NWQE (3 * D_MODEL * D_MODEL)    // 1769472
#define NWE (D_MODEL * D_MODEL)         // 589824
#define SPLIT_TOTAL (2 * NXE + NWQE + 2 * NWE)
#define SPLIT_V4 (SPLIT_TOTAL / 4)

__global__ __launch_bounds__(256) void split_all(
    const float* __restrict__ x, const float* __restrict__ pos,
    const float* __restrict__ wq, const float* __restrict__ wpq,
    const float* __restrict__ wpk)
{
    const int i4 = blockIdx.x * 256 + threadIdx.x;
    if (i4 >= SPLIT_V4) return;
    const int i = i4 * 4;
    const float* src;
    __nv_bfloat16 *hi, *lo;
    int j;
    if (i < NXE)                       { j = i;                        src = x;   hi = g_xh;   lo = g_xl;   }
    else if (i < 2 * NXE)              { j = i - NXE;                  src = pos; hi = g_ph;   lo = g_pl;   }
    else if (i < 2 * NXE + NWQE)       { j = i - 2 * NXE;              src = wq;  hi = g_wqh;  lo = g_wql;  }
    else if (i < 2 * NXE + NWQE + NWE) { j = i - 2 * NXE - NWQE;       src = wpq; hi = g_wpqh; lo = g_wpql; }
    else                               { j = i - 2 * NXE - NWQE - NWE; src = wpk; hi = g_wpkh; lo = g_wpkl; }

    const float4 v = *(const float4*)(src + j);
    union { __nv_bfloat162 h2[2]; uint2 u; } H, L;
    __nv_bfloat16 h0 = __float2bfloat16(v.x), h1 = __float2bfloat16(v.y);
    __nv_bfloat16 h2 = __float2bfloat16(v.z), h3 = __float2bfloat16(v.w);
    H.h2[0] = __nv_bfloat162(h0, h1);
    H.h2[1] = __nv_bfloat162(h2, h3);
    L.h2[0] = __nv_bfloat162(__float2bfloat16(v.x - __bfloat162float(h0)),
                             __float2bfloat16(v.y - __bfloat162float(h1)));
    L.h2[1] = __nv_bfloat162(__float2bfloat16(v.z - __bfloat162float(h2)),
                             __float2bfloat16(v.w - __bfloat162float(h3)));
    *(uint2*)(hi + j) = H.u;
    *(uint2*)(lo + j) = L.u;
}

// ==================== launch 2: split-bf16 GEMM with fused fp16 operand epilogues ====
//   bx  0-5  (q):  fp16 q -> g_Qc[0..63]
//   bx  6-11 (k):  fp32 k -> g_QKV (for k'=k+pq) AND fp16 k/48 -> g_Qc[64..127]
//   bx 12-17 (v):  fp16 transposed -> g_Vt
//   bx 18-23 (pq): fp32 -> g_PQ
//   bx 24-29 (pk): fp16 -> g_Kc[64..127]   (single-plane GEMM)
#define GK    768
#define GBK2  32
#define GP2   40
#define PL2B  (128 * GP2 * 2)
#define OFF2_AH 0
#define OFF2_AL PL2B
#define OFF2_WH (2 * PL2B)
#define OFF2_WL (3 * PL2B)
#define GBUF2  (4 * PL2B)
#define GSM2   (2 * GBUF2)                // 81920 -> 2 CTAs/SM

__global__ __launch_bounds__(256, 2) void gemm128(
    const __nv_bfloat16* __restrict__ xh, const __nv_bfloat16* __restrict__ xl,
    const __nv_bfloat16* __restrict__ ph, const __nv_bfloat16* __restrict__ pl,
    const __nv_bfloat16* __restrict__ wqh, const __nv_bfloat16* __restrict__ wql,
    const __nv_bfloat16* __restrict__ wpqh, const __nv_bfloat16* __restrict__ wpql,
    const __nv_bfloat16* __restrict__ wpkh, const __nv_bfloat16* __restrict__ wpkl,
    const float* __restrict__ qkv_b, const float* __restrict__ pq_b,
    const float* __restrict__ pk_b)
{
    extern __shared__ char smg[];
    const uint32_t sbase = smem_u32(smg);
    const int tid = threadIdx.x, lane = tid & 31, wid = tid >> 5;
    const int wm = wid >> 1;
    const int wn = wid & 1;
    const int bx = blockIdx.x;
    const int rowBase = blockIdx.y << 7;

    const __nv_bfloat16 *Ah, *Al, *Wh, *Wl;
    const float* bias;
    int colBase;
    bool three = true;
    if (bx < 18)      { Ah = xh; Al = xl; Wh = wqh;  Wl = wql;  bias = qkv_b; colBase = bx * 128; }
    else if (bx < 24) { Ah = ph; Al = pl; Wh = wpqh; Wl = wpql; bias = pq_b;  colBase = (bx - 18) * 128; }
    else              { Ah = ph; Al = pl; Wh = wpkh; Wl = wpkl; bias = pk_b;  colBase = (bx - 24) * 128; three = false; }

    const __nv_bfloat16* Ahg = Ah + (size_t)rowBase * GK;
    const __nv_bfloat16* Alg = Al + (size_t)rowBase * GK;
    const __nv_bfloat16* Whg = Wh + (size_t)colBase * GK;
    const __nv_bfloat16* Wlg = Wl + (size_t)colBase * GK;

    const uint32_t aoff = ((uint32_t)((wm * 32 + (lane & 15)) * GP2 + ((lane >> 4) * 8))) * 2;
    const uint32_t woff = ((uint32_t)((wn * 64 + ((lane >> 4) & 1) * 8 + (lane & 7)) * GP2
                                     + (((lane >> 3) & 1) * 8))) * 2;

    float c[2][8][4];
    #pragma unroll
    for (int i = 0; i < 2; i++)
        #pragma unroll
        for (int j = 0; j < 8; j++)
            #pragma unroll
            for (int k = 0; k < 4; k++) c[i][j][k] = 0.0f;

    auto load_chunk = [&](int ch, int buf) {
        const uint32_t base = sbase + (uint32_t)buf * GBUF2;
        const int k0 = ch * GBK2;
        #pragma unroll
        for (int it = 0; it < 2; it++) {
            const int idx = it * 256 + tid;
            const int row = idx >> 2, seg = (idx & 3) * 8;
            const uint32_t so = (uint32_t)(row * GP2 + seg) * 2;
            const size_t go = (size_t)row * GK + k0 + seg;
            cp16(base + OFF2_AH + so, Ahg + go);
            cp16(base + OFF2_WH + so, Whg + go);
            if (three) {
                cp16(base + OFF2_AL + so, Alg + go);
                cp16(base + OFF2_WL + so, Wlg + go);
            }
        }
    };

    load_chunk(0, 0);
    cp_commit();

    const int NCH = GK / GBK2;   // 24
    for (int ch = 0; ch < NCH; ch++) {
        if (ch + 1 < NCH) {
            load_chunk(ch + 1, (ch + 1) & 1);
            cp_commit();
            cp_wait<1>();
        } else {
            cp_wait<0>();
        }
        __syncthreads();

        const uint32_t base = sbase + (uint32_t)(ch & 1) * GBUF2;
        #pragma unroll
        for (int kk = 0; kk < GBK2; kk += 16) {
            uint32_t ah[2][4], al[2][4];
            #pragma unroll
            for (int fa = 0; fa < 2; fa++) {
                ldm_x4(ah[fa][0], ah[fa][1], ah[fa][2], ah[fa][3],
                       base + OFF2_AH + aoff + (uint32_t)(fa * 16 * GP2 + kk) * 2);
                if (three)
                    ldm_x4(al[fa][0], al[fa][1], al[fa][2], al[fa][3],
                           base + OFF2_AL + aoff + (uint32_t)(fa * 16 * GP2 + kk) * 2);
            }
            #pragma unroll
            for (int fb = 0; fb < 4; fb++) {
                uint32_t b[4];
                ldm_x4(b[0], b[1], b[2], b[3],
                       base + OFF2_WH + woff + (uint32_t)(fb * 16 * GP2 + kk) * 2);
                #pragma unroll
                for (int fa = 0; fa < 2; fa++) {
                    mma16816(c[fa][fb * 2],     ah[fa], b[0], b[1]);
                    mma16816(c[fa][fb * 2 + 1], ah[fa], b[2], b[3]);
                    if (three) {
                        mma16816(c[fa][fb * 2],     al[fa], b[0], b[1]);
                        mma16816(c[fa][fb * 2 + 1], al[fa], b[2], b[3]);
                    }
                }
                if (three) {
                    ldm_x4(b[0], b[1], b[2], b[3],
                           base + OFF2_WL + woff + (uint32_t)(fb * 16 * GP2 + kk) * 2);
                    #pragma unroll
                    for (int fa = 0; fa < 2; fa++) {
                        mma16816(c[fa][fb * 2],     ah[fa], b[0], b[1]);
                        mma16816(c[fa][fb * 2 + 1], ah[fa], b[2], b[3]);
                    }
                }
            }
        }
        __syncthreads();
    }

    // ---- fused epilogue ----
    const int gq = lane >> 2, tq = lane & 3;
    #pragma unroll
    for (int fa = 0; fa < 2; fa++) {
        #pragma unroll
        for (int nf = 0; nf < 8; nf++) {
            const int row0 = rowBase + wm * 32 + fa * 16 + gq;
            const int col = colBase + wn * 64 + nf * 8 + tq * 2;
            const float b0 = bias[col], b1 = bias[col + 1];
            const float v0a = c[fa][nf][0] + b0, v1a = c[fa][nf][1] + b1;
            const float v0b = c[fa][nf][2] + b0, v1b = c[fa][nf][3] + b1;

            if (bx < 6) {
                // ---- q -> fp16 Qc[0..63] ----
                const int h = col >> 6, d = col & 63;
                #pragma unroll
                for (int rr = 0; rr < 2; rr++) {
                    const int row = row0 + rr * 8;
                    const float u0 = rr ? v0b : v0a, u1 = rr ? v1b : v1a;
                    const int b_ = row >> 10, l = row & (SEQ - 1);
                    const size_t baseQ = ((size_t)(b_ * NHEAD + h) * SEQ + l) * ADQ;
                    *(__half2*)&g_Qc[baseQ + d] = __floats2half2_rn(u0, u1);
                }
            } else if (bx < 12) {
                // ---- k -> fp32 g_QKV AND fp16 k/48 -> Qc[64..127] ----
                *(float2*)(g_QKV + (size_t)row0 * 2304 + col) = make_float2(v0a, v1a);
                *(float2*)(g_QKV + (size_t)(row0 + 8) * 2304 + col) = make_float2(v0b, v1b);
                const int ch = col - 768, h = ch >> 6, d = ch & 63;
                #pragma unroll
                for (int rr = 0; rr < 2; rr++) {
                    const int row = row0 + rr * 8;
                    const float u0 = rr ? v0b : v0a, u1 = rr ? v1b : v1a;
                    const int b_ = row >> 10, l = row & (SEQ - 1);
                    const size_t baseQ = ((size_t)(b_ * NHEAD + h) * SEQ + l) * ADQ;
                    *(__half2*)&g_Qc[baseQ + 64 + d] =
                        __floats2half2_rn(u0 * INV_SCALE, u1 * INV_SCALE);
                }
            } else if (bx < 18) {
                // ---- v -> fp16 transposed g_Vt[bh][d][l] ----
                const int ch = col - 1536, h = ch >> 6, d = ch & 63;
                #pragma unroll
                for (int rr = 0; rr < 2; rr++) {
                    const int row = row0 + rr * 8;
                    const float u0 = rr ? v0b : v0a, u1 = rr ? v1b : v1a;
                    const int b_ = row >> 10, l = row & (SEQ - 1);
                    const size_t bh = (size_t)(b_ * NHEAD + h);
                    g_Vt[(bh * HEAD_DIM + d) * SEQ + l]     = __float2half(u0);
                    g_Vt[(bh * HEAD_DIM + d + 1) * SEQ + l] = __float2half(u1);
                }
            } else if (bx < 24) {
                // ---- pq -> fp32 g_PQ ----
                *(float2*)(g_PQ + (size_t)row0 * 768 + col) = make_float2(v0a, v1a);
                *(float2*)(g_PQ + (size_t)(row0 + 8) * 768 + col) = make_float2(v0b, v1b);
            } else {
                // ---- pk -> fp16 Kc[64..127] ----
                const int h = col >> 6, d = col & 63;
                #pragma unroll
                for (int rr = 0; rr < 2; rr++) {
                    const int row = row0 + rr * 8;
                    const float u0 = rr ? v0b : v0a, u1 = rr ? v1b : v1a;
                    const int b_ = row >> 10, l = row & (SEQ - 1);
                    const size_t baseK = ((size_t)(b_ * NHEAD + h) * SEQ + l) * ADQ;
                    *(__half2*)&g_Kc[baseK + 64 + d] = __floats2half2_rn(u0, u1);
                }
            }
        }
    }
}

// ==================== launch 3: build Kc[0..63] = fp16(k + pq) ====================
#define BQK_BLOCKS ((BH * SEQ * 64) / 256)   // 24576

__global__ __launch_bounds__(256) void build_all()
{
    const int idx = blockIdx.x * 256 + threadIdx.x;
    const int d  = idx & 63;
    const int l  = (idx >> 6) & (SEQ - 1);
    const int bh = idx >> 16;
    const int b  = bh / NHEAD, h = bh - b * NHEAD;
    const size_t row = (size_t)b * SEQ + l;
    const int c = h * HEAD_DIM + d;
    const float k  = g_QKV[row * 2304 + 768 + c];
    const float pq = g_PQ[row * 768 + c];
    g_Kc[((size_t)bh * SEQ + l) * ADQ + d] = __float2half(k + pq);
}

// ==================== launch 4: fp16 flash attention, 4-warp CTAs, 3 CTAs/SM ====================
#define ABM 64
#define ABN 64
#define AQP 136                          // half units; 272B rows -> conflict-free LDSM
#define AVP 72
#define SK_OFF 0
#define SK_BYTES (ABN * AQP * 2)         // 17408
#define SV_OFF (SK_OFF + 2 * SK_BYTES)   // 34816
#define SV_BYTES (ABN * AVP * 2)         // 9216
#define ASMEM (SV_OFF + 2 * SV_BYTES)    // 53248 -> 3 CTAs/SM (160KB)

__global__ __launch_bounds__(128, 3) void attn_mma(float* __restrict__ out)
{
    extern __shared__ char smc[];
    const uint32_t sb = smem_u32(smc);
    const int tid = threadIdx.x, lane = tid & 31, w = tid >> 5;
    const int qb = blockIdx.x, bh = blockIdx.y;
    const int g = lane >> 2, t = lane & 3;

    const __half* Qg = g_Qc + ((size_t)bh * SEQ + (size_t)qb * ABM) * ADQ;
    const __half* Kg = g_Kc + (size_t)bh * SEQ * ADQ;
    const __half* Vg = g_Vt + (size_t)bh * HEAD_DIM * SEQ;

    const uint32_t aoff = (uint32_t)((w * 16 + (lane & 15)) * AQP + (lane >> 4) * 8) * 2;
    const uint32_t kfrag = (uint32_t)((((lane >> 4) & 1) * 8 + (lane & 7)) * AQP
                                     + ((lane >> 3) & 1) * 8) * 2;
    const uint32_t vfrag = (uint32_t)((((lane >> 4) & 1) * 8 + (lane & 7)) * AVP
                                     + ((lane >> 3) & 1) * 8) * 2;

    // ---- stage Q (64 rows x 256B) in K buffer 0, hoist frags to regs ----
    #pragma unroll
    for (int it = 0; it < 8; it++) {
        const int idx = it * 128 + tid;             // 0..1023
        const int r = idx >> 4, s = idx & 15;
        cp16(sb + SK_OFF + (uint32_t)(r * AQP + s * 8) * 2, Qg + (size_t)r * ADQ + s * 8);
    }
    cp_commit();
    cp_wait<0>();
    __syncthreads();

    uint32_t qr[8][4];
    #pragma unroll
    for (int ks = 0; ks < ADQ / 16; ks++)
        ldm_x4(qr[ks][0], qr[ks][1], qr[ks][2], qr[ks][3],
               sb + SK_OFF + aoff + ks * 32);
    __syncthreads();

    auto loadKV = [&](int kt, int buf) {
        const __half* Kt = Kg + (size_t)kt * ABN * ADQ;
        #pragma unroll
        for (int it = 0; it < 8; it++) {
            const int idx = it * 128 + tid;
            const int r = idx >> 4, s = idx & 15;
            cp16(sb + SK_OFF + buf * SK_BYTES + (uint32_t)(r * AQP + s * 8) * 2,
                 Kt + (size_t)r * ADQ + s * 8);
        }
        #pragma unroll
        for (int it = 0; it < 4; it++) {
            const int idx = it * 128 + tid;
            const int r = idx >> 3, s = idx & 7;
            cp16(sb + SV_OFF + buf * SV_BYTES + (uint32_t)(r * AVP + s * 8) * 2,
                 Vg + (size_t)r * SEQ + kt * ABN + s * 8);
        }
    };
    loadKV(0, 0);
    cp_commit();

    float m0 = -1e30f, m1 = -1e30f, l0 = 0.0f, l1 = 0.0f;
    float o[8][4];
    #pragma unroll
    for (int f = 0; f < 8; f++)
        #pragma unroll
        for (int j = 0; j < 4; j++) o[f][j] = 0.0f;

    for (int kt = 0; kt < SEQ / ABN; kt++) {
        if (kt + 1 < SEQ / ABN) {
            loadKV(kt + 1, (kt + 1) & 1);
            cp_commit();
            cp_wait<1>();
        } else {
            cp_wait<0>();
        }
        __syncthreads();

        const uint32_t sK = sb + SK_OFF + (kt & 1) * SK_BYTES;
        const uint32_t sV = sb + SV_OFF + (kt & 1) * SV_BYTES;

        // ---- S = Q @ K^T (fp16, m16 x n64 per warp, k=128) ----
        float c[8][4];
        #pragma unroll
        for (int f = 0; f < 8; f++)
            #pragma unroll
            for (int j = 0; j < 4; j++) c[f][j] = 0.0f;

        #pragma unroll
        for (int ks = 0; ks < ADQ / 16; ks++) {
            #pragma unroll
            for (int fb = 0; fb < 4; fb++) {
                uint32_t b[4];
                ldm_x4(b[0], b[1], b[2], b[3],
                       sK + kfrag + (uint32_t)(fb * 16 * AQP) * 2 + ks * 32);
                mma16816h(c[fb * 2],     qr[ks], b[0], b[1]);
                mma16816h(c[fb * 2 + 1], qr[ks], b[2], b[3]);
            }
        }

        // ---- online softmax (fp32 __expf) ----
        float mx0 = c[0][0], mx1 = c[0][2];
        #pragma unroll
        for (int f = 0; f < 8; f++) {
            mx0 = fmaxf(mx0, fmaxf(c[f][0], c[f][1]));
            mx1 = fmaxf(mx1, fmaxf(c[f][2], c[f][3]));
        }
        mx0 = fmaxf(mx0, __shfl_xor_sync(0xffffffffu, mx0, 1));
        mx0 = fmaxf(mx0, __shfl_xor_sync(0xffffffffu, mx0, 2));
        mx1 = fmaxf(mx1, __shfl_xor_sync(0xffffffffu, mx1, 1));
        mx1 = fmaxf(mx1, __shfl_xor_sync(0xffffffffu, mx1, 2));
        const float nm0 = fmaxf(m0, mx0), nm1 = fmaxf(m1, mx1);
        const float cr0 = __expf(m0 - nm0), cr1 = __expf(m1 - nm1);
        m0 = nm0; m1 = nm1;
        float rs0 = 0.0f, rs1 = 0.0f;
        #pragma unroll
        for (int f = 0; f < 8; f++) {
            c[f][0] = __expf(c[f][0] - nm0); rs0 += c[f][0];
            c[f][1] = __expf(c[f][1] - nm0); rs0 += c[f][1];
            c[f][2] = __expf(c[f][2] - nm1); rs1 += c[f][2];
            c[f][3] = __expf(c[f][3] - nm1); rs1 += c[f][3];
        }
        l0 = l0 * cr0 + rs0;
        l1 = l1 * cr1 + rs1;
        #pragma unroll
        for (int f = 0; f < 8; f++) {
            o[f][0] *= cr0; o[f][1] *= cr0;
            o[f][2] *= cr1; o[f][3] *= cr1;
        }

        // ---- O += P @ V (P packed to fp16 A-frags from registers) ----
        #pragma unroll
        for (int ks = 0; ks < ABN / 16; ks++) {
            uint32_t pa[4];
            pa[0] = pack_h2(c[2 * ks][0],     c[2 * ks][1]);
            pa[1] = pack_h2(c[2 * ks][2],     c[2 * ks][3]);
            pa[2] = pack_h2(c[2 * ks + 1][0], c[2 * ks + 1][1]);
            pa[3] = pack_h2(c[2 * ks + 1][2], c[2 * ks + 1][3]);
            #pragma unroll
            for (int fb = 0; fb < 4; fb++) {
                uint32_t vb[4];
                ldm_x4(vb[0], vb[1], vb[2], vb[3],
                       sV + vfrag + (uint32_t)(fb * 16 * AVP) * 2 + ks * 32);
                mma16816h(o[fb * 2],     pa, vb[0], vb[1]);
                mma16816h(o[fb * 2 + 1], pa, vb[2], vb[3]);
            }
        }
        __syncthreads();
    }

    l0 += __shfl_xor_sync(0xffffffffu, l0, 1);
    l0 += __shfl_xor_sync(0xffffffffu, l0, 2);
    l1 += __shfl_xor_sync(0xffffffffu, l1, 1);
    l1 += __shfl_xor_sync(0xffffffffu, l1, 2);
    const float inv0 = 1.0f / l0, inv1 = 1.0f / l1;
    const int b_ = bh / NHEAD, h = bh - b_ * NHEAD;
    const int r0 = qb * ABM + w * 16 + g;
    float* p0 = out + (((size_t)(b_ * SEQ + r0)) * NHEAD + h) * HEAD_DIM;
    float* p1 = out + (((size_t)(b_ * SEQ + r0 + 8)) * NHEAD + h) * HEAD_DIM;
    #pragma unroll
    for (int f = 0; f < 8; f++) {
        const int col = f * 8 + t * 2;
        *(float2*)(p0 + col) = make_float2(o[f][0] * inv0, o[f][1] * inv0);
        *(float2*)(p1 + col) = make_float2(o[f][2] * inv1, o[f][3] * inv1);
    }
}

// ====================================================================
extern "C" void kernel_launch(void* const* d_in, const int* in_sizes, int n_in,
                              void* d_out, int out_size)
{
    const float* x     = (const float*)d_in[0];
    const float* pos   = (const float*)d_in[1];
    const float* qkv_w = (const float*)d_in[2];
    const float* qkv_b = (const float*)d_in[3];
    const float* pq_w  = (const float*)d_in[4];
    const float* pq_b  = (const float*)d_in[5];
    const float* pk_w  = (const float*)d_in[6];
    const float* pk_b  = (const float*)d_in[7];
    float* out = (float*)d_out;

    __nv_bfloat16 *xh, *xl, *ph, *pl, *wqh, *wql, *wpqh, *wpql, *wpkh, *wpkl;
    cudaGetSymbolAddress((void**)&xh,   g_xh);
    cudaGetSymbolAddress((void**)&xl,   g_xl);
    cudaGetSymbolAddress((void**)&ph,   g_ph);
    cudaGetSymbolAddress((void**)&pl,   g_pl);
    cudaGetSymbolAddress((void**)&wqh,  g_wqh);
    cudaGetSymbolAddress((void**)&wql,  g_wql);
    cudaGetSymbolAddress((void**)&wpqh, g_wpqh);
    cudaGetSymbolAddress((void**)&wpql, g_wpql);
    cudaGetSymbolAddress((void**)&wpkh, g_wpkh);
    cudaGetSymbolAddress((void**)&wpkl, g_wpkl);

    // 1) split into hi/lo bf16 planes (float4 vectorized)
    split_all<<<(SPLIT_V4 + 255) / 256, 256>>>(x, pos, qkv_w, pq_w, pk_w);

    // 2) all projections + fused fp16 operand-build epilogues
    cudaFuncSetAttribute(gemm128, cudaFuncAttributeMaxDynamicSharedMemorySize, GSM2);
    gemm128<<<dim3(30, 64), 256, GSM2>>>(xh, xl, ph, pl, wqh, wql,
                                         wpqh, wpql, wpkh, wpkl,
                                         qkv_b, pq_b, pk_b);

    // 3) build Kc[0..63] = fp16(k + pq)
    build_all<<<BQK_BLOCKS, 256>>>();

    // 4) fp16 flash attention (ADQ=128, 4-warp CTAs, 3 CTAs/SM)
    cudaFuncSetAttribute(attn_mma, cudaFuncAttributeMaxDynamicSharedMemorySize, ASMEM);
    attn_mma<<<dim3(SEQ / ABM, BH), 128, ASMEM>>>(out);
}